// round 1
// baseline (speedup 1.0000x reference)
#include <cuda_runtime.h>
#include <cuda_bf16.h>
#include <math.h>

// Problem constants
#define T_ 1024
#define S_ 1024
#define B_ 4
#define D_ 512
#define H_ 8
#define HD_ 64
#define DFF_ 2048
#define W_ 16
#define NROWS (T_ * B_)          // 4096
#define SCALE_ 0.125f            // 1/sqrt(64)
#define EPS_ 1e-5f

// ---------------------------------------------------------------------------
// Scratch: single __device__ global array (no runtime allocation allowed).
// ---------------------------------------------------------------------------
#define OFF_QKV     0            // 4096*1536
#define OFF_ATTN    6291456      // 4096*512
#define OFF_PROJ    8388608
#define OFF_X1      10485760
#define OFF_SWQ     12582912
#define OFF_SWK     14680064
#define OFF_SWV     16777216
#define OFF_SWATTN  18874368
#define OFF_X2      20971520
#define OFF_H       23068672     // 4096*2048
#define OFF_FF      31457280
#define SCRATCH_FLOATS 33554432  // 128 MB

__device__ float g_scratch[SCRATCH_FLOATS];

// ---------------------------------------------------------------------------
// Generic fp32 GEMM: C[M,N] = A[M,K] * W[N,K]^T + bias[N], optional ReLU.
// BM=BN=64, BK=16, 256 threads, 4x4 per thread.
// ---------------------------------------------------------------------------
__global__ void __launch_bounds__(256) gemm_kernel(
    const float* __restrict__ A, const float* __restrict__ Wt,
    const float* __restrict__ bias, float* __restrict__ C,
    int M, int N, int K, int relu)
{
    __shared__ __align__(16) float As[16][68];
    __shared__ __align__(16) float Bs[16][68];

    const int tid = threadIdx.x;
    const int tx = tid & 15;   // N direction (0..15)
    const int ty = tid >> 4;   // M direction (0..15)
    const int m0 = blockIdx.y * 64;
    const int n0 = blockIdx.x * 64;

    const int lr = tid >> 4;   // load row group base
    const int lc = tid & 15;   // load col (k within tile)

    float acc[4][4];
#pragma unroll
    for (int i = 0; i < 4; ++i)
#pragma unroll
        for (int j = 0; j < 4; ++j) acc[i][j] = 0.f;

    for (int k0 = 0; k0 < K; k0 += 16) {
#pragma unroll
        for (int r = 0; r < 4; ++r) {
            int row = lr + r * 16;
            As[lc][row] = A[(size_t)(m0 + row) * K + k0 + lc];
            Bs[lc][row] = Wt[(size_t)(n0 + row) * K + k0 + lc];
        }
        __syncthreads();
#pragma unroll
        for (int kk = 0; kk < 16; ++kk) {
            float4 a4 = *reinterpret_cast<const float4*>(&As[kk][ty * 4]);
            float4 b4 = *reinterpret_cast<const float4*>(&Bs[kk][tx * 4]);
            float ra[4] = {a4.x, a4.y, a4.z, a4.w};
            float rb[4] = {b4.x, b4.y, b4.z, b4.w};
#pragma unroll
            for (int i = 0; i < 4; ++i)
#pragma unroll
                for (int j = 0; j < 4; ++j)
                    acc[i][j] += ra[i] * rb[j];
        }
        __syncthreads();
    }

#pragma unroll
    for (int i = 0; i < 4; ++i) {
        int m = m0 + ty * 4 + i;
#pragma unroll
        for (int j = 0; j < 4; ++j) {
            int n = n0 + tx * 4 + j;
            float v = acc[i][j] + bias[n];
            if (relu) v = fmaxf(v, 0.f);
            C[(size_t)m * N + n] = v;
        }
    }
}

// ---------------------------------------------------------------------------
// Flash-style full self-attention over qkv buffer [T,B,3D].
// Block: 128 threads = 128 query rows for one (b,h). Grid: (T/128, B*H).
// ---------------------------------------------------------------------------
__global__ void __launch_bounds__(128) self_attn_kernel(
    const float* __restrict__ qkv, float* __restrict__ out)
{
    __shared__ float Ks[32 * 64];
    __shared__ float Vs[32 * 64];
    __shared__ float Ss[32 * 128];

    const int tid = threadIdx.x;
    const int b = blockIdx.y >> 3;
    const int h = blockIdx.y & 7;
    const int t = blockIdx.x * 128 + tid;

    const float* qp = qkv + ((size_t)t * B_ + b) * (3 * D_) + h * HD_;
    float qreg[64];
#pragma unroll
    for (int d = 0; d < 64; ++d) qreg[d] = qp[d];

    float accv[64];
#pragma unroll
    for (int d = 0; d < 64; ++d) accv[d] = 0.f;
    float m = -1e30f, l = 0.f;

    for (int kt = 0; kt < 32; ++kt) {
        __syncthreads();
        // cooperative load of 32 keys + 32 values (2048 floats each)
#pragma unroll
        for (int i = 0; i < 16; ++i) {
            int idx = i * 128 + tid;
            int r = idx >> 6, d = idx & 63;
            int row = kt * 32 + r;
            const float* kp = qkv + ((size_t)row * B_ + b) * (3 * D_) + D_ + h * HD_;
            Ks[r * 64 + d] = kp[d];
            Vs[r * 64 + d] = kp[D_ + d];
        }
        __syncthreads();

        // scores for this tile
        for (int j = 0; j < 32; ++j) {
            const float* kr = &Ks[j * 64];
            float s = 0.f;
#pragma unroll
            for (int d = 0; d < 64; ++d) s += qreg[d] * kr[d];
            Ss[j * 128 + tid] = s * SCALE_;
        }

        float mt = -1e30f;
#pragma unroll
        for (int j = 0; j < 32; ++j) mt = fmaxf(mt, Ss[j * 128 + tid]);
        float mn = fmaxf(m, mt);
        float corr = __expf(m - mn);
        l *= corr;
#pragma unroll
        for (int d = 0; d < 64; ++d) accv[d] *= corr;

        for (int j = 0; j < 32; ++j) {
            float p = __expf(Ss[j * 128 + tid] - mn);
            l += p;
            const float* vr = &Vs[j * 64];
#pragma unroll
            for (int d = 0; d < 64; ++d) accv[d] += p * vr[d];
        }
        m = mn;
    }

    float inv = 1.f / l;
    float* op = out + ((size_t)t * B_ + b) * D_ + h * HD_;
#pragma unroll
    for (int d = 0; d < 64; ++d) op[d] = accv[d] * inv;
}

// ---------------------------------------------------------------------------
// Sliding-window cross-attention. One warp per (t,b,h); lane owns 2 dims.
// q: [T,B,D], k/v: [S,B,D], out: [T,B,D].
// ---------------------------------------------------------------------------
__global__ void __launch_bounds__(256) sw_attn_kernel(
    const float* __restrict__ q, const float* __restrict__ k,
    const float* __restrict__ v, float* __restrict__ out)
{
    const int gw = (blockIdx.x * blockDim.x + threadIdx.x) >> 5;
    const int lane = threadIdx.x & 31;
    if (gw >= T_ * B_ * H_) return;
    const int h = gw & 7;
    const int b = (gw >> 3) & 3;
    const int t = gw >> 5;

    const float2 q2 = reinterpret_cast<const float2*>(
        q + ((size_t)t * B_ + b) * D_ + h * HD_)[lane];

    float sc[33];
#pragma unroll
    for (int jj = 0; jj < 33; ++jj) {
        int j = t - W_ + jj;
        float s = -1e30f;
        if (j >= 0 && j < S_) {
            const float2 k2 = reinterpret_cast<const float2*>(
                k + ((size_t)j * B_ + b) * D_ + h * HD_)[lane];
            float p = q2.x * k2.x + q2.y * k2.y;
#pragma unroll
            for (int o = 16; o > 0; o >>= 1)
                p += __shfl_xor_sync(0xffffffffu, p, o);
            s = p * SCALE_;
        }
        sc[jj] = s;
    }

    float m = -1e30f;
#pragma unroll
    for (int jj = 0; jj < 33; ++jj) m = fmaxf(m, sc[jj]);

    float l = 0.f, a0 = 0.f, a1 = 0.f;
#pragma unroll
    for (int jj = 0; jj < 33; ++jj) {
        int j = t - W_ + jj;
        if (j >= 0 && j < S_) {
            float p = __expf(sc[jj] - m);
            l += p;
            const float2 v2 = reinterpret_cast<const float2*>(
                v + ((size_t)j * B_ + b) * D_ + h * HD_)[lane];
            a0 += p * v2.x;
            a1 += p * v2.y;
        }
    }
    float inv = 1.f / l;
    float* op = out + ((size_t)t * B_ + b) * D_ + h * HD_;
    op[lane * 2] = a0 * inv;
    op[lane * 2 + 1] = a1 * inv;
}

// ---------------------------------------------------------------------------
// Fused residual-add + LayerNorm over D=512. Block per row, 256 threads.
// out = LN(x + y) * g + beta
// ---------------------------------------------------------------------------
__global__ void __launch_bounds__(256) add_ln_kernel(
    const float* __restrict__ x, const float* __restrict__ y,
    const float* __restrict__ g, const float* __restrict__ beta,
    float* __restrict__ out)
{
    __shared__ float sh[33];
    const int row = blockIdx.x;
    const int tid = threadIdx.x;
    const size_t base = (size_t)row * D_;

    float v0 = x[base + tid] + y[base + tid];
    float v1 = x[base + tid + 256] + y[base + tid + 256];

    // --- reduce sum ---
    float s = v0 + v1;
#pragma unroll
    for (int o = 16; o > 0; o >>= 1) s += __shfl_xor_sync(0xffffffffu, s, o);
    int lane = tid & 31, wid = tid >> 5;
    if (lane == 0) sh[wid] = s;
    __syncthreads();
    if (wid == 0) {
        float t = (lane < 8) ? sh[lane] : 0.f;
#pragma unroll
        for (int o = 4; o > 0; o >>= 1) t += __shfl_xor_sync(0xffffffffu, t, o);
        if (lane == 0) sh[32] = t;
    }
    __syncthreads();
    float mean = sh[32] * (1.f / D_);
    __syncthreads();

    float d0 = v0 - mean, d1 = v1 - mean;
    float sq = d0 * d0 + d1 * d1;
#pragma unroll
    for (int o = 16; o > 0; o >>= 1) sq += __shfl_xor_sync(0xffffffffu, sq, o);
    if (lane == 0) sh[wid] = sq;
    __syncthreads();
    if (wid == 0) {
        float t = (lane < 8) ? sh[lane] : 0.f;
#pragma unroll
        for (int o = 4; o > 0; o >>= 1) t += __shfl_xor_sync(0xffffffffu, t, o);
        if (lane == 0) sh[32] = t;
    }
    __syncthreads();
    float rstd = rsqrtf(sh[32] * (1.f / D_) + EPS_);

    out[base + tid] = d0 * rstd * g[tid] + beta[tid];
    out[base + tid + 256] = d1 * rstd * g[tid + 256] + beta[tid + 256];
}

// ---------------------------------------------------------------------------
// Launch
// ---------------------------------------------------------------------------
extern "C" void kernel_launch(void* const* d_in, const int* in_sizes, int n_in,
                              void* d_out, int out_size)
{
    (void)in_sizes; (void)n_in; (void)out_size;
    const float* tgt        = (const float*)d_in[0];
    const float* memory     = (const float*)d_in[1];
    const float* in_proj_w  = (const float*)d_in[2];
    const float* in_proj_b  = (const float*)d_in[3];
    const float* out_proj_w = (const float*)d_in[4];
    const float* out_proj_b = (const float*)d_in[5];
    const float* sw_q_w = (const float*)d_in[6];
    const float* sw_q_b = (const float*)d_in[7];
    const float* sw_k_w = (const float*)d_in[8];
    const float* sw_k_b = (const float*)d_in[9];
    const float* sw_v_w = (const float*)d_in[10];
    const float* sw_v_b = (const float*)d_in[11];
    const float* sw_o_w = (const float*)d_in[12];
    const float* sw_o_b = (const float*)d_in[13];
    const float* lin1_w = (const float*)d_in[14];
    const float* lin1_b = (const float*)d_in[15];
    const float* lin2_w = (const float*)d_in[16];
    const float* lin2_b = (const float*)d_in[17];
    const float* n1_g = (const float*)d_in[18];
    const float* n1_b = (const float*)d_in[19];
    const float* n2_g = (const float*)d_in[20];
    const float* n2_b = (const float*)d_in[21];
    const float* n3_g = (const float*)d_in[22];
    const float* n3_b = (const float*)d_in[23];
    float* out = (float*)d_out;

    float* s = nullptr;
    cudaGetSymbolAddress((void**)&s, g_scratch);
    float* qkv    = s + OFF_QKV;
    float* attn   = s + OFF_ATTN;
    float* proj   = s + OFF_PROJ;
    float* x1     = s + OFF_X1;
    float* swq    = s + OFF_SWQ;
    float* swk    = s + OFF_SWK;
    float* swv    = s + OFF_SWV;
    float* swattn = s + OFF_SWATTN;
    float* x2     = s + OFF_X2;
    float* hbuf   = s + OFF_H;
    float* ffbuf  = s + OFF_FF;

    // 1. QKV projection: [4096,512] x [1536,512]^T
    gemm_kernel<<<dim3(24, 64), 256>>>(tgt, in_proj_w, in_proj_b, qkv,
                                       NROWS, 3 * D_, D_, 0);
    // 2. self attention
    self_attn_kernel<<<dim3(8, 32), 128>>>(qkv, attn);
    // 3. out projection
    gemm_kernel<<<dim3(8, 64), 256>>>(attn, out_proj_w, out_proj_b, proj,
                                      NROWS, D_, D_, 0);
    // 4. add + LN1
    add_ln_kernel<<<NROWS, 256>>>(tgt, proj, n1_g, n1_b, x1);
    // 5-7. sliding-window projections
    gemm_kernel<<<dim3(8, 64), 256>>>(x1, sw_q_w, sw_q_b, swq, NROWS, D_, D_, 0);
    gemm_kernel<<<dim3(8, 64), 256>>>(memory, sw_k_w, sw_k_b, swk, NROWS, D_, D_, 0);
    gemm_kernel<<<dim3(8, 64), 256>>>(memory, sw_v_w, sw_v_b, swv, NROWS, D_, D_, 0);
    // 8. banded attention
    sw_attn_kernel<<<4096, 256>>>(swq, swk, swv, swattn);
    // 9. sw out projection
    gemm_kernel<<<dim3(8, 64), 256>>>(swattn, sw_o_w, sw_o_b, proj, NROWS, D_, D_, 0);
    // 10. add + LN2
    add_ln_kernel<<<NROWS, 256>>>(x1, proj, n2_g, n2_b, x2);
    // 11. FFN up + ReLU
    gemm_kernel<<<dim3(32, 64), 256>>>(x2, lin1_w, lin1_b, hbuf, NROWS, DFF_, D_, 1);
    // 12. FFN down
    gemm_kernel<<<dim3(8, 64), 256>>>(hbuf, lin2_w, lin2_b, ffbuf, NROWS, D_, DFF_, 0);
    // 13. add + LN3 -> output
    add_ln_kernel<<<NROWS, 256>>>(x2, ffbuf, n3_g, n3_b, out);
}

// round 2
// speedup vs baseline: 1.8537x; 1.8537x over previous
#include <cuda_runtime.h>
#include <cuda_bf16.h>
#include <math.h>

// Problem constants
#define T_ 1024
#define S_ 1024
#define B_ 4
#define D_ 512
#define H_ 8
#define HD_ 64
#define DFF_ 2048
#define W_ 16
#define NROWS (T_ * B_)          // 4096
#define SCALE_ 0.125f
#define EPS_ 1e-5f

// ---------------------------------------------------------------------------
// Scratch
// ---------------------------------------------------------------------------
#define OFF_QKV     0
#define OFF_ATTN    6291456
#define OFF_PROJ    8388608
#define OFF_X1      10485760
#define OFF_SWQ     12582912
#define OFF_SWK     14680064
#define OFF_SWV     16777216
#define OFF_SWATTN  18874368
#define OFF_X2      20971520
#define OFF_H       23068672
#define OFF_FF      31457280
#define SCRATCH_FLOATS 33554432

__device__ float g_scratch[SCRATCH_FLOATS];

// ---------------------------------------------------------------------------
// TF32 tensor-core GEMM: C[M,N] = A[M,K] * W[N,K]^T + bias[N], optional ReLU.
// Block tile 128x128, BK=16, 256 threads (8 warps, 4x2), warp tile 32x64.
// mma.m16n8k8 tf32, ldmatrix fragments, cp.async double buffering.
// ---------------------------------------------------------------------------
#define BM 128
#define BN 128
#define BK 16
#define STR 20   // smem row stride in floats (conflict-free for ldsm)

__device__ __forceinline__ void cp_async16(void* smem_ptr, const void* gmem_ptr) {
    unsigned saddr = (unsigned)__cvta_generic_to_shared(smem_ptr);
    asm volatile("cp.async.cg.shared.global [%0], [%1], 16;\n"
                 :: "r"(saddr), "l"(gmem_ptr));
}
__device__ __forceinline__ void cp_commit() {
    asm volatile("cp.async.commit_group;\n");
}
__device__ __forceinline__ void cp_wait0() {
    asm volatile("cp.async.wait_group 0;\n");
}
__device__ __forceinline__ void ldsm_x4(unsigned& r0, unsigned& r1, unsigned& r2, unsigned& r3,
                                        const float* p) {
    unsigned saddr = (unsigned)__cvta_generic_to_shared((void*)p);
    asm volatile("ldmatrix.sync.aligned.m8n8.x4.shared.b16 {%0,%1,%2,%3}, [%4];\n"
                 : "=r"(r0), "=r"(r1), "=r"(r2), "=r"(r3) : "r"(saddr));
}
__device__ __forceinline__ void mma_tf32(float& c0, float& c1, float& c2, float& c3,
                                         unsigned a0, unsigned a1, unsigned a2, unsigned a3,
                                         unsigned b0, unsigned b1) {
    asm volatile("mma.sync.aligned.m16n8k8.row.col.f32.tf32.tf32.f32 "
                 "{%0,%1,%2,%3}, {%4,%5,%6,%7}, {%8,%9}, {%0,%1,%2,%3};\n"
                 : "+f"(c0), "+f"(c1), "+f"(c2), "+f"(c3)
                 : "r"(a0), "r"(a1), "r"(a2), "r"(a3), "r"(b0), "r"(b1));
}

__global__ void __launch_bounds__(256) gemm_tf32_kernel(
    const float* __restrict__ A, const float* __restrict__ Wt,
    const float* __restrict__ bias, float* __restrict__ C,
    int M, int N, int K, int relu)
{
    __shared__ __align__(16) float As[2][BM * STR];
    __shared__ __align__(16) float Bs[2][BN * STR];

    const int tid  = threadIdx.x;
    const int wid  = tid >> 5;
    const int lane = tid & 31;
    const int wm   = (wid & 3) * 32;   // warp row offset within block
    const int wn   = (wid >> 2) * 64;  // warp col offset within block
    const int m0   = blockIdx.y * BM;
    const int n0   = blockIdx.x * BN;

    // loader mapping: 256 threads, 16B each, 2 passes per tile
    const int lrow = tid >> 2;       // 0..63
    const int lcol = (tid & 3) * 4;  // float offset in k

    float acc[2][8][4];
#pragma unroll
    for (int i = 0; i < 2; ++i)
#pragma unroll
        for (int j = 0; j < 8; ++j)
#pragma unroll
            for (int q = 0; q < 4; ++q) acc[i][j][q] = 0.f;

    const int ntiles = K / BK;

    // prologue: load stage 0
    {
        const float* Ab = A + (size_t)m0 * K;
        const float* Bb = Wt + (size_t)n0 * K;
#pragma unroll
        for (int p = 0; p < 2; ++p) {
            int r = lrow + p * 64;
            cp_async16(&As[0][r * STR + lcol], Ab + (size_t)r * K + lcol);
            cp_async16(&Bs[0][r * STR + lcol], Bb + (size_t)r * K + lcol);
        }
        cp_commit();
    }

    // ldsm source addresses (per-lane, buffer-relative offsets)
    const int a_row = wm + (lane & 15);
    const int a_koff = (lane >> 4) * 4;
    const int b_row_base = wn + (lane & 7) + ((lane >> 4) * 8);
    const int b_koff = ((lane >> 3) & 1) * 4;

    for (int t = 0; t < ntiles; ++t) {
        cp_wait0();
        __syncthreads();

        int buf = t & 1;
        if (t + 1 < ntiles) {
            int nb = (t + 1) & 1;
            int k0 = (t + 1) * BK;
            const float* Ab = A + (size_t)m0 * K + k0;
            const float* Bb = Wt + (size_t)n0 * K + k0;
#pragma unroll
            for (int p = 0; p < 2; ++p) {
                int r = lrow + p * 64;
                cp_async16(&As[nb][r * STR + lcol], Ab + (size_t)r * K + lcol);
                cp_async16(&Bs[nb][r * STR + lcol], Bb + (size_t)r * K + lcol);
            }
            cp_commit();
        }

#pragma unroll
        for (int ks = 0; ks < 2; ++ks) {
            unsigned a[2][4];
            unsigned b[8][2];
#pragma unroll
            for (int im = 0; im < 2; ++im) {
                const float* p = &As[buf][(a_row + im * 16) * STR + ks * 8 + a_koff];
                ldsm_x4(a[im][0], a[im][1], a[im][2], a[im][3], p);
            }
#pragma unroll
            for (int it = 0; it < 4; ++it) {
                const float* p = &Bs[buf][(b_row_base + it * 16) * STR + ks * 8 + b_koff];
                unsigned r0, r1, r2, r3;
                ldsm_x4(r0, r1, r2, r3, p);
                b[it * 2][0] = r0; b[it * 2][1] = r1;
                b[it * 2 + 1][0] = r2; b[it * 2 + 1][1] = r3;
            }
#pragma unroll
            for (int im = 0; im < 2; ++im)
#pragma unroll
                for (int in = 0; in < 8; ++in)
                    mma_tf32(acc[im][in][0], acc[im][in][1], acc[im][in][2], acc[im][in][3],
                             a[im][0], a[im][1], a[im][2], a[im][3],
                             b[in][0], b[in][1]);
        }
        __syncthreads();
    }

    // epilogue
    const int row_base = m0 + wm + (lane >> 2);
    const int col_base = n0 + wn + (lane & 3) * 2;
#pragma unroll
    for (int im = 0; im < 2; ++im) {
#pragma unroll
        for (int in = 0; in < 8; ++in) {
            int col = col_base + in * 8;
            float b0 = bias[col], b1 = bias[col + 1];
            int r0 = row_base + im * 16;
            float v0 = acc[im][in][0] + b0;
            float v1 = acc[im][in][1] + b1;
            float v2 = acc[im][in][2] + b0;
            float v3 = acc[im][in][3] + b1;
            if (relu) {
                v0 = fmaxf(v0, 0.f); v1 = fmaxf(v1, 0.f);
                v2 = fmaxf(v2, 0.f); v3 = fmaxf(v3, 0.f);
            }
            C[(size_t)r0 * N + col] = v0;
            C[(size_t)r0 * N + col + 1] = v1;
            C[(size_t)(r0 + 8) * N + col] = v2;
            C[(size_t)(r0 + 8) * N + col + 1] = v3;
        }
    }
}

// ---------------------------------------------------------------------------
// Flash-style full self-attention over qkv buffer [T,B,3D].
// ---------------------------------------------------------------------------
__global__ void __launch_bounds__(128) self_attn_kernel(
    const float* __restrict__ qkv, float* __restrict__ out)
{
    __shared__ float Ks[32 * 64];
    __shared__ float Vs[32 * 64];
    __shared__ float Ss[32 * 128];

    const int tid = threadIdx.x;
    const int b = blockIdx.y >> 3;
    const int h = blockIdx.y & 7;
    const int t = blockIdx.x * 128 + tid;

    const float* qp = qkv + ((size_t)t * B_ + b) * (3 * D_) + h * HD_;
    float qreg[64];
#pragma unroll
    for (int d = 0; d < 64; ++d) qreg[d] = qp[d];

    float accv[64];
#pragma unroll
    for (int d = 0; d < 64; ++d) accv[d] = 0.f;
    float m = -1e30f, l = 0.f;

    for (int kt = 0; kt < 32; ++kt) {
        __syncthreads();
#pragma unroll
        for (int i = 0; i < 16; ++i) {
            int idx = i * 128 + tid;
            int r = idx >> 6, d = idx & 63;
            int row = kt * 32 + r;
            const float* kp = qkv + ((size_t)row * B_ + b) * (3 * D_) + D_ + h * HD_;
            Ks[r * 64 + d] = kp[d];
            Vs[r * 64 + d] = kp[D_ + d];
        }
        __syncthreads();

        for (int j = 0; j < 32; ++j) {
            const float* kr = &Ks[j * 64];
            float s = 0.f;
#pragma unroll
            for (int d = 0; d < 64; ++d) s += qreg[d] * kr[d];
            Ss[j * 128 + tid] = s * SCALE_;
        }

        float mt = -1e30f;
#pragma unroll
        for (int j = 0; j < 32; ++j) mt = fmaxf(mt, Ss[j * 128 + tid]);
        float mn = fmaxf(m, mt);
        float corr = __expf(m - mn);
        l *= corr;
#pragma unroll
        for (int d = 0; d < 64; ++d) accv[d] *= corr;

        for (int j = 0; j < 32; ++j) {
            float p = __expf(Ss[j * 128 + tid] - mn);
            l += p;
            const float* vr = &Vs[j * 64];
#pragma unroll
            for (int d = 0; d < 64; ++d) accv[d] += p * vr[d];
        }
        m = mn;
    }

    float inv = 1.f / l;
    float* op = out + ((size_t)t * B_ + b) * D_ + h * HD_;
#pragma unroll
    for (int d = 0; d < 64; ++d) op[d] = accv[d] * inv;
}

// ---------------------------------------------------------------------------
// Sliding-window cross-attention. One warp per (t,b,h); lane owns 2 dims.
// ---------------------------------------------------------------------------
__global__ void __launch_bounds__(256) sw_attn_kernel(
    const float* __restrict__ q, const float* __restrict__ k,
    const float* __restrict__ v, float* __restrict__ out)
{
    const int gw = (blockIdx.x * blockDim.x + threadIdx.x) >> 5;
    const int lane = threadIdx.x & 31;
    if (gw >= T_ * B_ * H_) return;
    const int h = gw & 7;
    const int b = (gw >> 3) & 3;
    const int t = gw >> 5;

    const float2 q2 = reinterpret_cast<const float2*>(
        q + ((size_t)t * B_ + b) * D_ + h * HD_)[lane];

    float sc[33];
#pragma unroll
    for (int jj = 0; jj < 33; ++jj) {
        int j = t - W_ + jj;
        float s = -1e30f;
        if (j >= 0 && j < S_) {
            const float2 k2 = reinterpret_cast<const float2*>(
                k + ((size_t)j * B_ + b) * D_ + h * HD_)[lane];
            float p = q2.x * k2.x + q2.y * k2.y;
#pragma unroll
            for (int o = 16; o > 0; o >>= 1)
                p += __shfl_xor_sync(0xffffffffu, p, o);
            s = p * SCALE_;
        }
        sc[jj] = s;
    }

    float m = -1e30f;
#pragma unroll
    for (int jj = 0; jj < 33; ++jj) m = fmaxf(m, sc[jj]);

    float l = 0.f, a0 = 0.f, a1 = 0.f;
#pragma unroll
    for (int jj = 0; jj < 33; ++jj) {
        int j = t - W_ + jj;
        if (j >= 0 && j < S_) {
            float p = __expf(sc[jj] - m);
            l += p;
            const float2 v2 = reinterpret_cast<const float2*>(
                v + ((size_t)j * B_ + b) * D_ + h * HD_)[lane];
            a0 += p * v2.x;
            a1 += p * v2.y;
        }
    }
    float inv = 1.f / l;
    float* op = out + ((size_t)t * B_ + b) * D_ + h * HD_;
    op[lane * 2] = a0 * inv;
    op[lane * 2 + 1] = a1 * inv;
}

// ---------------------------------------------------------------------------
// Fused residual-add + LayerNorm over D=512.
// ---------------------------------------------------------------------------
__global__ void __launch_bounds__(256) add_ln_kernel(
    const float* __restrict__ x, const float* __restrict__ y,
    const float* __restrict__ g, const float* __restrict__ beta,
    float* __restrict__ out)
{
    __shared__ float sh[33];
    const int row = blockIdx.x;
    const int tid = threadIdx.x;
    const size_t base = (size_t)row * D_;

    float v0 = x[base + tid] + y[base + tid];
    float v1 = x[base + tid + 256] + y[base + tid + 256];

    float s = v0 + v1;
#pragma unroll
    for (int o = 16; o > 0; o >>= 1) s += __shfl_xor_sync(0xffffffffu, s, o);
    int lane = tid & 31, wid = tid >> 5;
    if (lane == 0) sh[wid] = s;
    __syncthreads();
    if (wid == 0) {
        float t = (lane < 8) ? sh[lane] : 0.f;
#pragma unroll
        for (int o = 4; o > 0; o >>= 1) t += __shfl_xor_sync(0xffffffffu, t, o);
        if (lane == 0) sh[32] = t;
    }
    __syncthreads();
    float mean = sh[32] * (1.f / D_);
    __syncthreads();

    float d0 = v0 - mean, d1 = v1 - mean;
    float sq = d0 * d0 + d1 * d1;
#pragma unroll
    for (int o = 16; o > 0; o >>= 1) sq += __shfl_xor_sync(0xffffffffu, sq, o);
    if (lane == 0) sh[wid] = sq;
    __syncthreads();
    if (wid == 0) {
        float t = (lane < 8) ? sh[lane] : 0.f;
#pragma unroll
        for (int o = 4; o > 0; o >>= 1) t += __shfl_xor_sync(0xffffffffu, t, o);
        if (lane == 0) sh[32] = t;
    }
    __syncthreads();
    float rstd = rsqrtf(sh[32] * (1.f / D_) + EPS_);

    out[base + tid] = d0 * rstd * g[tid] + beta[tid];
    out[base + tid + 256] = d1 * rstd * g[tid + 256] + beta[tid + 256];
}

// ---------------------------------------------------------------------------
// Launch
// ---------------------------------------------------------------------------
extern "C" void kernel_launch(void* const* d_in, const int* in_sizes, int n_in,
                              void* d_out, int out_size)
{
    (void)in_sizes; (void)n_in; (void)out_size;
    const float* tgt        = (const float*)d_in[0];
    const float* memory     = (const float*)d_in[1];
    const float* in_proj_w  = (const float*)d_in[2];
    const float* in_proj_b  = (const float*)d_in[3];
    const float* out_proj_w = (const float*)d_in[4];
    const float* out_proj_b = (const float*)d_in[5];
    const float* sw_q_w = (const float*)d_in[6];
    const float* sw_q_b = (const float*)d_in[7];
    const float* sw_k_w = (const float*)d_in[8];
    const float* sw_k_b = (const float*)d_in[9];
    const float* sw_v_w = (const float*)d_in[10];
    const float* sw_v_b = (const float*)d_in[11];
    const float* sw_o_w = (const float*)d_in[12];
    const float* sw_o_b = (const float*)d_in[13];
    const float* lin1_w = (const float*)d_in[14];
    const float* lin1_b = (const float*)d_in[15];
    const float* lin2_w = (const float*)d_in[16];
    const float* lin2_b = (const float*)d_in[17];
    const float* n1_g = (const float*)d_in[18];
    const float* n1_b = (const float*)d_in[19];
    const float* n2_g = (const float*)d_in[20];
    const float* n2_b = (const float*)d_in[21];
    const float* n3_g = (const float*)d_in[22];
    const float* n3_b = (const float*)d_in[23];
    float* out = (float*)d_out;

    float* s = nullptr;
    cudaGetSymbolAddress((void**)&s, g_scratch);
    float* qkv    = s + OFF_QKV;
    float* attn   = s + OFF_ATTN;
    float* proj   = s + OFF_PROJ;
    float* x1     = s + OFF_X1;
    float* swq    = s + OFF_SWQ;
    float* swk    = s + OFF_SWK;
    float* swv    = s + OFF_SWV;
    float* swattn = s + OFF_SWATTN;
    float* x2     = s + OFF_X2;
    float* hbuf   = s + OFF_H;
    float* ffbuf  = s + OFF_FF;

    // 1. QKV projection: [4096,512] x [1536,512]^T
    gemm_tf32_kernel<<<dim3(12, 32), 256>>>(tgt, in_proj_w, in_proj_b, qkv,
                                            NROWS, 3 * D_, D_, 0);
    // 2. self attention
    self_attn_kernel<<<dim3(8, 32), 128>>>(qkv, attn);
    // 3. out projection
    gemm_tf32_kernel<<<dim3(4, 32), 256>>>(attn, out_proj_w, out_proj_b, proj,
                                           NROWS, D_, D_, 0);
    // 4. add + LN1
    add_ln_kernel<<<NROWS, 256>>>(tgt, proj, n1_g, n1_b, x1);
    // 5-7. sliding-window projections
    gemm_tf32_kernel<<<dim3(4, 32), 256>>>(x1, sw_q_w, sw_q_b, swq, NROWS, D_, D_, 0);
    gemm_tf32_kernel<<<dim3(4, 32), 256>>>(memory, sw_k_w, sw_k_b, swk, NROWS, D_, D_, 0);
    gemm_tf32_kernel<<<dim3(4, 32), 256>>>(memory, sw_v_w, sw_v_b, swv, NROWS, D_, D_, 0);
    // 8. banded attention
    sw_attn_kernel<<<4096, 256>>>(swq, swk, swv, swattn);
    // 9. sw out projection
    gemm_tf32_kernel<<<dim3(4, 32), 256>>>(swattn, sw_o_w, sw_o_b, proj, NROWS, D_, D_, 0);
    // 10. add + LN2
    add_ln_kernel<<<NROWS, 256>>>(x1, proj, n2_g, n2_b, x2);
    // 11. FFN up + ReLU
    gemm_tf32_kernel<<<dim3(16, 32), 256>>>(x2, lin1_w, lin1_b, hbuf, NROWS, DFF_, D_, 1);
    // 12. FFN down
    gemm_tf32_kernel<<<dim3(4, 32), 256>>>(hbuf, lin2_w, lin2_b, ffbuf, NROWS, D_, DFF_, 0);
    // 13. add + LN3 -> output
    add_ln_kernel<<<NROWS, 256>>>(x2, ffbuf, n3_g, n3_b, out);
}

// round 3
// speedup vs baseline: 2.7783x; 1.4988x over previous
#include <cuda_runtime.h>
#include <cuda_bf16.h>
#include <math.h>

// Problem constants
#define T_ 1024
#define S_ 1024
#define B_ 4
#define D_ 512
#define H_ 8
#define HD_ 64
#define DFF_ 2048
#define W_ 16
#define NROWS (T_ * B_)
#define SCALE_ 0.125f
#define EPS_ 1e-5f

// ---------------------------------------------------------------------------
// Scratch
// ---------------------------------------------------------------------------
#define OFF_QKV     0
#define OFF_ATTN    6291456
#define OFF_PROJ    8388608
#define OFF_X1      10485760
#define OFF_SWQ     12582912
#define OFF_SWK     14680064
#define OFF_SWV     16777216
#define OFF_SWATTN  18874368
#define OFF_X2      20971520
#define OFF_H       23068672
#define OFF_FF      31457280
#define SCRATCH_FLOATS 33554432

__device__ float g_scratch[SCRATCH_FLOATS];

// ---------------------------------------------------------------------------
// Shared PTX helpers
// ---------------------------------------------------------------------------
__device__ __forceinline__ void cp_async16(void* smem_ptr, const void* gmem_ptr) {
    unsigned saddr = (unsigned)__cvta_generic_to_shared(smem_ptr);
    asm volatile("cp.async.cg.shared.global [%0], [%1], 16;\n"
                 :: "r"(saddr), "l"(gmem_ptr));
}
__device__ __forceinline__ void cp_commit() {
    asm volatile("cp.async.commit_group;\n");
}
__device__ __forceinline__ void cp_wait0() {
    asm volatile("cp.async.wait_group 0;\n");
}
__device__ __forceinline__ void cp_wait1() {
    asm volatile("cp.async.wait_group 1;\n");
}
__device__ __forceinline__ void ldsm_x4(unsigned& r0, unsigned& r1, unsigned& r2, unsigned& r3,
                                        const float* p) {
    unsigned saddr = (unsigned)__cvta_generic_to_shared((void*)p);
    asm volatile("ldmatrix.sync.aligned.m8n8.x4.shared.b16 {%0,%1,%2,%3}, [%4];\n"
                 : "=r"(r0), "=r"(r1), "=r"(r2), "=r"(r3) : "r"(saddr));
}
__device__ __forceinline__ void mma_tf32(float& c0, float& c1, float& c2, float& c3,
                                         unsigned a0, unsigned a1, unsigned a2, unsigned a3,
                                         unsigned b0, unsigned b1) {
    asm volatile("mma.sync.aligned.m16n8k8.row.col.f32.tf32.tf32.f32 "
                 "{%0,%1,%2,%3}, {%4,%5,%6,%7}, {%8,%9}, {%0,%1,%2,%3};\n"
                 : "+f"(c0), "+f"(c1), "+f"(c2), "+f"(c3)
                 : "r"(a0), "r"(a1), "r"(a2), "r"(a3), "r"(b0), "r"(b1));
}

// ---------------------------------------------------------------------------
// TF32 tensor-core GEMM: C[M,N] = A[M,K] * W[N,K]^T + bias[N], optional ReLU.
// ---------------------------------------------------------------------------
#define BM 128
#define BN 128
#define BK 16
#define STR 20

__global__ void __launch_bounds__(256) gemm_tf32_kernel(
    const float* __restrict__ A, const float* __restrict__ Wt,
    const float* __restrict__ bias, float* __restrict__ C,
    int M, int N, int K, int relu)
{
    __shared__ __align__(16) float As[2][BM * STR];
    __shared__ __align__(16) float Bs[2][BN * STR];

    const int tid  = threadIdx.x;
    const int wid  = tid >> 5;
    const int lane = tid & 31;
    const int wm   = (wid & 3) * 32;
    const int wn   = (wid >> 2) * 64;
    const int m0   = blockIdx.y * BM;
    const int n0   = blockIdx.x * BN;

    const int lrow = tid >> 2;
    const int lcol = (tid & 3) * 4;

    float acc[2][8][4];
#pragma unroll
    for (int i = 0; i < 2; ++i)
#pragma unroll
        for (int j = 0; j < 8; ++j)
#pragma unroll
            for (int q = 0; q < 4; ++q) acc[i][j][q] = 0.f;

    const int ntiles = K / BK;

    {
        const float* Ab = A + (size_t)m0 * K;
        const float* Bb = Wt + (size_t)n0 * K;
#pragma unroll
        for (int p = 0; p < 2; ++p) {
            int r = lrow + p * 64;
            cp_async16(&As[0][r * STR + lcol], Ab + (size_t)r * K + lcol);
            cp_async16(&Bs[0][r * STR + lcol], Bb + (size_t)r * K + lcol);
        }
        cp_commit();
    }

    const int a_row = wm + (lane & 15);
    const int a_koff = (lane >> 4) * 4;
    const int b_row_base = wn + (lane & 7) + ((lane >> 4) * 8);
    const int b_koff = ((lane >> 3) & 1) * 4;

    for (int t = 0; t < ntiles; ++t) {
        cp_wait0();
        __syncthreads();

        int buf = t & 1;
        if (t + 1 < ntiles) {
            int nb = (t + 1) & 1;
            int k0 = (t + 1) * BK;
            const float* Ab = A + (size_t)m0 * K + k0;
            const float* Bb = Wt + (size_t)n0 * K + k0;
#pragma unroll
            for (int p = 0; p < 2; ++p) {
                int r = lrow + p * 64;
                cp_async16(&As[nb][r * STR + lcol], Ab + (size_t)r * K + lcol);
                cp_async16(&Bs[nb][r * STR + lcol], Bb + (size_t)r * K + lcol);
            }
            cp_commit();
        }

#pragma unroll
        for (int ks = 0; ks < 2; ++ks) {
            unsigned a[2][4];
            unsigned b[8][2];
#pragma unroll
            for (int im = 0; im < 2; ++im) {
                const float* p = &As[buf][(a_row + im * 16) * STR + ks * 8 + a_koff];
                ldsm_x4(a[im][0], a[im][1], a[im][2], a[im][3], p);
            }
#pragma unroll
            for (int it = 0; it < 4; ++it) {
                const float* p = &Bs[buf][(b_row_base + it * 16) * STR + ks * 8 + b_koff];
                unsigned r0, r1, r2, r3;
                ldsm_x4(r0, r1, r2, r3, p);
                b[it * 2][0] = r0; b[it * 2][1] = r1;
                b[it * 2 + 1][0] = r2; b[it * 2 + 1][1] = r3;
            }
#pragma unroll
            for (int im = 0; im < 2; ++im)
#pragma unroll
                for (int in = 0; in < 8; ++in)
                    mma_tf32(acc[im][in][0], acc[im][in][1], acc[im][in][2], acc[im][in][3],
                             a[im][0], a[im][1], a[im][2], a[im][3],
                             b[in][0], b[in][1]);
        }
        __syncthreads();
    }

    const int row_base = m0 + wm + (lane >> 2);
    const int col_base = n0 + wn + (lane & 3) * 2;
#pragma unroll
    for (int im = 0; im < 2; ++im) {
#pragma unroll
        for (int in = 0; in < 8; ++in) {
            int col = col_base + in * 8;
            float b0 = bias[col], b1 = bias[col + 1];
            int r0 = row_base + im * 16;
            float v0 = acc[im][in][0] + b0;
            float v1 = acc[im][in][1] + b1;
            float v2 = acc[im][in][2] + b0;
            float v3 = acc[im][in][3] + b1;
            if (relu) {
                v0 = fmaxf(v0, 0.f); v1 = fmaxf(v1, 0.f);
                v2 = fmaxf(v2, 0.f); v3 = fmaxf(v3, 0.f);
            }
            C[(size_t)r0 * N + col] = v0;
            C[(size_t)r0 * N + col + 1] = v1;
            C[(size_t)(r0 + 8) * N + col] = v2;
            C[(size_t)(r0 + 8) * N + col + 1] = v3;
        }
    }
}

// ---------------------------------------------------------------------------
// TF32 flash self-attention. Block = 128 query rows, 256 threads (8 warps x
// 16 rows), one (b,h) per blockIdx.y. K/V tiles of 64 keys, double-buffered.
// smem layout (floats, stride 68):
//   Ps[128*68]  : Q staging then per-warp-private P tiles
//   Ks[2*64*68] : K double buffer
//   Vt[2*64*68] : V transposed (rows=hd, cols=key, xor-swizzled)
// ---------------------------------------------------------------------------
#define ASTR 68
#define KBUF (64 * ASTR)
#define ROWF 6144   // (t+1) row step in qkv floats = B_*3*D_

__global__ void __launch_bounds__(256) self_attn_mma_kernel(
    const float* __restrict__ qkv, float* __restrict__ out)
{
    extern __shared__ float sm[];
    float* Ps = sm;
    float* Ks = sm + 128 * ASTR;
    float* Vt = sm + 256 * ASTR;

    const int tid = threadIdx.x;
    const int wid = tid >> 5;
    const int lane = tid & 31;
    const int b = blockIdx.y >> 3;
    const int h = blockIdx.y & 7;
    const int t0 = blockIdx.x * 128;
    const int wm = wid * 16;

    const float* qbase = qkv + ((size_t)t0 * B_ + b) * 1536 + h * 64;
    const float* kroot = qkv + (size_t)b * 1536 + 512 + h * 64;
    const float* vroot = qkv + (size_t)b * 1536 + 1024 + h * 64;

    // static per-thread load mapping (16 floats of a 64x64 tile)
    int vkey[4], vc[4];
#pragma unroll
    for (int i = 0; i < 4; ++i) {
        int fidx = i * 256 + tid;
        vkey[i] = fidx >> 4;
        vc[i] = (fidx & 15) * 4;
    }

    // prologue: Q -> Ps, K0 -> Ks[0] via cp.async; V0 via LDG
#pragma unroll
    for (int i = 0; i < 8; ++i) {
        int fidx = i * 256 + tid;
        int r = fidx >> 4, c = (fidx & 15) * 4;
        cp_async16(&Ps[r * ASTR + c], qbase + (size_t)r * ROWF + c);
    }
#pragma unroll
    for (int i = 0; i < 4; ++i)
        cp_async16(&Ks[vkey[i] * ASTR + vc[i]], kroot + (size_t)vkey[i] * ROWF + vc[i]);
    cp_commit();

    float4 vreg[4];
#pragma unroll
    for (int i = 0; i < 4; ++i)
        vreg[i] = *reinterpret_cast<const float4*>(vroot + (size_t)vkey[i] * ROWF + vc[i]);

    cp_wait0();
    __syncthreads();

    // Q fragments (pre-scaled by SCALE_), held for all tiles
    unsigned qf[8][4];
    {
        const int a_row = wm + (lane & 15);
        const int a_koff = (lane >> 4) * 4;
#pragma unroll
        for (int ks = 0; ks < 8; ++ks) {
            unsigned r0, r1, r2, r3;
            ldsm_x4(r0, r1, r2, r3, &Ps[a_row * ASTR + ks * 8 + a_koff]);
            qf[ks][0] = __float_as_uint(__uint_as_float(r0) * SCALE_);
            qf[ks][1] = __float_as_uint(__uint_as_float(r1) * SCALE_);
            qf[ks][2] = __float_as_uint(__uint_as_float(r2) * SCALE_);
            qf[ks][3] = __float_as_uint(__uint_as_float(r3) * SCALE_);
        }
    }

    // store V0 transposed into Vt[0]
#pragma unroll
    for (int i = 0; i < 4; ++i) {
        float v[4] = {vreg[i].x, vreg[i].y, vreg[i].z, vreg[i].w};
#pragma unroll
        for (int j = 0; j < 4; ++j) {
            int hd = vc[i] + j;
            Vt[hd * ASTR + (vkey[i] ^ (4 * ((hd >> 5) & 1)))] = v[j];
        }
    }

    float o[8][4];
#pragma unroll
    for (int n = 0; n < 8; ++n)
#pragma unroll
        for (int c = 0; c < 4; ++c) o[n][c] = 0.f;
    float m0 = -1e30f, m1 = -1e30f, l0 = 0.f, l1 = 0.f;

    const int brow_base = (lane & 7) + ((lane >> 4) * 8);
    const int bko = ((lane >> 3) & 1) * 4;
    const int prow0 = wm + (lane >> 2);
    const int pcol = 2 * (lane & 3);
    const int a_row = wm + (lane & 15);
    const int a_koff = (lane >> 4) * 4;

    for (int kt = 0; kt < 16; ++kt) {
        const int buf = kt & 1;
        __syncthreads();

        if (kt + 1 < 16) {
            const float* kb = kroot + (size_t)(kt + 1) * 64 * ROWF;
            float* kd = Ks + (buf ^ 1) * KBUF;
#pragma unroll
            for (int i = 0; i < 4; ++i)
                cp_async16(&kd[vkey[i] * ASTR + vc[i]], kb + (size_t)vkey[i] * ROWF + vc[i]);
            cp_commit();
            const float* vb = vroot + (size_t)(kt + 1) * 64 * ROWF;
#pragma unroll
            for (int i = 0; i < 4; ++i)
                vreg[i] = *reinterpret_cast<const float4*>(vb + (size_t)vkey[i] * ROWF + vc[i]);
            cp_wait1();
        } else {
            cp_wait0();
        }
        __syncthreads();

        // ---- S = Q K^T (16 rows x 64 keys per warp) ----
        const float* Kb = Ks + buf * KBUF;
        float s[8][4];
#pragma unroll
        for (int n = 0; n < 8; ++n)
#pragma unroll
            for (int c = 0; c < 4; ++c) s[n][c] = 0.f;
#pragma unroll
        for (int ks = 0; ks < 8; ++ks) {
#pragma unroll
            for (int ng = 0; ng < 4; ++ng) {
                unsigned r0, r1, r2, r3;
                ldsm_x4(r0, r1, r2, r3, &Kb[(brow_base + ng * 16) * ASTR + ks * 8 + bko]);
                mma_tf32(s[ng * 2][0], s[ng * 2][1], s[ng * 2][2], s[ng * 2][3],
                         qf[ks][0], qf[ks][1], qf[ks][2], qf[ks][3], r0, r1);
                mma_tf32(s[ng * 2 + 1][0], s[ng * 2 + 1][1], s[ng * 2 + 1][2], s[ng * 2 + 1][3],
                         qf[ks][0], qf[ks][1], qf[ks][2], qf[ks][3], r2, r3);
            }
        }

        // ---- online softmax on fragments ----
        float mx0 = -1e30f, mx1 = -1e30f;
#pragma unroll
        for (int n = 0; n < 8; ++n) {
            mx0 = fmaxf(mx0, fmaxf(s[n][0], s[n][1]));
            mx1 = fmaxf(mx1, fmaxf(s[n][2], s[n][3]));
        }
        mx0 = fmaxf(mx0, __shfl_xor_sync(0xffffffffu, mx0, 1));
        mx0 = fmaxf(mx0, __shfl_xor_sync(0xffffffffu, mx0, 2));
        mx1 = fmaxf(mx1, __shfl_xor_sync(0xffffffffu, mx1, 1));
        mx1 = fmaxf(mx1, __shfl_xor_sync(0xffffffffu, mx1, 2));

        float mn0 = fmaxf(m0, mx0), mn1 = fmaxf(m1, mx1);
        float corr0 = __expf(m0 - mn0), corr1 = __expf(m1 - mn1);
        m0 = mn0; m1 = mn1;
        l0 *= corr0; l1 *= corr1;
#pragma unroll
        for (int n = 0; n < 8; ++n) {
            o[n][0] *= corr0; o[n][1] *= corr0;
            o[n][2] *= corr1; o[n][3] *= corr1;
        }
#pragma unroll
        for (int n = 0; n < 8; ++n) {
            float p0 = __expf(s[n][0] - mn0);
            float p1 = __expf(s[n][1] - mn0);
            float p2 = __expf(s[n][2] - mn1);
            float p3 = __expf(s[n][3] - mn1);
            l0 += p0 + p1; l1 += p2 + p3;
            // store P to warp-private smem rows
            *reinterpret_cast<float2*>(&Ps[prow0 * ASTR + n * 8 + pcol]) = make_float2(p0, p1);
            *reinterpret_cast<float2*>(&Ps[(prow0 + 8) * ASTR + n * 8 + pcol]) = make_float2(p2, p3);
        }
        __syncwarp();

        // ---- O += P V ----
        const float* Vb = Vt + buf * KBUF;
#pragma unroll
        for (int ks = 0; ks < 8; ++ks) {
            unsigned a0, a1, a2, a3;
            ldsm_x4(a0, a1, a2, a3, &Ps[a_row * ASTR + ks * 8 + a_koff]);
#pragma unroll
            for (int ng = 0; ng < 4; ++ng) {
                int br = brow_base + ng * 16;
                unsigned r0, r1, r2, r3;
                ldsm_x4(r0, r1, r2, r3,
                        &Vb[br * ASTR + ((ks * 8 + bko) ^ (4 * ((br >> 5) & 1)))]);
                mma_tf32(o[ng * 2][0], o[ng * 2][1], o[ng * 2][2], o[ng * 2][3],
                         a0, a1, a2, a3, r0, r1);
                mma_tf32(o[ng * 2 + 1][0], o[ng * 2 + 1][1], o[ng * 2 + 1][2], o[ng * 2 + 1][3],
                         a0, a1, a2, a3, r2, r3);
            }
        }

        // stage next V into the other buffer
        if (kt + 1 < 16) {
            float* Vd = Vt + (buf ^ 1) * KBUF;
#pragma unroll
            for (int i = 0; i < 4; ++i) {
                float v[4] = {vreg[i].x, vreg[i].y, vreg[i].z, vreg[i].w};
#pragma unroll
                for (int j = 0; j < 4; ++j) {
                    int hd = vc[i] + j;
                    Vd[hd * ASTR + (vkey[i] ^ (4 * ((hd >> 5) & 1)))] = v[j];
                }
            }
        }
    }

    // epilogue: normalize and store
    l0 += __shfl_xor_sync(0xffffffffu, l0, 1);
    l0 += __shfl_xor_sync(0xffffffffu, l0, 2);
    l1 += __shfl_xor_sync(0xffffffffu, l1, 1);
    l1 += __shfl_xor_sync(0xffffffffu, l1, 2);
    float inv0 = 1.f / l0, inv1 = 1.f / l1;

    float* ob0 = out + ((size_t)(t0 + prow0) * B_ + b) * D_ + h * 64 + pcol;
    float* ob1 = out + ((size_t)(t0 + prow0 + 8) * B_ + b) * D_ + h * 64 + pcol;
#pragma unroll
    for (int n = 0; n < 8; ++n) {
        *reinterpret_cast<float2*>(ob0 + n * 8) = make_float2(o[n][0] * inv0, o[n][1] * inv0);
        *reinterpret_cast<float2*>(ob1 + n * 8) = make_float2(o[n][2] * inv1, o[n][3] * inv1);
    }
}

#define ATTN_SMEM (384 * ASTR * 4)

// ---------------------------------------------------------------------------
// Sliding-window cross-attention. One warp per (t,b,h); lane owns 2 dims.
// ---------------------------------------------------------------------------
__global__ void __launch_bounds__(256) sw_attn_kernel(
    const float* __restrict__ q, const float* __restrict__ k,
    const float* __restrict__ v, float* __restrict__ out)
{
    const int gw = (blockIdx.x * blockDim.x + threadIdx.x) >> 5;
    const int lane = threadIdx.x & 31;
    if (gw >= T_ * B_ * H_) return;
    const int h = gw & 7;
    const int b = (gw >> 3) & 3;
    const int t = gw >> 5;

    const float2 q2 = reinterpret_cast<const float2*>(
        q + ((size_t)t * B_ + b) * D_ + h * HD_)[lane];

    float sc[33];
#pragma unroll
    for (int jj = 0; jj < 33; ++jj) {
        int j = t - W_ + jj;
        float s = -1e30f;
        if (j >= 0 && j < S_) {
            const float2 k2 = reinterpret_cast<const float2*>(
                k + ((size_t)j * B_ + b) * D_ + h * HD_)[lane];
            float p = q2.x * k2.x + q2.y * k2.y;
#pragma unroll
            for (int o = 16; o > 0; o >>= 1)
                p += __shfl_xor_sync(0xffffffffu, p, o);
            s = p * SCALE_;
        }
        sc[jj] = s;
    }

    float m = -1e30f;
#pragma unroll
    for (int jj = 0; jj < 33; ++jj) m = fmaxf(m, sc[jj]);

    float l = 0.f, a0 = 0.f, a1 = 0.f;
#pragma unroll
    for (int jj = 0; jj < 33; ++jj) {
        int j = t - W_ + jj;
        if (j >= 0 && j < S_) {
            float p = __expf(sc[jj] - m);
            l += p;
            const float2 v2 = reinterpret_cast<const float2*>(
                v + ((size_t)j * B_ + b) * D_ + h * HD_)[lane];
            a0 += p * v2.x;
            a1 += p * v2.y;
        }
    }
    float inv = 1.f / l;
    float* op = out + ((size_t)t * B_ + b) * D_ + h * HD_;
    op[lane * 2] = a0 * inv;
    op[lane * 2 + 1] = a1 * inv;
}

// ---------------------------------------------------------------------------
// Fused residual-add + LayerNorm over D=512.
// ---------------------------------------------------------------------------
__global__ void __launch_bounds__(256) add_ln_kernel(
    const float* __restrict__ x, const float* __restrict__ y,
    const float* __restrict__ g, const float* __restrict__ beta,
    float* __restrict__ out)
{
    __shared__ float sh[33];
    const int row = blockIdx.x;
    const int tid = threadIdx.x;
    const size_t base = (size_t)row * D_;

    float v0 = x[base + tid] + y[base + tid];
    float v1 = x[base + tid + 256] + y[base + tid + 256];

    float s = v0 + v1;
#pragma unroll
    for (int o = 16; o > 0; o >>= 1) s += __shfl_xor_sync(0xffffffffu, s, o);
    int lane = tid & 31, wid = tid >> 5;
    if (lane == 0) sh[wid] = s;
    __syncthreads();
    if (wid == 0) {
        float t = (lane < 8) ? sh[lane] : 0.f;
#pragma unroll
        for (int o = 4; o > 0; o >>= 1) t += __shfl_xor_sync(0xffffffffu, t, o);
        if (lane == 0) sh[32] = t;
    }
    __syncthreads();
    float mean = sh[32] * (1.f / D_);
    __syncthreads();

    float d0 = v0 - mean, d1 = v1 - mean;
    float sq = d0 * d0 + d1 * d1;
#pragma unroll
    for (int o = 16; o > 0; o >>= 1) sq += __shfl_xor_sync(0xffffffffu, sq, o);
    if (lane == 0) sh[wid] = sq;
    __syncthreads();
    if (wid == 0) {
        float t = (lane < 8) ? sh[lane] : 0.f;
#pragma unroll
        for (int o = 4; o > 0; o >>= 1) t += __shfl_xor_sync(0xffffffffu, t, o);
        if (lane == 0) sh[32] = t;
    }
    __syncthreads();
    float rstd = rsqrtf(sh[32] * (1.f / D_) + EPS_);

    out[base + tid] = d0 * rstd * g[tid] + beta[tid];
    out[base + tid + 256] = d1 * rstd * g[tid + 256] + beta[tid + 256];
}

// ---------------------------------------------------------------------------
// Launch
// ---------------------------------------------------------------------------
extern "C" void kernel_launch(void* const* d_in, const int* in_sizes, int n_in,
                              void* d_out, int out_size)
{
    (void)in_sizes; (void)n_in; (void)out_size;
    const float* tgt        = (const float*)d_in[0];
    const float* memory     = (const float*)d_in[1];
    const float* in_proj_w  = (const float*)d_in[2];
    const float* in_proj_b  = (const float*)d_in[3];
    const float* out_proj_w = (const float*)d_in[4];
    const float* out_proj_b = (const float*)d_in[5];
    const float* sw_q_w = (const float*)d_in[6];
    const float* sw_q_b = (const float*)d_in[7];
    const float* sw_k_w = (const float*)d_in[8];
    const float* sw_k_b = (const float*)d_in[9];
    const float* sw_v_w = (const float*)d_in[10];
    const float* sw_v_b = (const float*)d_in[11];
    const float* sw_o_w = (const float*)d_in[12];
    const float* sw_o_b = (const float*)d_in[13];
    const float* lin1_w = (const float*)d_in[14];
    const float* lin1_b = (const float*)d_in[15];
    const float* lin2_w = (const float*)d_in[16];
    const float* lin2_b = (const float*)d_in[17];
    const float* n1_g = (const float*)d_in[18];
    const float* n1_b = (const float*)d_in[19];
    const float* n2_g = (const float*)d_in[20];
    const float* n2_b = (const float*)d_in[21];
    const float* n3_g = (const float*)d_in[22];
    const float* n3_b = (const float*)d_in[23];
    float* out = (float*)d_out;

    float* s = nullptr;
    cudaGetSymbolAddress((void**)&s, g_scratch);
    float* qkv    = s + OFF_QKV;
    float* attn   = s + OFF_ATTN;
    float* proj   = s + OFF_PROJ;
    float* x1     = s + OFF_X1;
    float* swq    = s + OFF_SWQ;
    float* swk    = s + OFF_SWK;
    float* swv    = s + OFF_SWV;
    float* swattn = s + OFF_SWATTN;
    float* x2     = s + OFF_X2;
    float* hbuf   = s + OFF_H;
    float* ffbuf  = s + OFF_FF;

    cudaFuncSetAttribute(self_attn_mma_kernel,
                         cudaFuncAttributeMaxDynamicSharedMemorySize, ATTN_SMEM);

    // 1. QKV projection
    gemm_tf32_kernel<<<dim3(12, 32), 256>>>(tgt, in_proj_w, in_proj_b, qkv,
                                            NROWS, 3 * D_, D_, 0);
    // 2. self attention (TF32 MMA flash)
    self_attn_mma_kernel<<<dim3(8, 32), 256, ATTN_SMEM>>>(qkv, attn);
    // 3. out projection
    gemm_tf32_kernel<<<dim3(4, 32), 256>>>(attn, out_proj_w, out_proj_b, proj,
                                           NROWS, D_, D_, 0);
    // 4. add + LN1
    add_ln_kernel<<<NROWS, 256>>>(tgt, proj, n1_g, n1_b, x1);
    // 5-7. sliding-window projections
    gemm_tf32_kernel<<<dim3(4, 32), 256>>>(x1, sw_q_w, sw_q_b, swq, NROWS, D_, D_, 0);
    gemm_tf32_kernel<<<dim3(4, 32), 256>>>(memory, sw_k_w, sw_k_b, swk, NROWS, D_, D_, 0);
    gemm_tf32_kernel<<<dim3(4, 32), 256>>>(memory, sw_v_w, sw_v_b, swv, NROWS, D_, D_, 0);
    // 8. banded attention
    sw_attn_kernel<<<4096, 256>>>(swq, swk, swv, swattn);
    // 9. sw out projection
    gemm_tf32_kernel<<<dim3(4, 32), 256>>>(swattn, sw_o_w, sw_o_b, proj, NROWS, D_, D_, 0);
    // 10. add + LN2
    add_ln_kernel<<<NROWS, 256>>>(x1, proj, n2_g, n2_b, x2);
    // 11. FFN up + ReLU
    gemm_tf32_kernel<<<dim3(16, 32), 256>>>(x2, lin1_w, lin1_b, hbuf, NROWS, DFF_, D_, 1);
    // 12. FFN down
    gemm_tf32_kernel<<<dim3(4, 32), 256>>>(hbuf, lin2_w, lin2_b, ffbuf, NROWS, D_, DFF_, 0);
    // 13. add + LN3 -> output
    add_ln_kernel<<<NROWS, 256>>>(x2, ffbuf, n3_g, n3_b, out);
}

// round 4
// speedup vs baseline: 2.9503x; 1.0619x over previous
#include <cuda_runtime.h>
#include <cuda_bf16.h>
#include <math.h>

// Problem constants
#define T_ 1024
#define S_ 1024
#define B_ 4
#define D_ 512
#define H_ 8
#define HD_ 64
#define DFF_ 2048
#define W_ 16
#define NROWS (T_ * B_)
#define SCALE_ 0.125f
#define EPS_ 1e-5f

// ---------------------------------------------------------------------------
// Scratch
// ---------------------------------------------------------------------------
#define OFF_QKV     0
#define OFF_ATTN    6291456
#define OFF_PROJ    8388608
#define OFF_X1      10485760
#define OFF_SWQ     12582912
#define OFF_SWK     14680064
#define OFF_SWV     16777216
#define OFF_SWATTN  18874368
#define OFF_X2      20971520
#define OFF_H       23068672
#define OFF_FF      31457280
#define SCRATCH_FLOATS 33554432

__device__ float g_scratch[SCRATCH_FLOATS];

// ---------------------------------------------------------------------------
// Shared PTX helpers
// ---------------------------------------------------------------------------
__device__ __forceinline__ void cp_async16(void* smem_ptr, const void* gmem_ptr) {
    unsigned saddr = (unsigned)__cvta_generic_to_shared(smem_ptr);
    asm volatile("cp.async.cg.shared.global [%0], [%1], 16;\n"
                 :: "r"(saddr), "l"(gmem_ptr));
}
__device__ __forceinline__ void cp_commit() {
    asm volatile("cp.async.commit_group;\n");
}
__device__ __forceinline__ void cp_wait0() {
    asm volatile("cp.async.wait_group 0;\n");
}
__device__ __forceinline__ void cp_wait1() {
    asm volatile("cp.async.wait_group 1;\n");
}
__device__ __forceinline__ void cp_wait2() {
    asm volatile("cp.async.wait_group 2;\n");
}
__device__ __forceinline__ void ldsm_x4(unsigned& r0, unsigned& r1, unsigned& r2, unsigned& r3,
                                        const float* p) {
    unsigned saddr = (unsigned)__cvta_generic_to_shared((void*)p);
    asm volatile("ldmatrix.sync.aligned.m8n8.x4.shared.b16 {%0,%1,%2,%3}, [%4];\n"
                 : "=r"(r0), "=r"(r1), "=r"(r2), "=r"(r3) : "r"(saddr));
}
__device__ __forceinline__ void mma_tf32(float& c0, float& c1, float& c2, float& c3,
                                         unsigned a0, unsigned a1, unsigned a2, unsigned a3,
                                         unsigned b0, unsigned b1) {
    asm volatile("mma.sync.aligned.m16n8k8.row.col.f32.tf32.tf32.f32 "
                 "{%0,%1,%2,%3}, {%4,%5,%6,%7}, {%8,%9}, {%0,%1,%2,%3};\n"
                 : "+f"(c0), "+f"(c1), "+f"(c2), "+f"(c3)
                 : "r"(a0), "r"(a1), "r"(a2), "r"(a3), "r"(b0), "r"(b1));
}

// ---------------------------------------------------------------------------
// TF32 tensor-core GEMM: C[M,N] = A[M,K] * W[N,K]^T + bias[N], optional ReLU.
// 128x128 block tile, BK=16, 4-stage cp.async pipeline, 256 threads.
// ---------------------------------------------------------------------------
#define BM 128
#define BN 128
#define BK 16
#define STR 20
#define NSTAGE 4

__global__ void __launch_bounds__(256) gemm_tf32_kernel(
    const float* __restrict__ A, const float* __restrict__ Wt,
    const float* __restrict__ bias, float* __restrict__ C,
    int M, int N, int K, int relu)
{
    __shared__ __align__(16) float As[NSTAGE][BM * STR];
    __shared__ __align__(16) float Bs[NSTAGE][BN * STR];

    const int tid  = threadIdx.x;
    const int wid  = tid >> 5;
    const int lane = tid & 31;
    const int wm   = (wid & 3) * 32;
    const int wn   = (wid >> 2) * 64;
    const int m0   = blockIdx.y * BM;
    const int n0   = blockIdx.x * BN;

    const int lrow = tid >> 2;
    const int lcol = (tid & 3) * 4;

    float acc[2][8][4];
#pragma unroll
    for (int i = 0; i < 2; ++i)
#pragma unroll
        for (int j = 0; j < 8; ++j)
#pragma unroll
            for (int q = 0; q < 4; ++q) acc[i][j][q] = 0.f;

    const int ntiles = K / BK;
    const float* Abase = A + (size_t)m0 * K;
    const float* Bbase = Wt + (size_t)n0 * K;

    // prologue: issue stages 0..2
#pragma unroll
    for (int s = 0; s < NSTAGE - 1; ++s) {
        int k0 = s * BK;
#pragma unroll
        for (int p = 0; p < 2; ++p) {
            int r = lrow + p * 64;
            cp_async16(&As[s][r * STR + lcol], Abase + (size_t)r * K + k0 + lcol);
            cp_async16(&Bs[s][r * STR + lcol], Bbase + (size_t)r * K + k0 + lcol);
        }
        cp_commit();
    }

    const int a_row = wm + (lane & 15);
    const int a_koff = (lane >> 4) * 4;
    const int b_row_base = wn + (lane & 7) + ((lane >> 4) * 8);
    const int b_koff = ((lane >> 3) & 1) * 4;

    for (int t = 0; t < ntiles; ++t) {
        cp_wait2();            // oldest pending group == tile t
        __syncthreads();       // also protects stage (t+3)%4 (read at iter t-1)

        int ps = t + NSTAGE - 1;
        if (ps < ntiles) {
            int sb = ps & (NSTAGE - 1);
            int k0 = ps * BK;
#pragma unroll
            for (int p = 0; p < 2; ++p) {
                int r = lrow + p * 64;
                cp_async16(&As[sb][r * STR + lcol], Abase + (size_t)r * K + k0 + lcol);
                cp_async16(&Bs[sb][r * STR + lcol], Bbase + (size_t)r * K + k0 + lcol);
            }
        }
        cp_commit();           // always commit (possibly empty group)

        const int buf = t & (NSTAGE - 1);
#pragma unroll
        for (int ks = 0; ks < 2; ++ks) {
            unsigned a[2][4];
            unsigned b[8][2];
#pragma unroll
            for (int im = 0; im < 2; ++im) {
                const float* p = &As[buf][(a_row + im * 16) * STR + ks * 8 + a_koff];
                ldsm_x4(a[im][0], a[im][1], a[im][2], a[im][3], p);
            }
#pragma unroll
            for (int it = 0; it < 4; ++it) {
                const float* p = &Bs[buf][(b_row_base + it * 16) * STR + ks * 8 + b_koff];
                unsigned r0, r1, r2, r3;
                ldsm_x4(r0, r1, r2, r3, p);
                b[it * 2][0] = r0; b[it * 2][1] = r1;
                b[it * 2 + 1][0] = r2; b[it * 2 + 1][1] = r3;
            }
#pragma unroll
            for (int im = 0; im < 2; ++im)
#pragma unroll
                for (int in = 0; in < 8; ++in)
                    mma_tf32(acc[im][in][0], acc[im][in][1], acc[im][in][2], acc[im][in][3],
                             a[im][0], a[im][1], a[im][2], a[im][3],
                             b[in][0], b[in][1]);
        }
    }

    const int row_base = m0 + wm + (lane >> 2);
    const int col_base = n0 + wn + (lane & 3) * 2;
#pragma unroll
    for (int im = 0; im < 2; ++im) {
#pragma unroll
        for (int in = 0; in < 8; ++in) {
            int col = col_base + in * 8;
            float b0 = bias[col], b1 = bias[col + 1];
            int r0 = row_base + im * 16;
            float v0 = acc[im][in][0] + b0;
            float v1 = acc[im][in][1] + b1;
            float v2 = acc[im][in][2] + b0;
            float v3 = acc[im][in][3] + b1;
            if (relu) {
                v0 = fmaxf(v0, 0.f); v1 = fmaxf(v1, 0.f);
                v2 = fmaxf(v2, 0.f); v3 = fmaxf(v3, 0.f);
            }
            C[(size_t)r0 * N + col] = v0;
            C[(size_t)r0 * N + col + 1] = v1;
            C[(size_t)(r0 + 8) * N + col] = v2;
            C[(size_t)(r0 + 8) * N + col + 1] = v3;
        }
    }
}

// ---------------------------------------------------------------------------
// TF32 flash self-attention (unchanged from R3).
// ---------------------------------------------------------------------------
#define ASTR 68
#define KBUF (64 * ASTR)
#define ROWF 6144

__global__ void __launch_bounds__(256) self_attn_mma_kernel(
    const float* __restrict__ qkv, float* __restrict__ out)
{
    extern __shared__ float sm[];
    float* Ps = sm;
    float* Ks = sm + 128 * ASTR;
    float* Vt = sm + 256 * ASTR;

    const int tid = threadIdx.x;
    const int wid = tid >> 5;
    const int lane = tid & 31;
    const int b = blockIdx.y >> 3;
    const int h = blockIdx.y & 7;
    const int t0 = blockIdx.x * 128;
    const int wm = wid * 16;

    const float* qbase = qkv + ((size_t)t0 * B_ + b) * 1536 + h * 64;
    const float* kroot = qkv + (size_t)b * 1536 + 512 + h * 64;
    const float* vroot = qkv + (size_t)b * 1536 + 1024 + h * 64;

    int vkey[4], vc[4];
#pragma unroll
    for (int i = 0; i < 4; ++i) {
        int fidx = i * 256 + tid;
        vkey[i] = fidx >> 4;
        vc[i] = (fidx & 15) * 4;
    }

#pragma unroll
    for (int i = 0; i < 8; ++i) {
        int fidx = i * 256 + tid;
        int r = fidx >> 4, c = (fidx & 15) * 4;
        cp_async16(&Ps[r * ASTR + c], qbase + (size_t)r * ROWF + c);
    }
#pragma unroll
    for (int i = 0; i < 4; ++i)
        cp_async16(&Ks[vkey[i] * ASTR + vc[i]], kroot + (size_t)vkey[i] * ROWF + vc[i]);
    cp_commit();

    float4 vreg[4];
#pragma unroll
    for (int i = 0; i < 4; ++i)
        vreg[i] = *reinterpret_cast<const float4*>(vroot + (size_t)vkey[i] * ROWF + vc[i]);

    cp_wait0();
    __syncthreads();

    unsigned qf[8][4];
    {
        const int a_row = wm + (lane & 15);
        const int a_koff = (lane >> 4) * 4;
#pragma unroll
        for (int ks = 0; ks < 8; ++ks) {
            unsigned r0, r1, r2, r3;
            ldsm_x4(r0, r1, r2, r3, &Ps[a_row * ASTR + ks * 8 + a_koff]);
            qf[ks][0] = __float_as_uint(__uint_as_float(r0) * SCALE_);
            qf[ks][1] = __float_as_uint(__uint_as_float(r1) * SCALE_);
            qf[ks][2] = __float_as_uint(__uint_as_float(r2) * SCALE_);
            qf[ks][3] = __float_as_uint(__uint_as_float(r3) * SCALE_);
        }
    }

#pragma unroll
    for (int i = 0; i < 4; ++i) {
        float v[4] = {vreg[i].x, vreg[i].y, vreg[i].z, vreg[i].w};
#pragma unroll
        for (int j = 0; j < 4; ++j) {
            int hd = vc[i] + j;
            Vt[hd * ASTR + (vkey[i] ^ (4 * ((hd >> 5) & 1)))] = v[j];
        }
    }

    float o[8][4];
#pragma unroll
    for (int n = 0; n < 8; ++n)
#pragma unroll
        for (int c = 0; c < 4; ++c) o[n][c] = 0.f;
    float m0 = -1e30f, m1 = -1e30f, l0 = 0.f, l1 = 0.f;

    const int brow_base = (lane & 7) + ((lane >> 4) * 8);
    const int bko = ((lane >> 3) & 1) * 4;
    const int prow0 = wm + (lane >> 2);
    const int pcol = 2 * (lane & 3);
    const int a_row = wm + (lane & 15);
    const int a_koff = (lane >> 4) * 4;

    for (int kt = 0; kt < 16; ++kt) {
        const int buf = kt & 1;
        __syncthreads();

        if (kt + 1 < 16) {
            const float* kb = kroot + (size_t)(kt + 1) * 64 * ROWF;
            float* kd = Ks + (buf ^ 1) * KBUF;
#pragma unroll
            for (int i = 0; i < 4; ++i)
                cp_async16(&kd[vkey[i] * ASTR + vc[i]], kb + (size_t)vkey[i] * ROWF + vc[i]);
            cp_commit();
            const float* vb = vroot + (size_t)(kt + 1) * 64 * ROWF;
#pragma unroll
            for (int i = 0; i < 4; ++i)
                vreg[i] = *reinterpret_cast<const float4*>(vb + (size_t)vkey[i] * ROWF + vc[i]);
            cp_wait1();
        } else {
            cp_wait0();
        }
        __syncthreads();

        const float* Kb = Ks + buf * KBUF;
        float s[8][4];
#pragma unroll
        for (int n = 0; n < 8; ++n)
#pragma unroll
            for (int c = 0; c < 4; ++c) s[n][c] = 0.f;
#pragma unroll
        for (int ks = 0; ks < 8; ++ks) {
#pragma unroll
            for (int ng = 0; ng < 4; ++ng) {
                unsigned r0, r1, r2, r3;
                ldsm_x4(r0, r1, r2, r3, &Kb[(brow_base + ng * 16) * ASTR + ks * 8 + bko]);
                mma_tf32(s[ng * 2][0], s[ng * 2][1], s[ng * 2][2], s[ng * 2][3],
                         qf[ks][0], qf[ks][1], qf[ks][2], qf[ks][3], r0, r1);
                mma_tf32(s[ng * 2 + 1][0], s[ng * 2 + 1][1], s[ng * 2 + 1][2], s[ng * 2 + 1][3],
                         qf[ks][0], qf[ks][1], qf[ks][2], qf[ks][3], r2, r3);
            }
        }

        float mx0 = -1e30f, mx1 = -1e30f;
#pragma unroll
        for (int n = 0; n < 8; ++n) {
            mx0 = fmaxf(mx0, fmaxf(s[n][0], s[n][1]));
            mx1 = fmaxf(mx1, fmaxf(s[n][2], s[n][3]));
        }
        mx0 = fmaxf(mx0, __shfl_xor_sync(0xffffffffu, mx0, 1));
        mx0 = fmaxf(mx0, __shfl_xor_sync(0xffffffffu, mx0, 2));
        mx1 = fmaxf(mx1, __shfl_xor_sync(0xffffffffu, mx1, 1));
        mx1 = fmaxf(mx1, __shfl_xor_sync(0xffffffffu, mx1, 2));

        float mn0 = fmaxf(m0, mx0), mn1 = fmaxf(m1, mx1);
        float corr0 = __expf(m0 - mn0), corr1 = __expf(m1 - mn1);
        m0 = mn0; m1 = mn1;
        l0 *= corr0; l1 *= corr1;
#pragma unroll
        for (int n = 0; n < 8; ++n) {
            o[n][0] *= corr0; o[n][1] *= corr0;
            o[n][2] *= corr1; o[n][3] *= corr1;
        }
#pragma unroll
        for (int n = 0; n < 8; ++n) {
            float p0 = __expf(s[n][0] - mn0);
            float p1 = __expf(s[n][1] - mn0);
            float p2 = __expf(s[n][2] - mn1);
            float p3 = __expf(s[n][3] - mn1);
            l0 += p0 + p1; l1 += p2 + p3;
            *reinterpret_cast<float2*>(&Ps[prow0 * ASTR + n * 8 + pcol]) = make_float2(p0, p1);
            *reinterpret_cast<float2*>(&Ps[(prow0 + 8) * ASTR + n * 8 + pcol]) = make_float2(p2, p3);
        }
        __syncwarp();

        const float* Vb = Vt + buf * KBUF;
#pragma unroll
        for (int ks = 0; ks < 8; ++ks) {
            unsigned a0, a1, a2, a3;
            ldsm_x4(a0, a1, a2, a3, &Ps[a_row * ASTR + ks * 8 + a_koff]);
#pragma unroll
            for (int ng = 0; ng < 4; ++ng) {
                int br = brow_base + ng * 16;
                unsigned r0, r1, r2, r3;
                ldsm_x4(r0, r1, r2, r3,
                        &Vb[br * ASTR + ((ks * 8 + bko) ^ (4 * ((br >> 5) & 1)))]);
                mma_tf32(o[ng * 2][0], o[ng * 2][1], o[ng * 2][2], o[ng * 2][3],
                         a0, a1, a2, a3, r0, r1);
                mma_tf32(o[ng * 2 + 1][0], o[ng * 2 + 1][1], o[ng * 2 + 1][2], o[ng * 2 + 1][3],
                         a0, a1, a2, a3, r2, r3);
            }
        }

        if (kt + 1 < 16) {
            float* Vd = Vt + (buf ^ 1) * KBUF;
#pragma unroll
            for (int i = 0; i < 4; ++i) {
                float v[4] = {vreg[i].x, vreg[i].y, vreg[i].z, vreg[i].w};
#pragma unroll
                for (int j = 0; j < 4; ++j) {
                    int hd = vc[i] + j;
                    Vd[hd * ASTR + (vkey[i] ^ (4 * ((hd >> 5) & 1)))] = v[j];
                }
            }
        }
    }

    l0 += __shfl_xor_sync(0xffffffffu, l0, 1);
    l0 += __shfl_xor_sync(0xffffffffu, l0, 2);
    l1 += __shfl_xor_sync(0xffffffffu, l1, 1);
    l1 += __shfl_xor_sync(0xffffffffu, l1, 2);
    float inv0 = 1.f / l0, inv1 = 1.f / l1;

    float* ob0 = out + ((size_t)(t0 + prow0) * B_ + b) * D_ + h * 64 + pcol;
    float* ob1 = out + ((size_t)(t0 + prow0 + 8) * B_ + b) * D_ + h * 64 + pcol;
#pragma unroll
    for (int n = 0; n < 8; ++n) {
        *reinterpret_cast<float2*>(ob0 + n * 8) = make_float2(o[n][0] * inv0, o[n][1] * inv0);
        *reinterpret_cast<float2*>(ob1 + n * 8) = make_float2(o[n][2] * inv1, o[n][3] * inv1);
    }
}

#define ATTN_SMEM (384 * ASTR * 4)

// ---------------------------------------------------------------------------
// Sliding-window cross-attention.
// ---------------------------------------------------------------------------
__global__ void __launch_bounds__(256) sw_attn_kernel(
    const float* __restrict__ q, const float* __restrict__ k,
    const float* __restrict__ v, float* __restrict__ out)
{
    const int gw = (blockIdx.x * blockDim.x + threadIdx.x) >> 5;
    const int lane = threadIdx.x & 31;
    if (gw >= T_ * B_ * H_) return;
    const int h = gw & 7;
    const int b = (gw >> 3) & 3;
    const int t = gw >> 5;

    const float2 q2 = reinterpret_cast<const float2*>(
        q + ((size_t)t * B_ + b) * D_ + h * HD_)[lane];

    float sc[33];
#pragma unroll
    for (int jj = 0; jj < 33; ++jj) {
        int j = t - W_ + jj;
        float s = -1e30f;
        if (j >= 0 && j < S_) {
            const float2 k2 = reinterpret_cast<const float2*>(
                k + ((size_t)j * B_ + b) * D_ + h * HD_)[lane];
            float p = q2.x * k2.x + q2.y * k2.y;
#pragma unroll
            for (int o = 16; o > 0; o >>= 1)
                p += __shfl_xor_sync(0xffffffffu, p, o);
            s = p * SCALE_;
        }
        sc[jj] = s;
    }

    float m = -1e30f;
#pragma unroll
    for (int jj = 0; jj < 33; ++jj) m = fmaxf(m, sc[jj]);

    float l = 0.f, a0 = 0.f, a1 = 0.f;
#pragma unroll
    for (int jj = 0; jj < 33; ++jj) {
        int j = t - W_ + jj;
        if (j >= 0 && j < S_) {
            float p = __expf(sc[jj] - m);
            l += p;
            const float2 v2 = reinterpret_cast<const float2*>(
                v + ((size_t)j * B_ + b) * D_ + h * HD_)[lane];
            a0 += p * v2.x;
            a1 += p * v2.y;
        }
    }
    float inv = 1.f / l;
    float* op = out + ((size_t)t * B_ + b) * D_ + h * HD_;
    op[lane * 2] = a0 * inv;
    op[lane * 2 + 1] = a1 * inv;
}

// ---------------------------------------------------------------------------
// Fused residual-add + LayerNorm over D=512.
// ---------------------------------------------------------------------------
__global__ void __launch_bounds__(256) add_ln_kernel(
    const float* __restrict__ x, const float* __restrict__ y,
    const float* __restrict__ g, const float* __restrict__ beta,
    float* __restrict__ out)
{
    __shared__ float sh[33];
    const int row = blockIdx.x;
    const int tid = threadIdx.x;
    const size_t base = (size_t)row * D_;

    float v0 = x[base + tid] + y[base + tid];
    float v1 = x[base + tid + 256] + y[base + tid + 256];

    float s = v0 + v1;
#pragma unroll
    for (int o = 16; o > 0; o >>= 1) s += __shfl_xor_sync(0xffffffffu, s, o);
    int lane = tid & 31, wid = tid >> 5;
    if (lane == 0) sh[wid] = s;
    __syncthreads();
    if (wid == 0) {
        float t = (lane < 8) ? sh[lane] : 0.f;
#pragma unroll
        for (int o = 4; o > 0; o >>= 1) t += __shfl_xor_sync(0xffffffffu, t, o);
        if (lane == 0) sh[32] = t;
    }
    __syncthreads();
    float mean = sh[32] * (1.f / D_);
    __syncthreads();

    float d0 = v0 - mean, d1 = v1 - mean;
    float sq = d0 * d0 + d1 * d1;
#pragma unroll
    for (int o = 16; o > 0; o >>= 1) sq += __shfl_xor_sync(0xffffffffu, sq, o);
    if (lane == 0) sh[wid] = sq;
    __syncthreads();
    if (wid == 0) {
        float t = (lane < 8) ? sh[lane] : 0.f;
#pragma unroll
        for (int o = 4; o > 0; o >>= 1) t += __shfl_xor_sync(0xffffffffu, t, o);
        if (lane == 0) sh[32] = t;
    }
    __syncthreads();
    float rstd = rsqrtf(sh[32] * (1.f / D_) + EPS_);

    out[base + tid] = d0 * rstd * g[tid] + beta[tid];
    out[base + tid + 256] = d1 * rstd * g[tid + 256] + beta[tid + 256];
}

// ---------------------------------------------------------------------------
// Launch
// ---------------------------------------------------------------------------
extern "C" void kernel_launch(void* const* d_in, const int* in_sizes, int n_in,
                              void* d_out, int out_size)
{
    (void)in_sizes; (void)n_in; (void)out_size;
    const float* tgt        = (const float*)d_in[0];
    const float* memory     = (const float*)d_in[1];
    const float* in_proj_w  = (const float*)d_in[2];
    const float* in_proj_b  = (const float*)d_in[3];
    const float* out_proj_w = (const float*)d_in[4];
    const float* out_proj_b = (const float*)d_in[5];
    const float* sw_q_w = (const float*)d_in[6];
    const float* sw_q_b = (const float*)d_in[7];
    const float* sw_k_w = (const float*)d_in[8];
    const float* sw_k_b = (const float*)d_in[9];
    const float* sw_v_w = (const float*)d_in[10];
    const float* sw_v_b = (const float*)d_in[11];
    const float* sw_o_w = (const float*)d_in[12];
    const float* sw_o_b = (const float*)d_in[13];
    const float* lin1_w = (const float*)d_in[14];
    const float* lin1_b = (const float*)d_in[15];
    const float* lin2_w = (const float*)d_in[16];
    const float* lin2_b = (const float*)d_in[17];
    const float* n1_g = (const float*)d_in[18];
    const float* n1_b = (const float*)d_in[19];
    const float* n2_g = (const float*)d_in[20];
    const float* n2_b = (const float*)d_in[21];
    const float* n3_g = (const float*)d_in[22];
    const float* n3_b = (const float*)d_in[23];
    float* out = (float*)d_out;

    float* s = nullptr;
    cudaGetSymbolAddress((void**)&s, g_scratch);
    float* qkv    = s + OFF_QKV;
    float* attn   = s + OFF_ATTN;
    float* proj   = s + OFF_PROJ;
    float* x1     = s + OFF_X1;
    float* swq    = s + OFF_SWQ;
    float* swk    = s + OFF_SWK;
    float* swv    = s + OFF_SWV;
    float* swattn = s + OFF_SWATTN;
    float* x2     = s + OFF_X2;
    float* hbuf   = s + OFF_H;
    float* ffbuf  = s + OFF_FF;

    cudaFuncSetAttribute(self_attn_mma_kernel,
                         cudaFuncAttributeMaxDynamicSharedMemorySize, ATTN_SMEM);

    // independent GEMMs on memory first (no dependency on attention chain)
    gemm_tf32_kernel<<<dim3(4, 32), 256>>>(memory, sw_k_w, sw_k_b, swk, NROWS, D_, D_, 0);
    gemm_tf32_kernel<<<dim3(4, 32), 256>>>(memory, sw_v_w, sw_v_b, swv, NROWS, D_, D_, 0);
    // 1. QKV projection
    gemm_tf32_kernel<<<dim3(12, 32), 256>>>(tgt, in_proj_w, in_proj_b, qkv,
                                            NROWS, 3 * D_, D_, 0);
    // 2. self attention (TF32 MMA flash)
    self_attn_mma_kernel<<<dim3(8, 32), 256, ATTN_SMEM>>>(qkv, attn);
    // 3. out projection
    gemm_tf32_kernel<<<dim3(4, 32), 256>>>(attn, out_proj_w, out_proj_b, proj,
                                           NROWS, D_, D_, 0);
    // 4. add + LN1
    add_ln_kernel<<<NROWS, 256>>>(tgt, proj, n1_g, n1_b, x1);
    // 5. sliding-window q projection
    gemm_tf32_kernel<<<dim3(4, 32), 256>>>(x1, sw_q_w, sw_q_b, swq, NROWS, D_, D_, 0);
    // 8. banded attention
    sw_attn_kernel<<<4096, 256>>>(swq, swk, swv, swattn);
    // 9. sw out projection
    gemm_tf32_kernel<<<dim3(4, 32), 256>>>(swattn, sw_o_w, sw_o_b, proj, NROWS, D_, D_, 0);
    // 10. add + LN2
    add_ln_kernel<<<NROWS, 256>>>(x1, proj, n2_g, n2_b, x2);
    // 11. FFN up + ReLU
    gemm_tf32_kernel<<<dim3(16, 32), 256>>>(x2, lin1_w, lin1_b, hbuf, NROWS, DFF_, D_, 1);
    // 12. FFN down
    gemm_tf32_kernel<<<dim3(4, 32), 256>>>(hbuf, lin2_w, lin2_b, ffbuf, NROWS, D_, DFF_, 0);
    // 13. add + LN3 -> output
    add_ln_kernel<<<NROWS, 256>>>(x2, ffbuf, n3_g, n3_b, out);
}

// round 5
// speedup vs baseline: 3.1612x; 1.0715x over previous
#include <cuda_runtime.h>
#include <cuda_bf16.h>
#include <math.h>

#define T_ 1024
#define S_ 1024
#define B_ 4
#define D_ 512
#define H_ 8
#define HD_ 64
#define DFF_ 2048
#define W_ 16
#define NROWS (T_ * B_)
#define SCALE_ 0.125f
#define EPS_ 1e-5f

#define OFF_QKV     0
#define OFF_ATTN    6291456
#define OFF_PROJ    8388608
#define OFF_X1      10485760
#define OFF_SWQ     12582912
#define OFF_SWK     14680064
#define OFF_SWV     16777216
#define OFF_SWATTN  18874368
#define OFF_X2      20971520
#define OFF_H       23068672
#define OFF_FF      31457280
#define SCRATCH_FLOATS 33554432

__device__ float g_scratch[SCRATCH_FLOATS];

// ---------------------------------------------------------------------------
// PTX helpers
// ---------------------------------------------------------------------------
__device__ __forceinline__ void cp_async16(void* smem_ptr, const void* gmem_ptr) {
    unsigned saddr = (unsigned)__cvta_generic_to_shared(smem_ptr);
    asm volatile("cp.async.cg.shared.global [%0], [%1], 16;\n"
                 :: "r"(saddr), "l"(gmem_ptr));
}
__device__ __forceinline__ void cp_commit() {
    asm volatile("cp.async.commit_group;\n");
}
__device__ __forceinline__ void cp_wait0() {
    asm volatile("cp.async.wait_group 0;\n");
}
__device__ __forceinline__ void cp_wait1() {
    asm volatile("cp.async.wait_group 1;\n");
}
__device__ __forceinline__ void cp_wait2() {
    asm volatile("cp.async.wait_group 2;\n");
}
__device__ __forceinline__ void ldsm_x4(unsigned& r0, unsigned& r1, unsigned& r2, unsigned& r3,
                                        const float* p) {
    unsigned saddr = (unsigned)__cvta_generic_to_shared((void*)p);
    asm volatile("ldmatrix.sync.aligned.m8n8.x4.shared.b16 {%0,%1,%2,%3}, [%4];\n"
                 : "=r"(r0), "=r"(r1), "=r"(r2), "=r"(r3) : "r"(saddr));
}
__device__ __forceinline__ void mma_tf32(float& c0, float& c1, float& c2, float& c3,
                                         unsigned a0, unsigned a1, unsigned a2, unsigned a3,
                                         unsigned b0, unsigned b1) {
    asm volatile("mma.sync.aligned.m16n8k8.row.col.f32.tf32.tf32.f32 "
                 "{%0,%1,%2,%3}, {%4,%5,%6,%7}, {%8,%9}, {%0,%1,%2,%3};\n"
                 : "+f"(c0), "+f"(c1), "+f"(c2), "+f"(c3)
                 : "r"(a0), "r"(a1), "r"(a2), "r"(a3), "r"(b0), "r"(b1));
}

#define BK 16
#define STR 20
#define NSTAGE 4

// ---------------------------------------------------------------------------
// GEMM 128x128 (qkv, ffn-up). 4-stage cp.async, 2 CTAs/SM target.
// ---------------------------------------------------------------------------
__global__ void __launch_bounds__(256, 2) gemm_tf32_kernel(
    const float* __restrict__ A, const float* __restrict__ Wt,
    const float* __restrict__ bias, float* __restrict__ C,
    int M, int N, int K, int relu)
{
    __shared__ __align__(16) float As[NSTAGE][128 * STR];
    __shared__ __align__(16) float Bs[NSTAGE][128 * STR];

    const int tid  = threadIdx.x;
    const int wid  = tid >> 5;
    const int lane = tid & 31;
    const int wm   = (wid & 3) * 32;
    const int wn   = (wid >> 2) * 64;
    const int m0   = blockIdx.y * 128;
    const int n0   = blockIdx.x * 128;

    const int lrow = tid >> 2;
    const int lcol = (tid & 3) * 4;

    float acc[2][8][4];
#pragma unroll
    for (int i = 0; i < 2; ++i)
#pragma unroll
        for (int j = 0; j < 8; ++j)
#pragma unroll
            for (int q = 0; q < 4; ++q) acc[i][j][q] = 0.f;

    const int ntiles = K / BK;
    const float* Abase = A + (size_t)m0 * K;
    const float* Bbase = Wt + (size_t)n0 * K;

#pragma unroll
    for (int s = 0; s < NSTAGE - 1; ++s) {
        int k0 = s * BK;
#pragma unroll
        for (int p = 0; p < 2; ++p) {
            int r = lrow + p * 64;
            cp_async16(&As[s][r * STR + lcol], Abase + (size_t)r * K + k0 + lcol);
            cp_async16(&Bs[s][r * STR + lcol], Bbase + (size_t)r * K + k0 + lcol);
        }
        cp_commit();
    }

    const int a_row = wm + (lane & 15);
    const int a_koff = (lane >> 4) * 4;
    const int b_row_base = wn + (lane & 7) + ((lane >> 4) * 8);
    const int b_koff = ((lane >> 3) & 1) * 4;

    for (int t = 0; t < ntiles; ++t) {
        cp_wait2();
        __syncthreads();

        int ps = t + NSTAGE - 1;
        if (ps < ntiles) {
            int sb = ps & (NSTAGE - 1);
            int k0 = ps * BK;
#pragma unroll
            for (int p = 0; p < 2; ++p) {
                int r = lrow + p * 64;
                cp_async16(&As[sb][r * STR + lcol], Abase + (size_t)r * K + k0 + lcol);
                cp_async16(&Bs[sb][r * STR + lcol], Bbase + (size_t)r * K + k0 + lcol);
            }
        }
        cp_commit();

        const int buf = t & (NSTAGE - 1);
#pragma unroll
        for (int ks = 0; ks < 2; ++ks) {
            unsigned a[2][4];
            unsigned b[8][2];
#pragma unroll
            for (int im = 0; im < 2; ++im) {
                const float* p = &As[buf][(a_row + im * 16) * STR + ks * 8 + a_koff];
                ldsm_x4(a[im][0], a[im][1], a[im][2], a[im][3], p);
            }
#pragma unroll
            for (int it = 0; it < 4; ++it) {
                const float* p = &Bs[buf][(b_row_base + it * 16) * STR + ks * 8 + b_koff];
                unsigned r0, r1, r2, r3;
                ldsm_x4(r0, r1, r2, r3, p);
                b[it * 2][0] = r0; b[it * 2][1] = r1;
                b[it * 2 + 1][0] = r2; b[it * 2 + 1][1] = r3;
            }
#pragma unroll
            for (int im = 0; im < 2; ++im)
#pragma unroll
                for (int in = 0; in < 8; ++in)
                    mma_tf32(acc[im][in][0], acc[im][in][1], acc[im][in][2], acc[im][in][3],
                             a[im][0], a[im][1], a[im][2], a[im][3],
                             b[in][0], b[in][1]);
        }
    }

    const int row_base = m0 + wm + (lane >> 2);
    const int col_base = n0 + wn + (lane & 3) * 2;
#pragma unroll
    for (int im = 0; im < 2; ++im) {
#pragma unroll
        for (int in = 0; in < 8; ++in) {
            int col = col_base + in * 8;
            float b0 = bias[col], b1 = bias[col + 1];
            int r0 = row_base + im * 16;
            float v0 = acc[im][in][0] + b0;
            float v1 = acc[im][in][1] + b1;
            float v2 = acc[im][in][2] + b0;
            float v3 = acc[im][in][3] + b1;
            if (relu) {
                v0 = fmaxf(v0, 0.f); v1 = fmaxf(v1, 0.f);
                v2 = fmaxf(v2, 0.f); v3 = fmaxf(v3, 0.f);
            }
            C[(size_t)r0 * N + col] = v0;
            C[(size_t)r0 * N + col + 1] = v1;
            C[(size_t)(r0 + 8) * N + col] = v2;
            C[(size_t)(r0 + 8) * N + col + 1] = v3;
        }
    }
}

// ---------------------------------------------------------------------------
// GEMM 128x64 (all N=512 GEMMs): more CTAs, 2 CTAs/SM, warp tile 32x32.
// ---------------------------------------------------------------------------
__global__ void __launch_bounds__(256, 2) gemm_tf32_n64_kernel(
    const float* __restrict__ A, const float* __restrict__ Wt,
    const float* __restrict__ bias, float* __restrict__ C,
    int M, int N, int K, int relu)
{
    __shared__ __align__(16) float As[NSTAGE][128 * STR];
    __shared__ __align__(16) float Bs[NSTAGE][64 * STR];

    const int tid  = threadIdx.x;
    const int wid  = tid >> 5;
    const int lane = tid & 31;
    const int wm   = (wid & 3) * 32;
    const int wn   = (wid >> 2) * 32;
    const int m0   = blockIdx.y * 128;
    const int n0   = blockIdx.x * 64;

    const int lrow = tid >> 2;
    const int lcol = (tid & 3) * 4;

    float acc[2][4][4];
#pragma unroll
    for (int i = 0; i < 2; ++i)
#pragma unroll
        for (int j = 0; j < 4; ++j)
#pragma unroll
            for (int q = 0; q < 4; ++q) acc[i][j][q] = 0.f;

    const int ntiles = K / BK;
    const float* Abase = A + (size_t)m0 * K;
    const float* Bbase = Wt + (size_t)n0 * K;

#pragma unroll
    for (int s = 0; s < NSTAGE - 1; ++s) {
        int k0 = s * BK;
#pragma unroll
        for (int p = 0; p < 2; ++p) {
            int r = lrow + p * 64;
            cp_async16(&As[s][r * STR + lcol], Abase + (size_t)r * K + k0 + lcol);
        }
        cp_async16(&Bs[s][lrow * STR + lcol], Bbase + (size_t)lrow * K + k0 + lcol);
        cp_commit();
    }

    const int a_row = wm + (lane & 15);
    const int a_koff = (lane >> 4) * 4;
    const int b_row_base = wn + (lane & 7) + ((lane >> 4) * 8);
    const int b_koff = ((lane >> 3) & 1) * 4;

    for (int t = 0; t < ntiles; ++t) {
        cp_wait2();
        __syncthreads();

        int ps = t + NSTAGE - 1;
        if (ps < ntiles) {
            int sb = ps & (NSTAGE - 1);
            int k0 = ps * BK;
#pragma unroll
            for (int p = 0; p < 2; ++p) {
                int r = lrow + p * 64;
                cp_async16(&As[sb][r * STR + lcol], Abase + (size_t)r * K + k0 + lcol);
            }
            cp_async16(&Bs[sb][lrow * STR + lcol], Bbase + (size_t)lrow * K + k0 + lcol);
        }
        cp_commit();

        const int buf = t & (NSTAGE - 1);
#pragma unroll
        for (int ks = 0; ks < 2; ++ks) {
            unsigned a[2][4];
            unsigned b[4][2];
#pragma unroll
            for (int im = 0; im < 2; ++im) {
                const float* p = &As[buf][(a_row + im * 16) * STR + ks * 8 + a_koff];
                ldsm_x4(a[im][0], a[im][1], a[im][2], a[im][3], p);
            }
#pragma unroll
            for (int it = 0; it < 2; ++it) {
                const float* p = &Bs[buf][(b_row_base + it * 16) * STR + ks * 8 + b_koff];
                unsigned r0, r1, r2, r3;
                ldsm_x4(r0, r1, r2, r3, p);
                b[it * 2][0] = r0; b[it * 2][1] = r1;
                b[it * 2 + 1][0] = r2; b[it * 2 + 1][1] = r3;
            }
#pragma unroll
            for (int im = 0; im < 2; ++im)
#pragma unroll
                for (int in = 0; in < 4; ++in)
                    mma_tf32(acc[im][in][0], acc[im][in][1], acc[im][in][2], acc[im][in][3],
                             a[im][0], a[im][1], a[im][2], a[im][3],
                             b[in][0], b[in][1]);
        }
    }

    const int row_base = m0 + wm + (lane >> 2);
    const int col_base = n0 + wn + (lane & 3) * 2;
#pragma unroll
    for (int im = 0; im < 2; ++im) {
#pragma unroll
        for (int in = 0; in < 4; ++in) {
            int col = col_base + in * 8;
            float b0 = bias[col], b1 = bias[col + 1];
            int r0 = row_base + im * 16;
            float v0 = acc[im][in][0] + b0;
            float v1 = acc[im][in][1] + b1;
            float v2 = acc[im][in][2] + b0;
            float v3 = acc[im][in][3] + b1;
            if (relu) {
                v0 = fmaxf(v0, 0.f); v1 = fmaxf(v1, 0.f);
                v2 = fmaxf(v2, 0.f); v3 = fmaxf(v3, 0.f);
            }
            C[(size_t)r0 * N + col] = v0;
            C[(size_t)r0 * N + col + 1] = v1;
            C[(size_t)(r0 + 8) * N + col] = v2;
            C[(size_t)(r0 + 8) * N + col + 1] = v3;
        }
    }
}

// ---------------------------------------------------------------------------
// TF32 flash self-attention, now 2 CTAs/SM.
// ---------------------------------------------------------------------------
#define ASTR 68
#define KBUF (64 * ASTR)
#define ROWF 6144

__global__ void __launch_bounds__(256, 2) self_attn_mma_kernel(
    const float* __restrict__ qkv, float* __restrict__ out)
{
    extern __shared__ float sm[];
    float* Ps = sm;
    float* Ks = sm + 128 * ASTR;
    float* Vt = sm + 256 * ASTR;

    const int tid = threadIdx.x;
    const int wid = tid >> 5;
    const int lane = tid & 31;
    const int b = blockIdx.y >> 3;
    const int h = blockIdx.y & 7;
    const int t0 = blockIdx.x * 128;
    const int wm = wid * 16;

    const float* qbase = qkv + ((size_t)t0 * B_ + b) * 1536 + h * 64;
    const float* kroot = qkv + (size_t)b * 1536 + 512 + h * 64;
    const float* vroot = qkv + (size_t)b * 1536 + 1024 + h * 64;

    int vkey[4], vc[4];
#pragma unroll
    for (int i = 0; i < 4; ++i) {
        int fidx = i * 256 + tid;
        vkey[i] = fidx >> 4;
        vc[i] = (fidx & 15) * 4;
    }

#pragma unroll
    for (int i = 0; i < 8; ++i) {
        int fidx = i * 256 + tid;
        int r = fidx >> 4, c = (fidx & 15) * 4;
        cp_async16(&Ps[r * ASTR + c], qbase + (size_t)r * ROWF + c);
    }
#pragma unroll
    for (int i = 0; i < 4; ++i)
        cp_async16(&Ks[vkey[i] * ASTR + vc[i]], kroot + (size_t)vkey[i] * ROWF + vc[i]);
    cp_commit();

    float4 vreg[4];
#pragma unroll
    for (int i = 0; i < 4; ++i)
        vreg[i] = *reinterpret_cast<const float4*>(vroot + (size_t)vkey[i] * ROWF + vc[i]);

    cp_wait0();
    __syncthreads();

    unsigned qf[8][4];
    {
        const int a_row = wm + (lane & 15);
        const int a_koff = (lane >> 4) * 4;
#pragma unroll
        for (int ks = 0; ks < 8; ++ks) {
            unsigned r0, r1, r2, r3;
            ldsm_x4(r0, r1, r2, r3, &Ps[a_row * ASTR + ks * 8 + a_koff]);
            qf[ks][0] = __float_as_uint(__uint_as_float(r0) * SCALE_);
            qf[ks][1] = __float_as_uint(__uint_as_float(r1) * SCALE_);
            qf[ks][2] = __float_as_uint(__uint_as_float(r2) * SCALE_);
            qf[ks][3] = __float_as_uint(__uint_as_float(r3) * SCALE_);
        }
    }

#pragma unroll
    for (int i = 0; i < 4; ++i) {
        float v[4] = {vreg[i].x, vreg[i].y, vreg[i].z, vreg[i].w};
#pragma unroll
        for (int j = 0; j < 4; ++j) {
            int hd = vc[i] + j;
            Vt[hd * ASTR + (vkey[i] ^ (4 * ((hd >> 5) & 1)))] = v[j];
        }
    }

    float o[8][4];
#pragma unroll
    for (int n = 0; n < 8; ++n)
#pragma unroll
        for (int c = 0; c < 4; ++c) o[n][c] = 0.f;
    float m0 = -1e30f, m1 = -1e30f, l0 = 0.f, l1 = 0.f;

    const int brow_base = (lane & 7) + ((lane >> 4) * 8);
    const int bko = ((lane >> 3) & 1) * 4;
    const int prow0 = wm + (lane >> 2);
    const int pcol = 2 * (lane & 3);
    const int a_row = wm + (lane & 15);
    const int a_koff = (lane >> 4) * 4;

    for (int kt = 0; kt < 16; ++kt) {
        const int buf = kt & 1;
        __syncthreads();

        if (kt + 1 < 16) {
            const float* kb = kroot + (size_t)(kt + 1) * 64 * ROWF;
            float* kd = Ks + (buf ^ 1) * KBUF;
#pragma unroll
            for (int i = 0; i < 4; ++i)
                cp_async16(&kd[vkey[i] * ASTR + vc[i]], kb + (size_t)vkey[i] * ROWF + vc[i]);
            cp_commit();
            const float* vb = vroot + (size_t)(kt + 1) * 64 * ROWF;
#pragma unroll
            for (int i = 0; i < 4; ++i)
                vreg[i] = *reinterpret_cast<const float4*>(vb + (size_t)vkey[i] * ROWF + vc[i]);
            cp_wait1();
        } else {
            cp_wait0();
        }
        __syncthreads();

        const float* Kb = Ks + buf * KBUF;
        float s[8][4];
#pragma unroll
        for (int n = 0; n < 8; ++n)
#pragma unroll
            for (int c = 0; c < 4; ++c) s[n][c] = 0.f;
#pragma unroll
        for (int ks = 0; ks < 8; ++ks) {
#pragma unroll
            for (int ng = 0; ng < 4; ++ng) {
                unsigned r0, r1, r2, r3;
                ldsm_x4(r0, r1, r2, r3, &Kb[(brow_base + ng * 16) * ASTR + ks * 8 + bko]);
                mma_tf32(s[ng * 2][0], s[ng * 2][1], s[ng * 2][2], s[ng * 2][3],
                         qf[ks][0], qf[ks][1], qf[ks][2], qf[ks][3], r0, r1);
                mma_tf32(s[ng * 2 + 1][0], s[ng * 2 + 1][1], s[ng * 2 + 1][2], s[ng * 2 + 1][3],
                         qf[ks][0], qf[ks][1], qf[ks][2], qf[ks][3], r2, r3);
            }
        }

        float mx0 = -1e30f, mx1 = -1e30f;
#pragma unroll
        for (int n = 0; n < 8; ++n) {
            mx0 = fmaxf(mx0, fmaxf(s[n][0], s[n][1]));
            mx1 = fmaxf(mx1, fmaxf(s[n][2], s[n][3]));
        }
        mx0 = fmaxf(mx0, __shfl_xor_sync(0xffffffffu, mx0, 1));
        mx0 = fmaxf(mx0, __shfl_xor_sync(0xffffffffu, mx0, 2));
        mx1 = fmaxf(mx1, __shfl_xor_sync(0xffffffffu, mx1, 1));
        mx1 = fmaxf(mx1, __shfl_xor_sync(0xffffffffu, mx1, 2));

        float mn0 = fmaxf(m0, mx0), mn1 = fmaxf(m1, mx1);
        float corr0 = __expf(m0 - mn0), corr1 = __expf(m1 - mn1);
        m0 = mn0; m1 = mn1;
        l0 *= corr0; l1 *= corr1;
#pragma unroll
        for (int n = 0; n < 8; ++n) {
            o[n][0] *= corr0; o[n][1] *= corr0;
            o[n][2] *= corr1; o[n][3] *= corr1;
        }
#pragma unroll
        for (int n = 0; n < 8; ++n) {
            float p0 = __expf(s[n][0] - mn0);
            float p1 = __expf(s[n][1] - mn0);
            float p2 = __expf(s[n][2] - mn1);
            float p3 = __expf(s[n][3] - mn1);
            l0 += p0 + p1; l1 += p2 + p3;
            *reinterpret_cast<float2*>(&Ps[prow0 * ASTR + n * 8 + pcol]) = make_float2(p0, p1);
            *reinterpret_cast<float2*>(&Ps[(prow0 + 8) * ASTR + n * 8 + pcol]) = make_float2(p2, p3);
        }
        __syncwarp();

        const float* Vb = Vt + buf * KBUF;
#pragma unroll
        for (int ks = 0; ks < 8; ++ks) {
            unsigned a0, a1, a2, a3;
            ldsm_x4(a0, a1, a2, a3, &Ps[a_row * ASTR + ks * 8 + a_koff]);
#pragma unroll
            for (int ng = 0; ng < 4; ++ng) {
                int br = brow_base + ng * 16;
                unsigned r0, r1, r2, r3;
                ldsm_x4(r0, r1, r2, r3,
                        &Vb[br * ASTR + ((ks * 8 + bko) ^ (4 * ((br >> 5) & 1)))]);
                mma_tf32(o[ng * 2][0], o[ng * 2][1], o[ng * 2][2], o[ng * 2][3],
                         a0, a1, a2, a3, r0, r1);
                mma_tf32(o[ng * 2 + 1][0], o[ng * 2 + 1][1], o[ng * 2 + 1][2], o[ng * 2 + 1][3],
                         a0, a1, a2, a3, r2, r3);
            }
        }

        if (kt + 1 < 16) {
            float* Vd = Vt + (buf ^ 1) * KBUF;
#pragma unroll
            for (int i = 0; i < 4; ++i) {
                float v[4] = {vreg[i].x, vreg[i].y, vreg[i].z, vreg[i].w};
#pragma unroll
                for (int j = 0; j < 4; ++j) {
                    int hd = vc[i] + j;
                    Vd[hd * ASTR + (vkey[i] ^ (4 * ((hd >> 5) & 1)))] = v[j];
                }
            }
        }
    }

    l0 += __shfl_xor_sync(0xffffffffu, l0, 1);
    l0 += __shfl_xor_sync(0xffffffffu, l0, 2);
    l1 += __shfl_xor_sync(0xffffffffu, l1, 1);
    l1 += __shfl_xor_sync(0xffffffffu, l1, 2);
    float inv0 = 1.f / l0, inv1 = 1.f / l1;

    float* ob0 = out + ((size_t)(t0 + prow0) * B_ + b) * D_ + h * 64 + pcol;
    float* ob1 = out + ((size_t)(t0 + prow0 + 8) * B_ + b) * D_ + h * 64 + pcol;
#pragma unroll
    for (int n = 0; n < 8; ++n) {
        *reinterpret_cast<float2*>(ob0 + n * 8) = make_float2(o[n][0] * inv0, o[n][1] * inv0);
        *reinterpret_cast<float2*>(ob1 + n * 8) = make_float2(o[n][2] * inv1, o[n][3] * inv1);
    }
}

#define ATTN_SMEM (384 * ASTR * 4)

// ---------------------------------------------------------------------------
// Sliding-window cross-attention.
// ---------------------------------------------------------------------------
__global__ void __launch_bounds__(256) sw_attn_kernel(
    const float* __restrict__ q, const float* __restrict__ k,
    const float* __restrict__ v, float* __restrict__ out)
{
    const int gw = (blockIdx.x * blockDim.x + threadIdx.x) >> 5;
    const int lane = threadIdx.x & 31;
    if (gw >= T_ * B_ * H_) return;
    const int h = gw & 7;
    const int b = (gw >> 3) & 3;
    const int t = gw >> 5;

    const float2 q2 = reinterpret_cast<const float2*>(
        q + ((size_t)t * B_ + b) * D_ + h * HD_)[lane];

    float sc[33];
#pragma unroll
    for (int jj = 0; jj < 33; ++jj) {
        int j = t - W_ + jj;
        float s = -1e30f;
        if (j >= 0 && j < S_) {
            const float2 k2 = reinterpret_cast<const float2*>(
                k + ((size_t)j * B_ + b) * D_ + h * HD_)[lane];
            float p = q2.x * k2.x + q2.y * k2.y;
#pragma unroll
            for (int o = 16; o > 0; o >>= 1)
                p += __shfl_xor_sync(0xffffffffu, p, o);
            s = p * SCALE_;
        }
        sc[jj] = s;
    }

    float m = -1e30f;
#pragma unroll
    for (int jj = 0; jj < 33; ++jj) m = fmaxf(m, sc[jj]);

    float l = 0.f, a0 = 0.f, a1 = 0.f;
#pragma unroll
    for (int jj = 0; jj < 33; ++jj) {
        int j = t - W_ + jj;
        if (j >= 0 && j < S_) {
            float p = __expf(sc[jj] - m);
            l += p;
            const float2 v2 = reinterpret_cast<const float2*>(
                v + ((size_t)j * B_ + b) * D_ + h * HD_)[lane];
            a0 += p * v2.x;
            a1 += p * v2.y;
        }
    }
    float inv = 1.f / l;
    float* op = out + ((size_t)t * B_ + b) * D_ + h * HD_;
    op[lane * 2] = a0 * inv;
    op[lane * 2 + 1] = a1 * inv;
}

// ---------------------------------------------------------------------------
// Fused residual-add + LayerNorm over D=512.
// ---------------------------------------------------------------------------
__global__ void __launch_bounds__(256) add_ln_kernel(
    const float* __restrict__ x, const float* __restrict__ y,
    const float* __restrict__ g, const float* __restrict__ beta,
    float* __restrict__ out)
{
    __shared__ float sh[33];
    const int row = blockIdx.x;
    const int tid = threadIdx.x;
    const size_t base = (size_t)row * D_;

    float v0 = x[base + tid] + y[base + tid];
    float v1 = x[base + tid + 256] + y[base + tid + 256];

    float s = v0 + v1;
#pragma unroll
    for (int o = 16; o > 0; o >>= 1) s += __shfl_xor_sync(0xffffffffu, s, o);
    int lane = tid & 31, wid = tid >> 5;
    if (lane == 0) sh[wid] = s;
    __syncthreads();
    if (wid == 0) {
        float t = (lane < 8) ? sh[lane] : 0.f;
#pragma unroll
        for (int o = 4; o > 0; o >>= 1) t += __shfl_xor_sync(0xffffffffu, t, o);
        if (lane == 0) sh[32] = t;
    }
    __syncthreads();
    float mean = sh[32] * (1.f / D_);
    __syncthreads();

    float d0 = v0 - mean, d1 = v1 - mean;
    float sq = d0 * d0 + d1 * d1;
#pragma unroll
    for (int o = 16; o > 0; o >>= 1) sq += __shfl_xor_sync(0xffffffffu, sq, o);
    if (lane == 0) sh[wid] = sq;
    __syncthreads();
    if (wid == 0) {
        float t = (lane < 8) ? sh[lane] : 0.f;
#pragma unroll
        for (int o = 4; o > 0; o >>= 1) t += __shfl_xor_sync(0xffffffffu, t, o);
        if (lane == 0) sh[32] = t;
    }
    __syncthreads();
    float rstd = rsqrtf(sh[32] * (1.f / D_) + EPS_);

    out[base + tid] = d0 * rstd * g[tid] + beta[tid];
    out[base + tid + 256] = d1 * rstd * g[tid + 256] + beta[tid + 256];
}

// ---------------------------------------------------------------------------
// Launch
// ---------------------------------------------------------------------------
extern "C" void kernel_launch(void* const* d_in, const int* in_sizes, int n_in,
                              void* d_out, int out_size)
{
    (void)in_sizes; (void)n_in; (void)out_size;
    const float* tgt        = (const float*)d_in[0];
    const float* memory     = (const float*)d_in[1];
    const float* in_proj_w  = (const float*)d_in[2];
    const float* in_proj_b  = (const float*)d_in[3];
    const float* out_proj_w = (const float*)d_in[4];
    const float* out_proj_b = (const float*)d_in[5];
    const float* sw_q_w = (const float*)d_in[6];
    const float* sw_q_b = (const float*)d_in[7];
    const float* sw_k_w = (const float*)d_in[8];
    const float* sw_k_b = (const float*)d_in[9];
    const float* sw_v_w = (const float*)d_in[10];
    const float* sw_v_b = (const float*)d_in[11];
    const float* sw_o_w = (const float*)d_in[12];
    const float* sw_o_b = (const float*)d_in[13];
    const float* lin1_w = (const float*)d_in[14];
    const float* lin1_b = (const float*)d_in[15];
    const float* lin2_w = (const float*)d_in[16];
    const float* lin2_b = (const float*)d_in[17];
    const float* n1_g = (const float*)d_in[18];
    const float* n1_b = (const float*)d_in[19];
    const float* n2_g = (const float*)d_in[20];
    const float* n2_b = (const float*)d_in[21];
    const float* n3_g = (const float*)d_in[22];
    const float* n3_b = (const float*)d_in[23];
    float* out = (float*)d_out;

    float* s = nullptr;
    cudaGetSymbolAddress((void**)&s, g_scratch);
    float* qkv    = s + OFF_QKV;
    float* attn   = s + OFF_ATTN;
    float* proj   = s + OFF_PROJ;
    float* x1     = s + OFF_X1;
    float* swq    = s + OFF_SWQ;
    float* swk    = s + OFF_SWK;
    float* swv    = s + OFF_SWV;
    float* swattn = s + OFF_SWATTN;
    float* x2     = s + OFF_X2;
    float* hbuf   = s + OFF_H;
    float* ffbuf  = s + OFF_FF;

    cudaFuncSetAttribute(self_attn_mma_kernel,
                         cudaFuncAttributeMaxDynamicSharedMemorySize, ATTN_SMEM);

    // independent GEMMs first
    gemm_tf32_n64_kernel<<<dim3(8, 32), 256>>>(memory, sw_k_w, sw_k_b, swk, NROWS, D_, D_, 0);
    gemm_tf32_n64_kernel<<<dim3(8, 32), 256>>>(memory, sw_v_w, sw_v_b, swv, NROWS, D_, D_, 0);
    // 1. QKV projection
    gemm_tf32_kernel<<<dim3(12, 32), 256>>>(tgt, in_proj_w, in_proj_b, qkv,
                                            NROWS, 3 * D_, D_, 0);
    // 2. self attention
    self_attn_mma_kernel<<<dim3(8, 32), 256, ATTN_SMEM>>>(qkv, attn);
    // 3. out projection
    gemm_tf32_n64_kernel<<<dim3(8, 32), 256>>>(attn, out_proj_w, out_proj_b, proj,
                                               NROWS, D_, D_, 0);
    // 4. add + LN1
    add_ln_kernel<<<NROWS, 256>>>(tgt, proj, n1_g, n1_b, x1);
    // 5. sw q projection
    gemm_tf32_n64_kernel<<<dim3(8, 32), 256>>>(x1, sw_q_w, sw_q_b, swq, NROWS, D_, D_, 0);
    // 8. banded attention
    sw_attn_kernel<<<4096, 256>>>(swq, swk, swv, swattn);
    // 9. sw out projection
    gemm_tf32_n64_kernel<<<dim3(8, 32), 256>>>(swattn, sw_o_w, sw_o_b, proj, NROWS, D_, D_, 0);
    // 10. add + LN2
    add_ln_kernel<<<NROWS, 256>>>(x1, proj, n2_g, n2_b, x2);
    // 11. FFN up + ReLU
    gemm_tf32_kernel<<<dim3(16, 32), 256>>>(x2, lin1_w, lin1_b, hbuf, NROWS, DFF_, D_, 1);
    // 12. FFN down
    gemm_tf32_n64_kernel<<<dim3(8, 32), 256>>>(hbuf, lin2_w, lin2_b, ffbuf, NROWS, D_, DFF_, 0);
    // 13. add + LN3 -> output
    add_ln_kernel<<<NROWS, 256>>>(x2, ffbuf, n3_g, n3_b, out);
}

// round 6
// speedup vs baseline: 3.5595x; 1.1260x over previous
#include <cuda_runtime.h>
#include <cuda_bf16.h>
#include <math.h>

#define T_ 1024
#define S_ 1024
#define B_ 4
#define D_ 512
#define H_ 8
#define HD_ 64
#define DFF_ 2048
#define W_ 16
#define NROWS (T_ * B_)
#define SCALE_ 0.125f
#define EPS_ 1e-5f

#define OFF_QKV     0
#define OFF_ATTN    6291456
#define OFF_PROJ    8388608
#define OFF_X1      10485760
#define OFF_SWQ     12582912
#define OFF_SWKV    14680064   /* 4096 x 1024 */
#define OFF_SWATTN  18874368
#define OFF_X2      20971520
#define OFF_H       23068672   /* also scratch for wcat/bcat before FFN */
#define OFF_FF      31457280
#define SCRATCH_FLOATS 33554432

__device__ float g_scratch[SCRATCH_FLOATS];

// ---------------------------------------------------------------------------
// PTX helpers
// ---------------------------------------------------------------------------
__device__ __forceinline__ void cp_async16(void* smem_ptr, const void* gmem_ptr) {
    unsigned saddr = (unsigned)__cvta_generic_to_shared(smem_ptr);
    asm volatile("cp.async.cg.shared.global [%0], [%1], 16;\n"
                 :: "r"(saddr), "l"(gmem_ptr));
}
__device__ __forceinline__ void cp_commit() {
    asm volatile("cp.async.commit_group;\n");
}
__device__ __forceinline__ void cp_wait0() {
    asm volatile("cp.async.wait_group 0;\n");
}
__device__ __forceinline__ void cp_wait1() {
    asm volatile("cp.async.wait_group 1;\n");
}
__device__ __forceinline__ void cp_wait2() {
    asm volatile("cp.async.wait_group 2;\n");
}
__device__ __forceinline__ void ldsm_x4(unsigned& r0, unsigned& r1, unsigned& r2, unsigned& r3,
                                        const float* p) {
    unsigned saddr = (unsigned)__cvta_generic_to_shared((void*)p);
    asm volatile("ldmatrix.sync.aligned.m8n8.x4.shared.b16 {%0,%1,%2,%3}, [%4];\n"
                 : "=r"(r0), "=r"(r1), "=r"(r2), "=r"(r3) : "r"(saddr));
}
__device__ __forceinline__ void mma_tf32(float& c0, float& c1, float& c2, float& c3,
                                         unsigned a0, unsigned a1, unsigned a2, unsigned a3,
                                         unsigned b0, unsigned b1) {
    asm volatile("mma.sync.aligned.m16n8k8.row.col.f32.tf32.tf32.f32 "
                 "{%0,%1,%2,%3}, {%4,%5,%6,%7}, {%8,%9}, {%0,%1,%2,%3};\n"
                 : "+f"(c0), "+f"(c1), "+f"(c2), "+f"(c3)
                 : "r"(a0), "r"(a1), "r"(a2), "r"(a3), "r"(b0), "r"(b1));
}

#define BK 16
#define STR 20
#define NSTAGE 4

// ---------------------------------------------------------------------------
// GEMM 128x128 (qkv, ffn-up, fused KV).
// ---------------------------------------------------------------------------
__global__ void __launch_bounds__(256, 2) gemm_tf32_kernel(
    const float* __restrict__ A, const float* __restrict__ Wt,
    const float* __restrict__ bias, float* __restrict__ C,
    int M, int N, int K, int relu)
{
    __shared__ __align__(16) float As[NSTAGE][128 * STR];
    __shared__ __align__(16) float Bs[NSTAGE][128 * STR];

    const int tid  = threadIdx.x;
    const int wid  = tid >> 5;
    const int lane = tid & 31;
    const int wm   = (wid & 3) * 32;
    const int wn   = (wid >> 2) * 64;
    const int m0   = blockIdx.y * 128;
    const int n0   = blockIdx.x * 128;

    const int lrow = tid >> 2;
    const int lcol = (tid & 3) * 4;

    float acc[2][8][4];
#pragma unroll
    for (int i = 0; i < 2; ++i)
#pragma unroll
        for (int j = 0; j < 8; ++j)
#pragma unroll
            for (int q = 0; q < 4; ++q) acc[i][j][q] = 0.f;

    const int ntiles = K / BK;
    const float* Abase = A + (size_t)m0 * K;
    const float* Bbase = Wt + (size_t)n0 * K;

#pragma unroll
    for (int s = 0; s < NSTAGE - 1; ++s) {
        int k0 = s * BK;
#pragma unroll
        for (int p = 0; p < 2; ++p) {
            int r = lrow + p * 64;
            cp_async16(&As[s][r * STR + lcol], Abase + (size_t)r * K + k0 + lcol);
            cp_async16(&Bs[s][r * STR + lcol], Bbase + (size_t)r * K + k0 + lcol);
        }
        cp_commit();
    }

    const int a_row = wm + (lane & 15);
    const int a_koff = (lane >> 4) * 4;
    const int b_row_base = wn + (lane & 7) + ((lane >> 4) * 8);
    const int b_koff = ((lane >> 3) & 1) * 4;

    for (int t = 0; t < ntiles; ++t) {
        cp_wait2();
        __syncthreads();

        int ps = t + NSTAGE - 1;
        if (ps < ntiles) {
            int sb = ps & (NSTAGE - 1);
            int k0 = ps * BK;
#pragma unroll
            for (int p = 0; p < 2; ++p) {
                int r = lrow + p * 64;
                cp_async16(&As[sb][r * STR + lcol], Abase + (size_t)r * K + k0 + lcol);
                cp_async16(&Bs[sb][r * STR + lcol], Bbase + (size_t)r * K + k0 + lcol);
            }
        }
        cp_commit();

        const int buf = t & (NSTAGE - 1);
#pragma unroll
        for (int ks = 0; ks < 2; ++ks) {
            unsigned a[2][4];
            unsigned b[8][2];
#pragma unroll
            for (int im = 0; im < 2; ++im) {
                const float* p = &As[buf][(a_row + im * 16) * STR + ks * 8 + a_koff];
                ldsm_x4(a[im][0], a[im][1], a[im][2], a[im][3], p);
            }
#pragma unroll
            for (int it = 0; it < 4; ++it) {
                const float* p = &Bs[buf][(b_row_base + it * 16) * STR + ks * 8 + b_koff];
                unsigned r0, r1, r2, r3;
                ldsm_x4(r0, r1, r2, r3, p);
                b[it * 2][0] = r0; b[it * 2][1] = r1;
                b[it * 2 + 1][0] = r2; b[it * 2 + 1][1] = r3;
            }
#pragma unroll
            for (int im = 0; im < 2; ++im)
#pragma unroll
                for (int in = 0; in < 8; ++in)
                    mma_tf32(acc[im][in][0], acc[im][in][1], acc[im][in][2], acc[im][in][3],
                             a[im][0], a[im][1], a[im][2], a[im][3],
                             b[in][0], b[in][1]);
        }
    }

    const int row_base = m0 + wm + (lane >> 2);
    const int col_base = n0 + wn + (lane & 3) * 2;
#pragma unroll
    for (int im = 0; im < 2; ++im) {
#pragma unroll
        for (int in = 0; in < 8; ++in) {
            int col = col_base + in * 8;
            float b0 = bias[col], b1 = bias[col + 1];
            int r0 = row_base + im * 16;
            float v0 = acc[im][in][0] + b0;
            float v1 = acc[im][in][1] + b1;
            float v2 = acc[im][in][2] + b0;
            float v3 = acc[im][in][3] + b1;
            if (relu) {
                v0 = fmaxf(v0, 0.f); v1 = fmaxf(v1, 0.f);
                v2 = fmaxf(v2, 0.f); v3 = fmaxf(v3, 0.f);
            }
            C[(size_t)r0 * N + col] = v0;
            C[(size_t)r0 * N + col + 1] = v1;
            C[(size_t)(r0 + 8) * N + col] = v2;
            C[(size_t)(r0 + 8) * N + col + 1] = v3;
        }
    }
}

// ---------------------------------------------------------------------------
// GEMM 128x64 (N=512 GEMMs).
// ---------------------------------------------------------------------------
__global__ void __launch_bounds__(256, 2) gemm_tf32_n64_kernel(
    const float* __restrict__ A, const float* __restrict__ Wt,
    const float* __restrict__ bias, float* __restrict__ C,
    int M, int N, int K, int relu)
{
    __shared__ __align__(16) float As[NSTAGE][128 * STR];
    __shared__ __align__(16) float Bs[NSTAGE][64 * STR];

    const int tid  = threadIdx.x;
    const int wid  = tid >> 5;
    const int lane = tid & 31;
    const int wm   = (wid & 3) * 32;
    const int wn   = (wid >> 2) * 32;
    const int m0   = blockIdx.y * 128;
    const int n0   = blockIdx.x * 64;

    const int lrow = tid >> 2;
    const int lcol = (tid & 3) * 4;

    float acc[2][4][4];
#pragma unroll
    for (int i = 0; i < 2; ++i)
#pragma unroll
        for (int j = 0; j < 4; ++j)
#pragma unroll
            for (int q = 0; q < 4; ++q) acc[i][j][q] = 0.f;

    const int ntiles = K / BK;
    const float* Abase = A + (size_t)m0 * K;
    const float* Bbase = Wt + (size_t)n0 * K;

#pragma unroll
    for (int s = 0; s < NSTAGE - 1; ++s) {
        int k0 = s * BK;
#pragma unroll
        for (int p = 0; p < 2; ++p) {
            int r = lrow + p * 64;
            cp_async16(&As[s][r * STR + lcol], Abase + (size_t)r * K + k0 + lcol);
        }
        cp_async16(&Bs[s][lrow * STR + lcol], Bbase + (size_t)lrow * K + k0 + lcol);
        cp_commit();
    }

    const int a_row = wm + (lane & 15);
    const int a_koff = (lane >> 4) * 4;
    const int b_row_base = wn + (lane & 7) + ((lane >> 4) * 8);
    const int b_koff = ((lane >> 3) & 1) * 4;

    for (int t = 0; t < ntiles; ++t) {
        cp_wait2();
        __syncthreads();

        int ps = t + NSTAGE - 1;
        if (ps < ntiles) {
            int sb = ps & (NSTAGE - 1);
            int k0 = ps * BK;
#pragma unroll
            for (int p = 0; p < 2; ++p) {
                int r = lrow + p * 64;
                cp_async16(&As[sb][r * STR + lcol], Abase + (size_t)r * K + k0 + lcol);
            }
            cp_async16(&Bs[sb][lrow * STR + lcol], Bbase + (size_t)lrow * K + k0 + lcol);
        }
        cp_commit();

        const int buf = t & (NSTAGE - 1);
#pragma unroll
        for (int ks = 0; ks < 2; ++ks) {
            unsigned a[2][4];
            unsigned b[4][2];
#pragma unroll
            for (int im = 0; im < 2; ++im) {
                const float* p = &As[buf][(a_row + im * 16) * STR + ks * 8 + a_koff];
                ldsm_x4(a[im][0], a[im][1], a[im][2], a[im][3], p);
            }
#pragma unroll
            for (int it = 0; it < 2; ++it) {
                const float* p = &Bs[buf][(b_row_base + it * 16) * STR + ks * 8 + b_koff];
                unsigned r0, r1, r2, r3;
                ldsm_x4(r0, r1, r2, r3, p);
                b[it * 2][0] = r0; b[it * 2][1] = r1;
                b[it * 2 + 1][0] = r2; b[it * 2 + 1][1] = r3;
            }
#pragma unroll
            for (int im = 0; im < 2; ++im)
#pragma unroll
                for (int in = 0; in < 4; ++in)
                    mma_tf32(acc[im][in][0], acc[im][in][1], acc[im][in][2], acc[im][in][3],
                             a[im][0], a[im][1], a[im][2], a[im][3],
                             b[in][0], b[in][1]);
        }
    }

    const int row_base = m0 + wm + (lane >> 2);
    const int col_base = n0 + wn + (lane & 3) * 2;
#pragma unroll
    for (int im = 0; im < 2; ++im) {
#pragma unroll
        for (int in = 0; in < 4; ++in) {
            int col = col_base + in * 8;
            float b0 = bias[col], b1 = bias[col + 1];
            int r0 = row_base + im * 16;
            float v0 = acc[im][in][0] + b0;
            float v1 = acc[im][in][1] + b1;
            float v2 = acc[im][in][2] + b0;
            float v3 = acc[im][in][3] + b1;
            if (relu) {
                v0 = fmaxf(v0, 0.f); v1 = fmaxf(v1, 0.f);
                v2 = fmaxf(v2, 0.f); v3 = fmaxf(v3, 0.f);
            }
            C[(size_t)r0 * N + col] = v0;
            C[(size_t)r0 * N + col + 1] = v1;
            C[(size_t)(r0 + 8) * N + col] = v2;
            C[(size_t)(r0 + 8) * N + col + 1] = v3;
        }
    }
}

// ---------------------------------------------------------------------------
// TF32 flash self-attention (conflict-free V staging).
// ---------------------------------------------------------------------------
#define ASTR 68
#define KBUF (64 * ASTR)
#define ROWF 6144

__global__ void __launch_bounds__(256, 2) self_attn_mma_kernel(
    const float* __restrict__ qkv, float* __restrict__ out)
{
    extern __shared__ float sm[];
    float* Ps = sm;
    float* Ks = sm + 128 * ASTR;
    float* Vt = sm + 256 * ASTR;

    const int tid = threadIdx.x;
    const int wid = tid >> 5;
    const int lane = tid & 31;
    const int b = blockIdx.y >> 3;
    const int h = blockIdx.y & 7;
    const int t0 = blockIdx.x * 128;
    const int wm = wid * 16;

    const float* qbase = qkv + ((size_t)t0 * B_ + b) * 1536 + h * 64;
    const float* kroot = qkv + (size_t)b * 1536 + 512 + h * 64;
    const float* vroot = qkv + (size_t)b * 1536 + 1024 + h * 64;

    // K loader mapping (row-contiguous)
    int kkey[4], kc[4];
#pragma unroll
    for (int i = 0; i < 4; ++i) {
        int fidx = i * 256 + tid;
        kkey[i] = fidx >> 4;
        kc[i] = (fidx & 15) * 4;
    }
    // V loader mapping (lane-per-key: conflict-free transpose STS)
    const int vkey = tid & 63;
    const int vh0 = (tid >> 6) * 4;   // + 16*i

#pragma unroll
    for (int i = 0; i < 8; ++i) {
        int fidx = i * 256 + tid;
        int r = fidx >> 4, c = (fidx & 15) * 4;
        cp_async16(&Ps[r * ASTR + c], qbase + (size_t)r * ROWF + c);
    }
#pragma unroll
    for (int i = 0; i < 4; ++i)
        cp_async16(&Ks[kkey[i] * ASTR + kc[i]], kroot + (size_t)kkey[i] * ROWF + kc[i]);
    cp_commit();

    float4 vreg[4];
#pragma unroll
    for (int i = 0; i < 4; ++i)
        vreg[i] = *reinterpret_cast<const float4*>(vroot + (size_t)vkey * ROWF + vh0 + 16 * i);

    cp_wait0();
    __syncthreads();

    unsigned qf[8][4];
    {
        const int a_row_q = wm + (lane & 15);
        const int a_koff_q = (lane >> 4) * 4;
#pragma unroll
        for (int ks = 0; ks < 8; ++ks) {
            unsigned r0, r1, r2, r3;
            ldsm_x4(r0, r1, r2, r3, &Ps[a_row_q * ASTR + ks * 8 + a_koff_q]);
            qf[ks][0] = __float_as_uint(__uint_as_float(r0) * SCALE_);
            qf[ks][1] = __float_as_uint(__uint_as_float(r1) * SCALE_);
            qf[ks][2] = __float_as_uint(__uint_as_float(r2) * SCALE_);
            qf[ks][3] = __float_as_uint(__uint_as_float(r3) * SCALE_);
        }
    }

#pragma unroll
    for (int i = 0; i < 4; ++i) {
        float v[4] = {vreg[i].x, vreg[i].y, vreg[i].z, vreg[i].w};
#pragma unroll
        for (int j = 0; j < 4; ++j) {
            int hd = vh0 + 16 * i + j;
            Vt[hd * ASTR + (vkey ^ (4 * ((hd >> 5) & 1)))] = v[j];
        }
    }

    float o[8][4];
#pragma unroll
    for (int n = 0; n < 8; ++n)
#pragma unroll
        for (int c = 0; c < 4; ++c) o[n][c] = 0.f;
    float m0 = -1e30f, m1 = -1e30f, l0 = 0.f, l1 = 0.f;

    const int brow_base = (lane & 7) + ((lane >> 4) * 8);
    const int bko = ((lane >> 3) & 1) * 4;
    const int prow0 = wm + (lane >> 2);
    const int pcol = 2 * (lane & 3);
    const int a_row = wm + (lane & 15);
    const int a_koff = (lane >> 4) * 4;

    for (int kt = 0; kt < 16; ++kt) {
        const int buf = kt & 1;
        __syncthreads();

        if (kt + 1 < 16) {
            const float* kb = kroot + (size_t)(kt + 1) * 64 * ROWF;
            float* kd = Ks + (buf ^ 1) * KBUF;
#pragma unroll
            for (int i = 0; i < 4; ++i)
                cp_async16(&kd[kkey[i] * ASTR + kc[i]], kb + (size_t)kkey[i] * ROWF + kc[i]);
            cp_commit();
            const float* vb = vroot + (size_t)(kt + 1) * 64 * ROWF;
#pragma unroll
            for (int i = 0; i < 4; ++i)
                vreg[i] = *reinterpret_cast<const float4*>(vb + (size_t)vkey * ROWF + vh0 + 16 * i);
            cp_wait1();
        } else {
            cp_wait0();
        }
        __syncthreads();

        const float* Kb = Ks + buf * KBUF;
        float s[8][4];
#pragma unroll
        for (int n = 0; n < 8; ++n)
#pragma unroll
            for (int c = 0; c < 4; ++c) s[n][c] = 0.f;
#pragma unroll
        for (int ks = 0; ks < 8; ++ks) {
#pragma unroll
            for (int ng = 0; ng < 4; ++ng) {
                unsigned r0, r1, r2, r3;
                ldsm_x4(r0, r1, r2, r3, &Kb[(brow_base + ng * 16) * ASTR + ks * 8 + bko]);
                mma_tf32(s[ng * 2][0], s[ng * 2][1], s[ng * 2][2], s[ng * 2][3],
                         qf[ks][0], qf[ks][1], qf[ks][2], qf[ks][3], r0, r1);
                mma_tf32(s[ng * 2 + 1][0], s[ng * 2 + 1][1], s[ng * 2 + 1][2], s[ng * 2 + 1][3],
                         qf[ks][0], qf[ks][1], qf[ks][2], qf[ks][3], r2, r3);
            }
        }

        float mx0 = -1e30f, mx1 = -1e30f;
#pragma unroll
        for (int n = 0; n < 8; ++n) {
            mx0 = fmaxf(mx0, fmaxf(s[n][0], s[n][1]));
            mx1 = fmaxf(mx1, fmaxf(s[n][2], s[n][3]));
        }
        mx0 = fmaxf(mx0, __shfl_xor_sync(0xffffffffu, mx0, 1));
        mx0 = fmaxf(mx0, __shfl_xor_sync(0xffffffffu, mx0, 2));
        mx1 = fmaxf(mx1, __shfl_xor_sync(0xffffffffu, mx1, 1));
        mx1 = fmaxf(mx1, __shfl_xor_sync(0xffffffffu, mx1, 2));

        float mn0 = fmaxf(m0, mx0), mn1 = fmaxf(m1, mx1);
        float corr0 = __expf(m0 - mn0), corr1 = __expf(m1 - mn1);
        m0 = mn0; m1 = mn1;
        l0 *= corr0; l1 *= corr1;
#pragma unroll
        for (int n = 0; n < 8; ++n) {
            o[n][0] *= corr0; o[n][1] *= corr0;
            o[n][2] *= corr1; o[n][3] *= corr1;
        }
#pragma unroll
        for (int n = 0; n < 8; ++n) {
            float p0 = __expf(s[n][0] - mn0);
            float p1 = __expf(s[n][1] - mn0);
            float p2 = __expf(s[n][2] - mn1);
            float p3 = __expf(s[n][3] - mn1);
            l0 += p0 + p1; l1 += p2 + p3;
            *reinterpret_cast<float2*>(&Ps[prow0 * ASTR + n * 8 + pcol]) = make_float2(p0, p1);
            *reinterpret_cast<float2*>(&Ps[(prow0 + 8) * ASTR + n * 8 + pcol]) = make_float2(p2, p3);
        }
        __syncwarp();

        const float* Vb = Vt + buf * KBUF;
#pragma unroll
        for (int ks = 0; ks < 8; ++ks) {
            unsigned a0, a1, a2, a3;
            ldsm_x4(a0, a1, a2, a3, &Ps[a_row * ASTR + ks * 8 + a_koff]);
#pragma unroll
            for (int ng = 0; ng < 4; ++ng) {
                int br = brow_base + ng * 16;
                unsigned r0, r1, r2, r3;
                ldsm_x4(r0, r1, r2, r3,
                        &Vb[br * ASTR + ((ks * 8 + bko) ^ (4 * ((br >> 5) & 1)))]);
                mma_tf32(o[ng * 2][0], o[ng * 2][1], o[ng * 2][2], o[ng * 2][3],
                         a0, a1, a2, a3, r0, r1);
                mma_tf32(o[ng * 2 + 1][0], o[ng * 2 + 1][1], o[ng * 2 + 1][2], o[ng * 2 + 1][3],
                         a0, a1, a2, a3, r2, r3);
            }
        }

        if (kt + 1 < 16) {
            float* Vd = Vt + (buf ^ 1) * KBUF;
#pragma unroll
            for (int i = 0; i < 4; ++i) {
                float v[4] = {vreg[i].x, vreg[i].y, vreg[i].z, vreg[i].w};
#pragma unroll
                for (int j = 0; j < 4; ++j) {
                    int hd = vh0 + 16 * i + j;
                    Vd[hd * ASTR + (vkey ^ (4 * ((hd >> 5) & 1)))] = v[j];
                }
            }
        }
    }

    l0 += __shfl_xor_sync(0xffffffffu, l0, 1);
    l0 += __shfl_xor_sync(0xffffffffu, l0, 2);
    l1 += __shfl_xor_sync(0xffffffffu, l1, 1);
    l1 += __shfl_xor_sync(0xffffffffu, l1, 2);
    float inv0 = 1.f / l0, inv1 = 1.f / l1;

    float* ob0 = out + ((size_t)(t0 + prow0) * B_ + b) * D_ + h * 64 + pcol;
    float* ob1 = out + ((size_t)(t0 + prow0 + 8) * B_ + b) * D_ + h * 64 + pcol;
#pragma unroll
    for (int n = 0; n < 8; ++n) {
        *reinterpret_cast<float2*>(ob0 + n * 8) = make_float2(o[n][0] * inv0, o[n][1] * inv0);
        *reinterpret_cast<float2*>(ob1 + n * 8) = make_float2(o[n][2] * inv1, o[n][3] * inv1);
    }
}

#define ATTN_SMEM (384 * ASTR * 4)

// ---------------------------------------------------------------------------
// Banded sliding-window cross-attention on tensor cores.
// q: swq [T,B,512]; kv: fused [T,B,1024] (K at col h*64, V at 512+h*64).
// 3 key tiles of 64 covering keys [t0-16, t0+175]; band mask in fragments.
// ---------------------------------------------------------------------------
__global__ void __launch_bounds__(256, 2) sw_attn_mma_kernel(
    const float* __restrict__ q, const float* __restrict__ kv,
    float* __restrict__ out)
{
    extern __shared__ float sm[];
    float* Ps = sm;
    float* Ks = sm + 128 * ASTR;
    float* Vt = sm + 256 * ASTR;

    const int tid = threadIdx.x;
    const int wid = tid >> 5;
    const int lane = tid & 31;
    const int b = blockIdx.y >> 3;
    const int h = blockIdx.y & 7;
    const int t0 = blockIdx.x * 128;
    const int wm = wid * 16;

    // K loader mapping
    int kkey[4], kc[4];
#pragma unroll
    for (int i = 0; i < 4; ++i) {
        int fidx = i * 256 + tid;
        kkey[i] = fidx >> 4;
        kc[i] = (fidx & 15) * 4;
    }
    const int vkey = tid & 63;
    const int vh0 = (tid >> 6) * 4;

    // Q -> Ps
#pragma unroll
    for (int i = 0; i < 8; ++i) {
        int fidx = i * 256 + tid;
        int r = fidx >> 4, c = (fidx & 15) * 4;
        cp_async16(&Ps[r * ASTR + c],
                   q + ((size_t)(t0 + r) * B_ + b) * D_ + h * 64 + c);
    }
    // K tile 0 (keys t0-16 .. t0+47, clamped)
    {
        int key0 = t0 - 16;
#pragma unroll
        for (int i = 0; i < 4; ++i) {
            int key = min(max(key0 + kkey[i], 0), S_ - 1);
            cp_async16(&Ks[kkey[i] * ASTR + kc[i]],
                       kv + ((size_t)key * B_ + b) * 1024 + h * 64 + kc[i]);
        }
    }
    cp_commit();

    float4 vreg[4];
    {
        int key0 = t0 - 16;
        int key = min(max(key0 + vkey, 0), S_ - 1);
        const float* vp = kv + ((size_t)key * B_ + b) * 1024 + 512 + h * 64;
#pragma unroll
        for (int i = 0; i < 4; ++i)
            vreg[i] = *reinterpret_cast<const float4*>(vp + vh0 + 16 * i);
    }

    cp_wait0();
    __syncthreads();

    unsigned qf[8][4];
    {
        const int a_row_q = wm + (lane & 15);
        const int a_koff_q = (lane >> 4) * 4;
#pragma unroll
        for (int ks = 0; ks < 8; ++ks) {
            unsigned r0, r1, r2, r3;
            ldsm_x4(r0, r1, r2, r3, &Ps[a_row_q * ASTR + ks * 8 + a_koff_q]);
            qf[ks][0] = __float_as_uint(__uint_as_float(r0) * SCALE_);
            qf[ks][1] = __float_as_uint(__uint_as_float(r1) * SCALE_);
            qf[ks][2] = __float_as_uint(__uint_as_float(r2) * SCALE_);
            qf[ks][3] = __float_as_uint(__uint_as_float(r3) * SCALE_);
        }
    }

#pragma unroll
    for (int i = 0; i < 4; ++i) {
        float v[4] = {vreg[i].x, vreg[i].y, vreg[i].z, vreg[i].w};
#pragma unroll
        for (int j = 0; j < 4; ++j) {
            int hd = vh0 + 16 * i + j;
            Vt[hd * ASTR + (vkey ^ (4 * ((hd >> 5) & 1)))] = v[j];
        }
    }

    float o[8][4];
#pragma unroll
    for (int n = 0; n < 8; ++n)
#pragma unroll
        for (int c = 0; c < 4; ++c) o[n][c] = 0.f;
    float m0 = -1e30f, m1 = -1e30f, l0 = 0.f, l1 = 0.f;

    const int brow_base = (lane & 7) + ((lane >> 4) * 8);
    const int bko = ((lane >> 3) & 1) * 4;
    const int prow0 = wm + (lane >> 2);
    const int pcol = 2 * (lane & 3);
    const int a_row = wm + (lane & 15);
    const int a_koff = (lane >> 4) * 4;

    for (int kt = 0; kt < 3; ++kt) {
        const int buf = kt & 1;
        const int key0 = t0 - 16 + kt * 64;
        __syncthreads();

        if (kt + 1 < 3) {
            int nk0 = t0 - 16 + (kt + 1) * 64;
            float* kd = Ks + (buf ^ 1) * KBUF;
#pragma unroll
            for (int i = 0; i < 4; ++i) {
                int key = min(max(nk0 + kkey[i], 0), S_ - 1);
                cp_async16(&kd[kkey[i] * ASTR + kc[i]],
                           kv + ((size_t)key * B_ + b) * 1024 + h * 64 + kc[i]);
            }
            cp_commit();
            int key = min(max(nk0 + vkey, 0), S_ - 1);
            const float* vp = kv + ((size_t)key * B_ + b) * 1024 + 512 + h * 64;
#pragma unroll
            for (int i = 0; i < 4; ++i)
                vreg[i] = *reinterpret_cast<const float4*>(vp + vh0 + 16 * i);
            cp_wait1();
        } else {
            cp_wait0();
        }
        __syncthreads();

        const float* Kb = Ks + buf * KBUF;
        float s[8][4];
#pragma unroll
        for (int n = 0; n < 8; ++n)
#pragma unroll
            for (int c = 0; c < 4; ++c) s[n][c] = 0.f;
#pragma unroll
        for (int ks = 0; ks < 8; ++ks) {
#pragma unroll
            for (int ng = 0; ng < 4; ++ng) {
                unsigned r0, r1, r2, r3;
                ldsm_x4(r0, r1, r2, r3, &Kb[(brow_base + ng * 16) * ASTR + ks * 8 + bko]);
                mma_tf32(s[ng * 2][0], s[ng * 2][1], s[ng * 2][2], s[ng * 2][3],
                         qf[ks][0], qf[ks][1], qf[ks][2], qf[ks][3], r0, r1);
                mma_tf32(s[ng * 2 + 1][0], s[ng * 2 + 1][1], s[ng * 2 + 1][2], s[ng * 2 + 1][3],
                         qf[ks][0], qf[ks][1], qf[ks][2], qf[ks][3], r2, r3);
            }
        }

        // ---- band mask: key in [0,S) and |key - q| <= W ----
#pragma unroll
        for (int n = 0; n < 8; ++n) {
#pragma unroll
            for (int c = 0; c < 4; ++c) {
                int key = key0 + n * 8 + pcol + (c & 1);
                int qg = t0 + prow0 + ((c >> 1) * 8);
                bool valid = (key >= 0) && (key < S_) && (key - qg <= W_) && (qg - key <= W_);
                if (!valid) s[n][c] = -1e38f;
            }
        }

        float mx0 = -1e30f, mx1 = -1e30f;
#pragma unroll
        for (int n = 0; n < 8; ++n) {
            mx0 = fmaxf(mx0, fmaxf(s[n][0], s[n][1]));
            mx1 = fmaxf(mx1, fmaxf(s[n][2], s[n][3]));
        }
        mx0 = fmaxf(mx0, __shfl_xor_sync(0xffffffffu, mx0, 1));
        mx0 = fmaxf(mx0, __shfl_xor_sync(0xffffffffu, mx0, 2));
        mx1 = fmaxf(mx1, __shfl_xor_sync(0xffffffffu, mx1, 1));
        mx1 = fmaxf(mx1, __shfl_xor_sync(0xffffffffu, mx1, 2));

        float mn0 = fmaxf(m0, mx0), mn1 = fmaxf(m1, mx1);
        float corr0 = __expf(m0 - mn0), corr1 = __expf(m1 - mn1);
        m0 = mn0; m1 = mn1;
        l0 *= corr0; l1 *= corr1;
#pragma unroll
        for (int n = 0; n < 8; ++n) {
            o[n][0] *= corr0; o[n][1] *= corr0;
            o[n][2] *= corr1; o[n][3] *= corr1;
        }
#pragma unroll
        for (int n = 0; n < 8; ++n) {
            float p0 = __expf(s[n][0] - mn0);
            float p1 = __expf(s[n][1] - mn0);
            float p2 = __expf(s[n][2] - mn1);
            float p3 = __expf(s[n][3] - mn1);
            l0 += p0 + p1; l1 += p2 + p3;
            *reinterpret_cast<float2*>(&Ps[prow0 * ASTR + n * 8 + pcol]) = make_float2(p0, p1);
            *reinterpret_cast<float2*>(&Ps[(prow0 + 8) * ASTR + n * 8 + pcol]) = make_float2(p2, p3);
        }
        __syncwarp();

        const float* Vb = Vt + buf * KBUF;
#pragma unroll
        for (int ks = 0; ks < 8; ++ks) {
            unsigned a0, a1, a2, a3;
            ldsm_x4(a0, a1, a2, a3, &Ps[a_row * ASTR + ks * 8 + a_koff]);
#pragma unroll
            for (int ng = 0; ng < 4; ++ng) {
                int br = brow_base + ng * 16;
                unsigned r0, r1, r2, r3;
                ldsm_x4(r0, r1, r2, r3,
                        &Vb[br * ASTR + ((ks * 8 + bko) ^ (4 * ((br >> 5) & 1)))]);
                mma_tf32(o[ng * 2][0], o[ng * 2][1], o[ng * 2][2], o[ng * 2][3],
                         a0, a1, a2, a3, r0, r1);
                mma_tf32(o[ng * 2 + 1][0], o[ng * 2 + 1][1], o[ng * 2 + 1][2], o[ng * 2 + 1][3],
                         a0, a1, a2, a3, r2, r3);
            }
        }

        if (kt + 1 < 3) {
            float* Vd = Vt + (buf ^ 1) * KBUF;
#pragma unroll
            for (int i = 0; i < 4; ++i) {
                float v[4] = {vreg[i].x, vreg[i].y, vreg[i].z, vreg[i].w};
#pragma unroll
                for (int j = 0; j < 4; ++j) {
                    int hd = vh0 + 16 * i + j;
                    Vd[hd * ASTR + (vkey ^ (4 * ((hd >> 5) & 1)))] = v[j];
                }
            }
        }
    }

    l0 += __shfl_xor_sync(0xffffffffu, l0, 1);
    l0 += __shfl_xor_sync(0xffffffffu, l0, 2);
    l1 += __shfl_xor_sync(0xffffffffu, l1, 1);
    l1 += __shfl_xor_sync(0xffffffffu, l1, 2);
    float inv0 = 1.f / l0, inv1 = 1.f / l1;

    float* ob0 = out + ((size_t)(t0 + prow0) * B_ + b) * D_ + h * 64 + pcol;
    float* ob1 = out + ((size_t)(t0 + prow0 + 8) * B_ + b) * D_ + h * 64 + pcol;
#pragma unroll
    for (int n = 0; n < 8; ++n) {
        *reinterpret_cast<float2*>(ob0 + n * 8) = make_float2(o[n][0] * inv0, o[n][1] * inv0);
        *reinterpret_cast<float2*>(ob1 + n * 8) = make_float2(o[n][2] * inv1, o[n][3] * inv1);
    }
}

// ---------------------------------------------------------------------------
// Concat sw_k_w / sw_v_w weights + biases into one [1024,512] weight.
// ---------------------------------------------------------------------------
__global__ void __launch_bounds__(256) concat_w_kernel(
    const float* __restrict__ kw, const float* __restrict__ kb,
    const float* __restrict__ vw, const float* __restrict__ vb,
    float* __restrict__ wcat, float* __restrict__ bcat)
{
    int idx = blockIdx.x * 256 + threadIdx.x;   // 0 .. 262143
    wcat[idx] = kw[idx];
    wcat[262144 + idx] = vw[idx];
    if (idx < 512) {
        bcat[idx] = kb[idx];
        bcat[512 + idx] = vb[idx];
    }
}

// ---------------------------------------------------------------------------
// Fused residual-add + LayerNorm over D=512.
// ---------------------------------------------------------------------------
__global__ void __launch_bounds__(256) add_ln_kernel(
    const float* __restrict__ x, const float* __restrict__ y,
    const float* __restrict__ g, const float* __restrict__ beta,
    float* __restrict__ out)
{
    __shared__ float sh[33];
    const int row = blockIdx.x;
    const int tid = threadIdx.x;
    const size_t base = (size_t)row * D_;

    float v0 = x[base + tid] + y[base + tid];
    float v1 = x[base + tid + 256] + y[base + tid + 256];

    float s = v0 + v1;
#pragma unroll
    for (int o = 16; o > 0; o >>= 1) s += __shfl_xor_sync(0xffffffffu, s, o);
    int lane = tid & 31, wid = tid >> 5;
    if (lane == 0) sh[wid] = s;
    __syncthreads();
    if (wid == 0) {
        float t = (lane < 8) ? sh[lane] : 0.f;
#pragma unroll
        for (int o = 4; o > 0; o >>= 1) t += __shfl_xor_sync(0xffffffffu, t, o);
        if (lane == 0) sh[32] = t;
    }
    __syncthreads();
    float mean = sh[32] * (1.f / D_);
    __syncthreads();

    float d0 = v0 - mean, d1 = v1 - mean;
    float sq = d0 * d0 + d1 * d1;
#pragma unroll
    for (int o = 16; o > 0; o >>= 1) sq += __shfl_xor_sync(0xffffffffu, sq, o);
    if (lane == 0) sh[wid] = sq;
    __syncthreads();
    if (wid == 0) {
        float t = (lane < 8) ? sh[lane] : 0.f;
#pragma unroll
        for (int o = 4; o > 0; o >>= 1) t += __shfl_xor_sync(0xffffffffu, t, o);
        if (lane == 0) sh[32] = t;
    }
    __syncthreads();
    float rstd = rsqrtf(sh[32] * (1.f / D_) + EPS_);

    out[base + tid] = d0 * rstd * g[tid] + beta[tid];
    out[base + tid + 256] = d1 * rstd * g[tid + 256] + beta[tid + 256];
}

// ---------------------------------------------------------------------------
// Launch
// ---------------------------------------------------------------------------
extern "C" void kernel_launch(void* const* d_in, const int* in_sizes, int n_in,
                              void* d_out, int out_size)
{
    (void)in_sizes; (void)n_in; (void)out_size;
    const float* tgt        = (const float*)d_in[0];
    const float* memory     = (const float*)d_in[1];
    const float* in_proj_w  = (const float*)d_in[2];
    const float* in_proj_b  = (const float*)d_in[3];
    const float* out_proj_w = (const float*)d_in[4];
    const float* out_proj_b = (const float*)d_in[5];
    const float* sw_q_w = (const float*)d_in[6];
    const float* sw_q_b = (const float*)d_in[7];
    const float* sw_k_w = (const float*)d_in[8];
    const float* sw_k_b = (const float*)d_in[9];
    const float* sw_v_w = (const float*)d_in[10];
    const float* sw_v_b = (const float*)d_in[11];
    const float* sw_o_w = (const float*)d_in[12];
    const float* sw_o_b = (const float*)d_in[13];
    const float* lin1_w = (const float*)d_in[14];
    const float* lin1_b = (const float*)d_in[15];
    const float* lin2_w = (const float*)d_in[16];
    const float* lin2_b = (const float*)d_in[17];
    const float* n1_g = (const float*)d_in[18];
    const float* n1_b = (const float*)d_in[19];
    const float* n2_g = (const float*)d_in[20];
    const float* n2_b = (const float*)d_in[21];
    const float* n3_g = (const float*)d_in[22];
    const float* n3_b = (const float*)d_in[23];
    float* out = (float*)d_out;

    float* s = nullptr;
    cudaGetSymbolAddress((void**)&s, g_scratch);
    float* qkv    = s + OFF_QKV;
    float* attn   = s + OFF_ATTN;
    float* proj   = s + OFF_PROJ;
    float* x1     = s + OFF_X1;
    float* swq    = s + OFF_SWQ;
    float* swkv   = s + OFF_SWKV;
    float* swattn = s + OFF_SWATTN;
    float* x2     = s + OFF_X2;
    float* hbuf   = s + OFF_H;
    float* ffbuf  = s + OFF_FF;
    float* wcat   = s + OFF_H;            // reused before FFN
    float* bcat   = s + OFF_H + 524288;

    cudaFuncSetAttribute(self_attn_mma_kernel,
                         cudaFuncAttributeMaxDynamicSharedMemorySize, ATTN_SMEM);
    cudaFuncSetAttribute(sw_attn_mma_kernel,
                         cudaFuncAttributeMaxDynamicSharedMemorySize, ATTN_SMEM);

    // 0. concat KV weights, fused KV projection of memory
    concat_w_kernel<<<1024, 256>>>(sw_k_w, sw_k_b, sw_v_w, sw_v_b, wcat, bcat);
    gemm_tf32_kernel<<<dim3(8, 32), 256>>>(memory, wcat, bcat, swkv,
                                           NROWS, 1024, D_, 0);
    // 1. QKV projection
    gemm_tf32_kernel<<<dim3(12, 32), 256>>>(tgt, in_proj_w, in_proj_b, qkv,
                                            NROWS, 3 * D_, D_, 0);
    // 2. self attention
    self_attn_mma_kernel<<<dim3(8, 32), 256, ATTN_SMEM>>>(qkv, attn);
    // 3. out projection
    gemm_tf32_n64_kernel<<<dim3(8, 32), 256>>>(attn, out_proj_w, out_proj_b, proj,
                                               NROWS, D_, D_, 0);
    // 4. add + LN1
    add_ln_kernel<<<NROWS, 256>>>(tgt, proj, n1_g, n1_b, x1);
    // 5. sw q projection
    gemm_tf32_n64_kernel<<<dim3(8, 32), 256>>>(x1, sw_q_w, sw_q_b, swq, NROWS, D_, D_, 0);
    // 6. banded attention (tensor cores)
    sw_attn_mma_kernel<<<dim3(8, 32), 256, ATTN_SMEM>>>(swq, swkv, swattn);
    // 7. sw out projection
    gemm_tf32_n64_kernel<<<dim3(8, 32), 256>>>(swattn, sw_o_w, sw_o_b, proj, NROWS, D_, D_, 0);
    // 8. add + LN2
    add_ln_kernel<<<NROWS, 256>>>(x1, proj, n2_g, n2_b, x2);
    // 9. FFN up + ReLU
    gemm_tf32_kernel<<<dim3(16, 32), 256>>>(x2, lin1_w, lin1_b, hbuf, NROWS, DFF_, D_, 1);
    // 10. FFN down
    gemm_tf32_n64_kernel<<<dim3(8, 32), 256>>>(hbuf, lin2_w, lin2_b, ffbuf, NROWS, D_, DFF_, 0);
    // 11. add + LN3 -> output
    add_ln_kernel<<<NROWS, 256>>>(x2, ffbuf, n3_g, n3_b, out);
}

// round 7
// speedup vs baseline: 5.7557x; 1.6170x over previous
#include <cuda_runtime.h>
#include <cuda_fp16.h>
#include <math.h>

#define T_ 1024
#define S_ 1024
#define B_ 4
#define D_ 512
#define H_ 8
#define HD_ 64
#define DFF_ 2048
#define W_ 16
#define NROWS (T_ * B_)
#define SCALE_ 0.125f
#define EPS_ 1e-5f

// fp32 region (float offsets)
#define FOFF_PROJ   0
#define FOFF_X1     2097152
#define FOFF_X2     4194304
#define FOFF_FF     6291456
#define FOFF_BCAT   8388608
#define HALF_BASE_F 9000000   /* half region starts here (float units) */

// half region (half offsets)
#define HOFF_QKV    0
#define HOFF_ATTN   6291456
#define HOFF_SWQ    8388608
#define HOFF_SWKV   10485760
#define HOFF_SWATTN 14680064
#define HOFF_HBUF   16777216
#define HOFF_TGT    25165824
#define HOFF_MEM    27262976
#define HOFF_X1H    29360128
#define HOFF_X2H    31457280
#define HOFF_WIN    33554432
#define HOFF_WOUT   34340864
#define HOFF_WSWQ   34603008
#define HOFF_WSWKV  34865152
#define HOFF_WSWO   35389440
#define HOFF_WLIN1  35651584
#define HOFF_WLIN2  36700160

#define SCRATCH_FLOATS 33554432
__device__ float g_scratch[SCRATCH_FLOATS];

// ---------------------------------------------------------------------------
// PTX helpers
// ---------------------------------------------------------------------------
__device__ __forceinline__ void cp_async16(void* smem_ptr, const void* gmem_ptr) {
    unsigned saddr = (unsigned)__cvta_generic_to_shared(smem_ptr);
    asm volatile("cp.async.cg.shared.global [%0], [%1], 16;\n"
                 :: "r"(saddr), "l"(gmem_ptr));
}
__device__ __forceinline__ void cp_commit() {
    asm volatile("cp.async.commit_group;\n");
}
__device__ __forceinline__ void cp_wait0() {
    asm volatile("cp.async.wait_group 0;\n");
}
__device__ __forceinline__ void cp_wait1() {
    asm volatile("cp.async.wait_group 1;\n");
}
__device__ __forceinline__ void cp_wait2() {
    asm volatile("cp.async.wait_group 2;\n");
}
__device__ __forceinline__ void ldsm_x4h(unsigned& r0, unsigned& r1, unsigned& r2, unsigned& r3,
                                         const __half* p) {
    unsigned saddr = (unsigned)__cvta_generic_to_shared((void*)p);
    asm volatile("ldmatrix.sync.aligned.m8n8.x4.shared.b16 {%0,%1,%2,%3}, [%4];\n"
                 : "=r"(r0), "=r"(r1), "=r"(r2), "=r"(r3) : "r"(saddr));
}
__device__ __forceinline__ void ldsm_x4h_t(unsigned& r0, unsigned& r1, unsigned& r2, unsigned& r3,
                                           const __half* p) {
    unsigned saddr = (unsigned)__cvta_generic_to_shared((void*)p);
    asm volatile("ldmatrix.sync.aligned.m8n8.x4.trans.shared.b16 {%0,%1,%2,%3}, [%4];\n"
                 : "=r"(r0), "=r"(r1), "=r"(r2), "=r"(r3) : "r"(saddr));
}
__device__ __forceinline__ void mma_f16(float& c0, float& c1, float& c2, float& c3,
                                        unsigned a0, unsigned a1, unsigned a2, unsigned a3,
                                        unsigned b0, unsigned b1) {
    asm volatile("mma.sync.aligned.m16n8k16.row.col.f32.f16.f16.f32 "
                 "{%0,%1,%2,%3}, {%4,%5,%6,%7}, {%8,%9}, {%0,%1,%2,%3};\n"
                 : "+f"(c0), "+f"(c1), "+f"(c2), "+f"(c3)
                 : "r"(a0), "r"(a1), "r"(a2), "r"(a3), "r"(b0), "r"(b1));
}

#define BKH 32     // K per tile (halfs/elements)
#define STRH 40    // smem row stride in halfs (GEMM tiles; conflict-free)
#define NSTAGE 4

// ---------------------------------------------------------------------------
// fp32 -> fp16 elementwise convert (n multiple of 1024)
// ---------------------------------------------------------------------------
__global__ void __launch_bounds__(256) f2h_kernel(const float* __restrict__ src,
                                                  __half* __restrict__ dst, int n)
{
    int idx = (blockIdx.x * 256 + threadIdx.x) * 4;
    for (; idx < n; idx += gridDim.x * 1024) {
        float4 v = *reinterpret_cast<const float4*>(src + idx);
        __half2 h0 = __floats2half2_rn(v.x, v.y);
        __half2 h1 = __floats2half2_rn(v.z, v.w);
        *reinterpret_cast<__half2*>(dst + idx) = h0;
        *reinterpret_cast<__half2*>(dst + idx + 2) = h1;
    }
}

// concat K/V weights -> fp16 [1024,512], biases -> fp32 [1024]
__global__ void __launch_bounds__(256) concat_kv16_kernel(
    const float* __restrict__ kw, const float* __restrict__ kb,
    const float* __restrict__ vw, const float* __restrict__ vb,
    __half* __restrict__ wcat, float* __restrict__ bcat)
{
    int idx = blockIdx.x * 256 + threadIdx.x;   // 0..262143
    wcat[idx] = __float2half_rn(kw[idx]);
    wcat[262144 + idx] = __float2half_rn(vw[idx]);
    if (idx < 512) {
        bcat[idx] = kb[idx];
        bcat[512 + idx] = vb[idx];
    }
}

// ---------------------------------------------------------------------------
// FP16 GEMM 128x128: C = A[M,K] * W[N,K]^T + bias, optional relu, fp16/fp32 out
// ---------------------------------------------------------------------------
__global__ void __launch_bounds__(256, 2) gemm_f16_kernel(
    const __half* __restrict__ A, const __half* __restrict__ Wt,
    const float* __restrict__ bias, void* __restrict__ Cout,
    int M, int N, int K, int relu, int out16)
{
    __shared__ __align__(16) __half As[NSTAGE][128 * STRH];
    __shared__ __align__(16) __half Bs[NSTAGE][128 * STRH];

    const int tid  = threadIdx.x;
    const int wid  = tid >> 5;
    const int lane = tid & 31;
    const int wm   = (wid & 3) * 32;
    const int wn   = (wid >> 2) * 64;
    const int m0   = blockIdx.y * 128;
    const int n0   = blockIdx.x * 128;

    const int lrow = tid >> 2;        // 0..63
    const int lcol = (tid & 3) * 8;   // half offset within 32

    float acc[2][8][4];
#pragma unroll
    for (int i = 0; i < 2; ++i)
#pragma unroll
        for (int j = 0; j < 8; ++j)
#pragma unroll
            for (int q = 0; q < 4; ++q) acc[i][j][q] = 0.f;

    const int ntiles = K / BKH;
    const __half* Abase = A + (size_t)m0 * K;
    const __half* Bbase = Wt + (size_t)n0 * K;

#pragma unroll
    for (int s = 0; s < NSTAGE - 1; ++s) {
        int k0 = s * BKH;
#pragma unroll
        for (int p = 0; p < 2; ++p) {
            int r = lrow + p * 64;
            cp_async16(&As[s][r * STRH + lcol], Abase + (size_t)r * K + k0 + lcol);
            cp_async16(&Bs[s][r * STRH + lcol], Bbase + (size_t)r * K + k0 + lcol);
        }
        cp_commit();
    }

    const int a_row = wm + (lane & 15);
    const int a_koff = (lane >> 4) * 8;
    const int b_row_base = wn + (lane & 7) + ((lane >> 4) * 8);
    const int b_koff = ((lane >> 3) & 1) * 8;

    for (int t = 0; t < ntiles; ++t) {
        cp_wait2();
        __syncthreads();

        int ps = t + NSTAGE - 1;
        if (ps < ntiles) {
            int sb = ps & (NSTAGE - 1);
            int k0 = ps * BKH;
#pragma unroll
            for (int p = 0; p < 2; ++p) {
                int r = lrow + p * 64;
                cp_async16(&As[sb][r * STRH + lcol], Abase + (size_t)r * K + k0 + lcol);
                cp_async16(&Bs[sb][r * STRH + lcol], Bbase + (size_t)r * K + k0 + lcol);
            }
        }
        cp_commit();

        const int buf = t & (NSTAGE - 1);
#pragma unroll
        for (int ks = 0; ks < 2; ++ks) {
            unsigned a[2][4];
            unsigned b[8][2];
#pragma unroll
            for (int im = 0; im < 2; ++im)
                ldsm_x4h(a[im][0], a[im][1], a[im][2], a[im][3],
                         &As[buf][(a_row + im * 16) * STRH + ks * 16 + a_koff]);
#pragma unroll
            for (int ng = 0; ng < 4; ++ng) {
                unsigned r0, r1, r2, r3;
                ldsm_x4h(r0, r1, r2, r3,
                         &Bs[buf][(b_row_base + ng * 16) * STRH + ks * 16 + b_koff]);
                b[ng * 2][0] = r0; b[ng * 2][1] = r1;
                b[ng * 2 + 1][0] = r2; b[ng * 2 + 1][1] = r3;
            }
#pragma unroll
            for (int im = 0; im < 2; ++im)
#pragma unroll
                for (int in = 0; in < 8; ++in)
                    mma_f16(acc[im][in][0], acc[im][in][1], acc[im][in][2], acc[im][in][3],
                            a[im][0], a[im][1], a[im][2], a[im][3],
                            b[in][0], b[in][1]);
        }
    }

    const int row_base = m0 + wm + (lane >> 2);
    const int col_base = n0 + wn + (lane & 3) * 2;
#pragma unroll
    for (int im = 0; im < 2; ++im) {
#pragma unroll
        for (int in = 0; in < 8; ++in) {
            int col = col_base + in * 8;
            float b0 = bias[col], b1 = bias[col + 1];
            int r0 = row_base + im * 16;
            float v0 = acc[im][in][0] + b0;
            float v1 = acc[im][in][1] + b1;
            float v2 = acc[im][in][2] + b0;
            float v3 = acc[im][in][3] + b1;
            if (relu) {
                v0 = fmaxf(v0, 0.f); v1 = fmaxf(v1, 0.f);
                v2 = fmaxf(v2, 0.f); v3 = fmaxf(v3, 0.f);
            }
            if (out16) {
                __half* C = (__half*)Cout;
                *reinterpret_cast<__half2*>(&C[(size_t)r0 * N + col]) = __floats2half2_rn(v0, v1);
                *reinterpret_cast<__half2*>(&C[(size_t)(r0 + 8) * N + col]) = __floats2half2_rn(v2, v3);
            } else {
                float* C = (float*)Cout;
                C[(size_t)r0 * N + col] = v0;
                C[(size_t)r0 * N + col + 1] = v1;
                C[(size_t)(r0 + 8) * N + col] = v2;
                C[(size_t)(r0 + 8) * N + col + 1] = v3;
            }
        }
    }
}

// ---------------------------------------------------------------------------
// FP16 GEMM 128x64 (N=512 GEMMs), warp tile 32x32.
// ---------------------------------------------------------------------------
__global__ void __launch_bounds__(256, 2) gemm_f16_n64_kernel(
    const __half* __restrict__ A, const __half* __restrict__ Wt,
    const float* __restrict__ bias, void* __restrict__ Cout,
    int M, int N, int K, int relu, int out16)
{
    __shared__ __align__(16) __half As[NSTAGE][128 * STRH];
    __shared__ __align__(16) __half Bs[NSTAGE][64 * STRH];

    const int tid  = threadIdx.x;
    const int wid  = tid >> 5;
    const int lane = tid & 31;
    const int wm   = (wid & 3) * 32;
    const int wn   = (wid >> 2) * 32;
    const int m0   = blockIdx.y * 128;
    const int n0   = blockIdx.x * 64;

    const int lrow = tid >> 2;
    const int lcol = (tid & 3) * 8;

    float acc[2][4][4];
#pragma unroll
    for (int i = 0; i < 2; ++i)
#pragma unroll
        for (int j = 0; j < 4; ++j)
#pragma unroll
            for (int q = 0; q < 4; ++q) acc[i][j][q] = 0.f;

    const int ntiles = K / BKH;
    const __half* Abase = A + (size_t)m0 * K;
    const __half* Bbase = Wt + (size_t)n0 * K;

#pragma unroll
    for (int s = 0; s < NSTAGE - 1; ++s) {
        int k0 = s * BKH;
#pragma unroll
        for (int p = 0; p < 2; ++p) {
            int r = lrow + p * 64;
            cp_async16(&As[s][r * STRH + lcol], Abase + (size_t)r * K + k0 + lcol);
        }
        cp_async16(&Bs[s][lrow * STRH + lcol], Bbase + (size_t)lrow * K + k0 + lcol);
        cp_commit();
    }

    const int a_row = wm + (lane & 15);
    const int a_koff = (lane >> 4) * 8;
    const int b_row_base = wn + (lane & 7) + ((lane >> 4) * 8);
    const int b_koff = ((lane >> 3) & 1) * 8;

    for (int t = 0; t < ntiles; ++t) {
        cp_wait2();
        __syncthreads();

        int ps = t + NSTAGE - 1;
        if (ps < ntiles) {
            int sb = ps & (NSTAGE - 1);
            int k0 = ps * BKH;
#pragma unroll
            for (int p = 0; p < 2; ++p) {
                int r = lrow + p * 64;
                cp_async16(&As[sb][r * STRH + lcol], Abase + (size_t)r * K + k0 + lcol);
            }
            cp_async16(&Bs[sb][lrow * STRH + lcol], Bbase + (size_t)lrow * K + k0 + lcol);
        }
        cp_commit();

        const int buf = t & (NSTAGE - 1);
#pragma unroll
        for (int ks = 0; ks < 2; ++ks) {
            unsigned a[2][4];
            unsigned b[4][2];
#pragma unroll
            for (int im = 0; im < 2; ++im)
                ldsm_x4h(a[im][0], a[im][1], a[im][2], a[im][3],
                         &As[buf][(a_row + im * 16) * STRH + ks * 16 + a_koff]);
#pragma unroll
            for (int ng = 0; ng < 2; ++ng) {
                unsigned r0, r1, r2, r3;
                ldsm_x4h(r0, r1, r2, r3,
                         &Bs[buf][(b_row_base + ng * 16) * STRH + ks * 16 + b_koff]);
                b[ng * 2][0] = r0; b[ng * 2][1] = r1;
                b[ng * 2 + 1][0] = r2; b[ng * 2 + 1][1] = r3;
            }
#pragma unroll
            for (int im = 0; im < 2; ++im)
#pragma unroll
                for (int in = 0; in < 4; ++in)
                    mma_f16(acc[im][in][0], acc[im][in][1], acc[im][in][2], acc[im][in][3],
                            a[im][0], a[im][1], a[im][2], a[im][3],
                            b[in][0], b[in][1]);
        }
    }

    const int row_base = m0 + wm + (lane >> 2);
    const int col_base = n0 + wn + (lane & 3) * 2;
#pragma unroll
    for (int im = 0; im < 2; ++im) {
#pragma unroll
        for (int in = 0; in < 4; ++in) {
            int col = col_base + in * 8;
            float b0 = bias[col], b1 = bias[col + 1];
            int r0 = row_base + im * 16;
            float v0 = acc[im][in][0] + b0;
            float v1 = acc[im][in][1] + b1;
            float v2 = acc[im][in][2] + b0;
            float v3 = acc[im][in][3] + b1;
            if (relu) {
                v0 = fmaxf(v0, 0.f); v1 = fmaxf(v1, 0.f);
                v2 = fmaxf(v2, 0.f); v3 = fmaxf(v3, 0.f);
            }
            if (out16) {
                __half* C = (__half*)Cout;
                *reinterpret_cast<__half2*>(&C[(size_t)r0 * N + col]) = __floats2half2_rn(v0, v1);
                *reinterpret_cast<__half2*>(&C[(size_t)(r0 + 8) * N + col]) = __floats2half2_rn(v2, v3);
            } else {
                float* C = (float*)Cout;
                C[(size_t)r0 * N + col] = v0;
                C[(size_t)r0 * N + col + 1] = v1;
                C[(size_t)(r0 + 8) * N + col] = v2;
                C[(size_t)(r0 + 8) * N + col + 1] = v3;
            }
        }
    }
}

// ---------------------------------------------------------------------------
// FP16 flash self-attention. 128 q rows x 256 threads, 16 key tiles of 64.
// K and V both row-major in smem (V consumed via ldsm.trans).
// smem halfs: Ps[128*72] | Ks[2][64*72] | Vs[2][64*72]
// ---------------------------------------------------------------------------
#define ASTRH 72
#define KBUFH (64 * ASTRH)
#define ROWH 6144

__global__ void __launch_bounds__(256, 2) self_attn_f16_kernel(
    const __half* __restrict__ qkv, __half* __restrict__ out)
{
    extern __shared__ __half smh[];
    __half* Ps = smh;
    __half* Ks = smh + 128 * ASTRH;
    __half* Vs = Ks + 2 * KBUFH;

    const int tid = threadIdx.x;
    const int wid = tid >> 5;
    const int lane = tid & 31;
    const int b = blockIdx.y >> 3;
    const int h = blockIdx.y & 7;
    const int t0 = blockIdx.x * 128;
    const int wm = wid * 16;

    const __half* qbase = qkv + ((size_t)t0 * B_ + b) * 1536 + h * 64;
    const __half* kroot = qkv + (size_t)b * 1536 + 512 + h * 64;
    const __half* vroot = qkv + (size_t)b * 1536 + 1024 + h * 64;

    // loaders: Q 128x64 halfs (4 chunks/thread); K,V 64x64 (2 chunks/thread each)
#pragma unroll
    for (int i = 0; i < 4; ++i) {
        int idx = i * 256 + tid;
        int r = idx >> 3, c = (idx & 7) * 8;
        cp_async16(&Ps[r * ASTRH + c], qbase + (size_t)r * ROWH + c);
    }
#pragma unroll
    for (int i = 0; i < 2; ++i) {
        int idx = i * 256 + tid;
        int r = idx >> 3, c = (idx & 7) * 8;
        cp_async16(&Ks[r * ASTRH + c], kroot + (size_t)r * ROWH + c);
        cp_async16(&Vs[r * ASTRH + c], vroot + (size_t)r * ROWH + c);
    }
    cp_commit();
    cp_wait0();
    __syncthreads();

    // Q fragments (4 ksubs of k16), pre-scaled by SCALE_
    unsigned qf[4][4];
    {
        const __half2 sc2 = __float2half2_rn(SCALE_);
        const int qrow = wm + (lane & 15);
        const int qko = (lane >> 4) * 8;
#pragma unroll
        for (int ks = 0; ks < 4; ++ks) {
            unsigned r0, r1, r2, r3;
            ldsm_x4h(r0, r1, r2, r3, &Ps[qrow * ASTRH + ks * 16 + qko]);
            unsigned rr[4] = {r0, r1, r2, r3};
#pragma unroll
            for (int j = 0; j < 4; ++j) {
                __half2 v = *reinterpret_cast<__half2*>(&rr[j]);
                v = __hmul2(v, sc2);
                qf[ks][j] = *reinterpret_cast<unsigned*>(&v);
            }
        }
    }
    __syncthreads();   // Ps now reusable for P

    float o[8][4];
#pragma unroll
    for (int n = 0; n < 8; ++n)
#pragma unroll
        for (int c = 0; c < 4; ++c) o[n][c] = 0.f;
    float m0 = -1e30f, m1 = -1e30f, l0 = 0.f, l1 = 0.f;

    const int brow_base = (lane & 7) + ((lane >> 4) * 8);
    const int bko = ((lane >> 3) & 1) * 8;
    const int prow0 = wm + (lane >> 2);
    const int pcol = 2 * (lane & 3);
    const int a_row = wm + (lane & 15);
    const int a_koff = (lane >> 4) * 8;
    const int v_row = lane & 15;
    const int v_coff = (lane >> 4) * 8;

    for (int kt = 0; kt < 16; ++kt) {
        const int buf = kt & 1;

        if (kt + 1 < 16) {
            const __half* kb = kroot + (size_t)(kt + 1) * 64 * ROWH;
            const __half* vb = vroot + (size_t)(kt + 1) * 64 * ROWH;
            __half* kd = Ks + (buf ^ 1) * KBUFH;
            __half* vd = Vs + (buf ^ 1) * KBUFH;
#pragma unroll
            for (int i = 0; i < 2; ++i) {
                int idx = i * 256 + tid;
                int r = idx >> 3, c = (idx & 7) * 8;
                cp_async16(&kd[r * ASTRH + c], kb + (size_t)r * ROWH + c);
                cp_async16(&vd[r * ASTRH + c], vb + (size_t)r * ROWH + c);
            }
            cp_commit();
            cp_wait1();
        } else {
            cp_wait0();
        }
        __syncthreads();

        // S = Q K^T
        const __half* Kb = Ks + buf * KBUFH;
        float s[8][4];
#pragma unroll
        for (int n = 0; n < 8; ++n)
#pragma unroll
            for (int c = 0; c < 4; ++c) s[n][c] = 0.f;
#pragma unroll
        for (int ks = 0; ks < 4; ++ks) {
#pragma unroll
            for (int ng = 0; ng < 4; ++ng) {
                unsigned r0, r1, r2, r3;
                ldsm_x4h(r0, r1, r2, r3, &Kb[(brow_base + ng * 16) * ASTRH + ks * 16 + bko]);
                mma_f16(s[ng * 2][0], s[ng * 2][1], s[ng * 2][2], s[ng * 2][3],
                        qf[ks][0], qf[ks][1], qf[ks][2], qf[ks][3], r0, r1);
                mma_f16(s[ng * 2 + 1][0], s[ng * 2 + 1][1], s[ng * 2 + 1][2], s[ng * 2 + 1][3],
                        qf[ks][0], qf[ks][1], qf[ks][2], qf[ks][3], r2, r3);
            }
        }

        // online softmax
        float mx0 = -1e30f, mx1 = -1e30f;
#pragma unroll
        for (int n = 0; n < 8; ++n) {
            mx0 = fmaxf(mx0, fmaxf(s[n][0], s[n][1]));
            mx1 = fmaxf(mx1, fmaxf(s[n][2], s[n][3]));
        }
        mx0 = fmaxf(mx0, __shfl_xor_sync(0xffffffffu, mx0, 1));
        mx0 = fmaxf(mx0, __shfl_xor_sync(0xffffffffu, mx0, 2));
        mx1 = fmaxf(mx1, __shfl_xor_sync(0xffffffffu, mx1, 1));
        mx1 = fmaxf(mx1, __shfl_xor_sync(0xffffffffu, mx1, 2));

        float mn0 = fmaxf(m0, mx0), mn1 = fmaxf(m1, mx1);
        float corr0 = __expf(m0 - mn0), corr1 = __expf(m1 - mn1);
        m0 = mn0; m1 = mn1;
        l0 *= corr0; l1 *= corr1;
#pragma unroll
        for (int n = 0; n < 8; ++n) {
            o[n][0] *= corr0; o[n][1] *= corr0;
            o[n][2] *= corr1; o[n][3] *= corr1;
        }
#pragma unroll
        for (int n = 0; n < 8; ++n) {
            float p0 = __expf(s[n][0] - mn0);
            float p1 = __expf(s[n][1] - mn0);
            float p2 = __expf(s[n][2] - mn1);
            float p3 = __expf(s[n][3] - mn1);
            l0 += p0 + p1; l1 += p2 + p3;
            *reinterpret_cast<__half2*>(&Ps[prow0 * ASTRH + n * 8 + pcol]) = __floats2half2_rn(p0, p1);
            *reinterpret_cast<__half2*>(&Ps[(prow0 + 8) * ASTRH + n * 8 + pcol]) = __floats2half2_rn(p2, p3);
        }
        __syncwarp();

        // O += P V (V row-major, trans ldsm)
        const __half* Vb = Vs + buf * KBUFH;
#pragma unroll
        for (int ks = 0; ks < 4; ++ks) {
            unsigned a0, a1, a2, a3;
            ldsm_x4h(a0, a1, a2, a3, &Ps[a_row * ASTRH + ks * 16 + a_koff]);
#pragma unroll
            for (int ng = 0; ng < 4; ++ng) {
                unsigned r0, r1, r2, r3;
                ldsm_x4h_t(r0, r1, r2, r3,
                           &Vb[(ks * 16 + v_row) * ASTRH + ng * 16 + v_coff]);
                mma_f16(o[ng * 2][0], o[ng * 2][1], o[ng * 2][2], o[ng * 2][3],
                        a0, a1, a2, a3, r0, r1);
                mma_f16(o[ng * 2 + 1][0], o[ng * 2 + 1][1], o[ng * 2 + 1][2], o[ng * 2 + 1][3],
                        a0, a1, a2, a3, r2, r3);
            }
        }
        __syncthreads();
    }

    l0 += __shfl_xor_sync(0xffffffffu, l0, 1);
    l0 += __shfl_xor_sync(0xffffffffu, l0, 2);
    l1 += __shfl_xor_sync(0xffffffffu, l1, 1);
    l1 += __shfl_xor_sync(0xffffffffu, l1, 2);
    float inv0 = 1.f / l0, inv1 = 1.f / l1;

    __half* ob0 = out + ((size_t)(t0 + prow0) * B_ + b) * D_ + h * 64 + pcol;
    __half* ob1 = out + ((size_t)(t0 + prow0 + 8) * B_ + b) * D_ + h * 64 + pcol;
#pragma unroll
    for (int n = 0; n < 8; ++n) {
        *reinterpret_cast<__half2*>(ob0 + n * 8) = __floats2half2_rn(o[n][0] * inv0, o[n][1] * inv0);
        *reinterpret_cast<__half2*>(ob1 + n * 8) = __floats2half2_rn(o[n][2] * inv1, o[n][3] * inv1);
    }
}

#define ATTN_SMEM ((128 + 4 * 64) * ASTRH * 2)   // halfs * 2 bytes

// ---------------------------------------------------------------------------
// FP16 banded sliding-window attention. 3 key tiles (keys t0-16 .. t0+175).
// ---------------------------------------------------------------------------
__global__ void __launch_bounds__(256, 2) sw_attn_f16_kernel(
    const __half* __restrict__ q, const __half* __restrict__ kv,
    __half* __restrict__ out)
{
    extern __shared__ __half smh[];
    __half* Ps = smh;
    __half* Ks = smh + 128 * ASTRH;
    __half* Vs = Ks + 2 * KBUFH;

    const int tid = threadIdx.x;
    const int wid = tid >> 5;
    const int lane = tid & 31;
    const int b = blockIdx.y >> 3;
    const int h = blockIdx.y & 7;
    const int t0 = blockIdx.x * 128;
    const int wm = wid * 16;

#pragma unroll
    for (int i = 0; i < 4; ++i) {
        int idx = i * 256 + tid;
        int r = idx >> 3, c = (idx & 7) * 8;
        cp_async16(&Ps[r * ASTRH + c],
                   q + ((size_t)(t0 + r) * B_ + b) * D_ + h * 64 + c);
    }
    {
        int key0 = t0 - 16;
#pragma unroll
        for (int i = 0; i < 2; ++i) {
            int idx = i * 256 + tid;
            int r = idx >> 3, c = (idx & 7) * 8;
            int key = min(max(key0 + r, 0), S_ - 1);
            const __half* base = kv + ((size_t)key * B_ + b) * 1024 + h * 64;
            cp_async16(&Ks[r * ASTRH + c], base + c);
            cp_async16(&Vs[r * ASTRH + c], base + 512 + c);
        }
    }
    cp_commit();
    cp_wait0();
    __syncthreads();

    unsigned qf[4][4];
    {
        const __half2 sc2 = __float2half2_rn(SCALE_);
        const int qrow = wm + (lane & 15);
        const int qko = (lane >> 4) * 8;
#pragma unroll
        for (int ks = 0; ks < 4; ++ks) {
            unsigned r0, r1, r2, r3;
            ldsm_x4h(r0, r1, r2, r3, &Ps[qrow * ASTRH + ks * 16 + qko]);
            unsigned rr[4] = {r0, r1, r2, r3};
#pragma unroll
            for (int j = 0; j < 4; ++j) {
                __half2 v = *reinterpret_cast<__half2*>(&rr[j]);
                v = __hmul2(v, sc2);
                qf[ks][j] = *reinterpret_cast<unsigned*>(&v);
            }
        }
    }
    __syncthreads();

    float o[8][4];
#pragma unroll
    for (int n = 0; n < 8; ++n)
#pragma unroll
        for (int c = 0; c < 4; ++c) o[n][c] = 0.f;
    float m0 = -1e30f, m1 = -1e30f, l0 = 0.f, l1 = 0.f;

    const int brow_base = (lane & 7) + ((lane >> 4) * 8);
    const int bko = ((lane >> 3) & 1) * 8;
    const int prow0 = wm + (lane >> 2);
    const int pcol = 2 * (lane & 3);
    const int a_row = wm + (lane & 15);
    const int a_koff = (lane >> 4) * 8;
    const int v_row = lane & 15;
    const int v_coff = (lane >> 4) * 8;

    for (int kt = 0; kt < 3; ++kt) {
        const int buf = kt & 1;
        const int key0 = t0 - 16 + kt * 64;

        if (kt + 1 < 3) {
            int nk0 = t0 - 16 + (kt + 1) * 64;
            __half* kd = Ks + (buf ^ 1) * KBUFH;
            __half* vd = Vs + (buf ^ 1) * KBUFH;
#pragma unroll
            for (int i = 0; i < 2; ++i) {
                int idx = i * 256 + tid;
                int r = idx >> 3, c = (idx & 7) * 8;
                int key = min(max(nk0 + r, 0), S_ - 1);
                const __half* base = kv + ((size_t)key * B_ + b) * 1024 + h * 64;
                cp_async16(&kd[r * ASTRH + c], base + c);
                cp_async16(&vd[r * ASTRH + c], base + 512 + c);
            }
            cp_commit();
            cp_wait1();
        } else {
            cp_wait0();
        }
        __syncthreads();

        const __half* Kb = Ks + buf * KBUFH;
        float s[8][4];
#pragma unroll
        for (int n = 0; n < 8; ++n)
#pragma unroll
            for (int c = 0; c < 4; ++c) s[n][c] = 0.f;
#pragma unroll
        for (int ks = 0; ks < 4; ++ks) {
#pragma unroll
            for (int ng = 0; ng < 4; ++ng) {
                unsigned r0, r1, r2, r3;
                ldsm_x4h(r0, r1, r2, r3, &Kb[(brow_base + ng * 16) * ASTRH + ks * 16 + bko]);
                mma_f16(s[ng * 2][0], s[ng * 2][1], s[ng * 2][2], s[ng * 2][3],
                        qf[ks][0], qf[ks][1], qf[ks][2], qf[ks][3], r0, r1);
                mma_f16(s[ng * 2 + 1][0], s[ng * 2 + 1][1], s[ng * 2 + 1][2], s[ng * 2 + 1][3],
                        qf[ks][0], qf[ks][1], qf[ks][2], qf[ks][3], r2, r3);
            }
        }

        // band mask
#pragma unroll
        for (int n = 0; n < 8; ++n) {
#pragma unroll
            for (int c = 0; c < 4; ++c) {
                int key = key0 + n * 8 + pcol + (c & 1);
                int qg = t0 + prow0 + ((c >> 1) * 8);
                bool valid = (key >= 0) && (key < S_) && (key - qg <= W_) && (qg - key <= W_);
                if (!valid) s[n][c] = -1e38f;
            }
        }

        float mx0 = -1e30f, mx1 = -1e30f;
#pragma unroll
        for (int n = 0; n < 8; ++n) {
            mx0 = fmaxf(mx0, fmaxf(s[n][0], s[n][1]));
            mx1 = fmaxf(mx1, fmaxf(s[n][2], s[n][3]));
        }
        mx0 = fmaxf(mx0, __shfl_xor_sync(0xffffffffu, mx0, 1));
        mx0 = fmaxf(mx0, __shfl_xor_sync(0xffffffffu, mx0, 2));
        mx1 = fmaxf(mx1, __shfl_xor_sync(0xffffffffu, mx1, 1));
        mx1 = fmaxf(mx1, __shfl_xor_sync(0xffffffffu, mx1, 2));

        float mn0 = fmaxf(m0, mx0), mn1 = fmaxf(m1, mx1);
        float corr0 = __expf(m0 - mn0), corr1 = __expf(m1 - mn1);
        m0 = mn0; m1 = mn1;
        l0 *= corr0; l1 *= corr1;
#pragma unroll
        for (int n = 0; n < 8; ++n) {
            o[n][0] *= corr0; o[n][1] *= corr0;
            o[n][2] *= corr1; o[n][3] *= corr1;
        }
#pragma unroll
        for (int n = 0; n < 8; ++n) {
            float p0 = __expf(s[n][0] - mn0);
            float p1 = __expf(s[n][1] - mn0);
            float p2 = __expf(s[n][2] - mn1);
            float p3 = __expf(s[n][3] - mn1);
            l0 += p0 + p1; l1 += p2 + p3;
            *reinterpret_cast<__half2*>(&Ps[prow0 * ASTRH + n * 8 + pcol]) = __floats2half2_rn(p0, p1);
            *reinterpret_cast<__half2*>(&Ps[(prow0 + 8) * ASTRH + n * 8 + pcol]) = __floats2half2_rn(p2, p3);
        }
        __syncwarp();

        const __half* Vb = Vs + buf * KBUFH;
#pragma unroll
        for (int ks = 0; ks < 4; ++ks) {
            unsigned a0, a1, a2, a3;
            ldsm_x4h(a0, a1, a2, a3, &Ps[a_row * ASTRH + ks * 16 + a_koff]);
#pragma unroll
            for (int ng = 0; ng < 4; ++ng) {
                unsigned r0, r1, r2, r3;
                ldsm_x4h_t(r0, r1, r2, r3,
                           &Vb[(ks * 16 + v_row) * ASTRH + ng * 16 + v_coff]);
                mma_f16(o[ng * 2][0], o[ng * 2][1], o[ng * 2][2], o[ng * 2][3],
                        a0, a1, a2, a3, r0, r1);
                mma_f16(o[ng * 2 + 1][0], o[ng * 2 + 1][1], o[ng * 2 + 1][2], o[ng * 2 + 1][3],
                        a0, a1, a2, a3, r2, r3);
            }
        }
        __syncthreads();
    }

    l0 += __shfl_xor_sync(0xffffffffu, l0, 1);
    l0 += __shfl_xor_sync(0xffffffffu, l0, 2);
    l1 += __shfl_xor_sync(0xffffffffu, l1, 1);
    l1 += __shfl_xor_sync(0xffffffffu, l1, 2);
    float inv0 = 1.f / l0, inv1 = 1.f / l1;

    __half* ob0 = out + ((size_t)(t0 + prow0) * B_ + b) * D_ + h * 64 + pcol;
    __half* ob1 = out + ((size_t)(t0 + prow0 + 8) * B_ + b) * D_ + h * 64 + pcol;
#pragma unroll
    for (int n = 0; n < 8; ++n) {
        *reinterpret_cast<__half2*>(ob0 + n * 8) = __floats2half2_rn(o[n][0] * inv0, o[n][1] * inv0);
        *reinterpret_cast<__half2*>(ob1 + n * 8) = __floats2half2_rn(o[n][2] * inv1, o[n][3] * inv1);
    }
}

// ---------------------------------------------------------------------------
// Fused residual-add + LayerNorm; fp32 out + optional fp16 out.
// ---------------------------------------------------------------------------
__global__ void __launch_bounds__(256) add_ln_kernel(
    const float* __restrict__ x, const float* __restrict__ y,
    const float* __restrict__ g, const float* __restrict__ beta,
    float* __restrict__ out, __half* __restrict__ out16)
{
    __shared__ float sh[33];
    const int row = blockIdx.x;
    const int tid = threadIdx.x;
    const size_t base = (size_t)row * D_;

    float v0 = x[base + tid] + y[base + tid];
    float v1 = x[base + tid + 256] + y[base + tid + 256];

    float s = v0 + v1;
#pragma unroll
    for (int o = 16; o > 0; o >>= 1) s += __shfl_xor_sync(0xffffffffu, s, o);
    int lane = tid & 31, wid = tid >> 5;
    if (lane == 0) sh[wid] = s;
    __syncthreads();
    if (wid == 0) {
        float t = (lane < 8) ? sh[lane] : 0.f;
#pragma unroll
        for (int o = 4; o > 0; o >>= 1) t += __shfl_xor_sync(0xffffffffu, t, o);
        if (lane == 0) sh[32] = t;
    }
    __syncthreads();
    float mean = sh[32] * (1.f / D_);
    __syncthreads();

    float d0 = v0 - mean, d1 = v1 - mean;
    float sq = d0 * d0 + d1 * d1;
#pragma unroll
    for (int o = 16; o > 0; o >>= 1) sq += __shfl_xor_sync(0xffffffffu, sq, o);
    if (lane == 0) sh[wid] = sq;
    __syncthreads();
    if (wid == 0) {
        float t = (lane < 8) ? sh[lane] : 0.f;
#pragma unroll
        for (int o = 4; o > 0; o >>= 1) t += __shfl_xor_sync(0xffffffffu, t, o);
        if (lane == 0) sh[32] = t;
    }
    __syncthreads();
    float rstd = rsqrtf(sh[32] * (1.f / D_) + EPS_);

    float r0 = d0 * rstd * g[tid] + beta[tid];
    float r1 = d1 * rstd * g[tid + 256] + beta[tid + 256];
    out[base + tid] = r0;
    out[base + tid + 256] = r1;
    if (out16) {
        out16[base + tid] = __float2half_rn(r0);
        out16[base + tid + 256] = __float2half_rn(r1);
    }
}

// ---------------------------------------------------------------------------
// Launch
// ---------------------------------------------------------------------------
extern "C" void kernel_launch(void* const* d_in, const int* in_sizes, int n_in,
                              void* d_out, int out_size)
{
    (void)in_sizes; (void)n_in; (void)out_size;
    const float* tgt        = (const float*)d_in[0];
    const float* memory     = (const float*)d_in[1];
    const float* in_proj_w  = (const float*)d_in[2];
    const float* in_proj_b  = (const float*)d_in[3];
    const float* out_proj_w = (const float*)d_in[4];
    const float* out_proj_b = (const float*)d_in[5];
    const float* sw_q_w = (const float*)d_in[6];
    const float* sw_q_b = (const float*)d_in[7];
    const float* sw_k_w = (const float*)d_in[8];
    const float* sw_k_b = (const float*)d_in[9];
    const float* sw_v_w = (const float*)d_in[10];
    const float* sw_v_b = (const float*)d_in[11];
    const float* sw_o_w = (const float*)d_in[12];
    const float* sw_o_b = (const float*)d_in[13];
    const float* lin1_w = (const float*)d_in[14];
    const float* lin1_b = (const float*)d_in[15];
    const float* lin2_w = (const float*)d_in[16];
    const float* lin2_b = (const float*)d_in[17];
    const float* n1_g = (const float*)d_in[18];
    const float* n1_b = (const float*)d_in[19];
    const float* n2_g = (const float*)d_in[20];
    const float* n2_b = (const float*)d_in[21];
    const float* n3_g = (const float*)d_in[22];
    const float* n3_b = (const float*)d_in[23];
    float* out = (float*)d_out;

    float* s = nullptr;
    cudaGetSymbolAddress((void**)&s, g_scratch);
    float* proj  = s + FOFF_PROJ;
    float* x1    = s + FOFF_X1;
    float* x2    = s + FOFF_X2;
    float* ffbuf = s + FOFF_FF;
    float* bcat  = s + FOFF_BCAT;
    __half* hb = (__half*)(s + HALF_BASE_F);
    __half* qkv16    = hb + HOFF_QKV;
    __half* attn16   = hb + HOFF_ATTN;
    __half* swq16    = hb + HOFF_SWQ;
    __half* swkv16   = hb + HOFF_SWKV;
    __half* swattn16 = hb + HOFF_SWATTN;
    __half* hbuf16   = hb + HOFF_HBUF;
    __half* tgt16    = hb + HOFF_TGT;
    __half* mem16    = hb + HOFF_MEM;
    __half* x1h      = hb + HOFF_X1H;
    __half* x2h      = hb + HOFF_X2H;
    __half* w_in     = hb + HOFF_WIN;
    __half* w_out    = hb + HOFF_WOUT;
    __half* w_swq    = hb + HOFF_WSWQ;
    __half* w_swkv   = hb + HOFF_WSWKV;
    __half* w_swo    = hb + HOFF_WSWO;
    __half* w_lin1   = hb + HOFF_WLIN1;
    __half* w_lin2   = hb + HOFF_WLIN2;

    cudaFuncSetAttribute(self_attn_f16_kernel,
                         cudaFuncAttributeMaxDynamicSharedMemorySize, ATTN_SMEM);
    cudaFuncSetAttribute(sw_attn_f16_kernel,
                         cudaFuncAttributeMaxDynamicSharedMemorySize, ATTN_SMEM);

    // converts
    f2h_kernel<<<512, 256>>>(tgt, tgt16, T_ * B_ * D_);
    f2h_kernel<<<512, 256>>>(memory, mem16, S_ * B_ * D_);
    f2h_kernel<<<256, 256>>>(in_proj_w, w_in, 3 * D_ * D_);
    f2h_kernel<<<128, 256>>>(out_proj_w, w_out, D_ * D_);
    f2h_kernel<<<128, 256>>>(sw_q_w, w_swq, D_ * D_);
    f2h_kernel<<<128, 256>>>(sw_o_w, w_swo, D_ * D_);
    f2h_kernel<<<256, 256>>>(lin1_w, w_lin1, DFF_ * D_);
    f2h_kernel<<<256, 256>>>(lin2_w, w_lin2, D_ * DFF_);
    concat_kv16_kernel<<<1024, 256>>>(sw_k_w, sw_k_b, sw_v_w, sw_v_b, w_swkv, bcat);

    // fused KV projection of memory -> swkv16 [T,B,1024]
    gemm_f16_kernel<<<dim3(8, 32), 256>>>(mem16, w_swkv, bcat, swkv16,
                                          NROWS, 1024, D_, 0, 1);
    // QKV projection
    gemm_f16_kernel<<<dim3(12, 32), 256>>>(tgt16, w_in, in_proj_b, qkv16,
                                           NROWS, 3 * D_, D_, 0, 1);
    // self attention
    self_attn_f16_kernel<<<dim3(8, 32), 256, ATTN_SMEM>>>(qkv16, attn16);
    // out projection -> fp32
    gemm_f16_n64_kernel<<<dim3(8, 32), 256>>>(attn16, w_out, out_proj_b, proj,
                                              NROWS, D_, D_, 0, 0);
    // add + LN1
    add_ln_kernel<<<NROWS, 256>>>(tgt, proj, n1_g, n1_b, x1, x1h);
    // sw q projection
    gemm_f16_n64_kernel<<<dim3(8, 32), 256>>>(x1h, w_swq, sw_q_b, swq16,
                                              NROWS, D_, D_, 0, 1);
    // banded attention
    sw_attn_f16_kernel<<<dim3(8, 32), 256, ATTN_SMEM>>>(swq16, swkv16, swattn16);
    // sw out projection -> fp32
    gemm_f16_n64_kernel<<<dim3(8, 32), 256>>>(swattn16, w_swo, sw_o_b, proj,
                                              NROWS, D_, D_, 0, 0);
    // add + LN2
    add_ln_kernel<<<NROWS, 256>>>(x1, proj, n2_g, n2_b, x2, x2h);
    // FFN up + ReLU -> fp16
    gemm_f16_kernel<<<dim3(16, 32), 256>>>(x2h, w_lin1, lin1_b, hbuf16,
                                           NROWS, DFF_, D_, 1, 1);
    // FFN down -> fp32
    gemm_f16_n64_kernel<<<dim3(8, 32), 256>>>(hbuf16, w_lin2, lin2_b, ffbuf,
                                              NROWS, D_, DFF_, 0, 0);
    // add + LN3 -> output
    add_ln_kernel<<<NROWS, 256>>>(x2, ffbuf, n3_g, n3_b, out, nullptr);
}

// round 8
// speedup vs baseline: 6.3294x; 1.0997x over previous
#include <cuda_runtime.h>
#include <cuda_fp16.h>
#include <math.h>

#define T_ 1024
#define S_ 1024
#define B_ 4
#define D_ 512
#define H_ 8
#define HD_ 64
#define DFF_ 2048
#define W_ 16
#define NROWS (T_ * B_)
#define SCALE_ 0.125f
#define EPS_ 1e-5f

// fp32 region (float offsets)
#define FOFF_X1     0
#define FOFF_X2     2097152
#define FOFF_FF     4194304
#define FOFF_BCAT   6291456
#define HALF_BASE_F 7000000

// half region (half offsets)
#define HOFF_QKV    0
#define HOFF_ATTN   6291456
#define HOFF_SWQ    8388608
#define HOFF_SWKV   10485760
#define HOFF_SWATTN 14680064
#define HOFF_HBUF   16777216
#define HOFF_TGT    25165824
#define HOFF_MEM    27262976
#define HOFF_X1H    29360128
#define HOFF_X2H    31457280
#define HOFF_WIN    33554432
#define HOFF_WOUT   34340864
#define HOFF_WSWQ   34603008
#define HOFF_WSWKV  34865152
#define HOFF_WSWO   35389440
#define HOFF_WLIN1  35651584
#define HOFF_WLIN2  36700160
#define HOFF_PROJ16 37748736
#define HOFF_FF16   39845888

#define SCRATCH_FLOATS 33554432
__device__ float g_scratch[SCRATCH_FLOATS];

// ---------------------------------------------------------------------------
// PTX helpers
// ---------------------------------------------------------------------------
__device__ __forceinline__ void cp_async16(void* smem_ptr, const void* gmem_ptr) {
    unsigned saddr = (unsigned)__cvta_generic_to_shared(smem_ptr);
    asm volatile("cp.async.cg.shared.global [%0], [%1], 16;\n"
                 :: "r"(saddr), "l"(gmem_ptr));
}
__device__ __forceinline__ void cp_commit() {
    asm volatile("cp.async.commit_group;\n");
}
__device__ __forceinline__ void cp_wait0() {
    asm volatile("cp.async.wait_group 0;\n");
}
__device__ __forceinline__ void cp_wait1() {
    asm volatile("cp.async.wait_group 1;\n");
}
__device__ __forceinline__ void cp_wait2() {
    asm volatile("cp.async.wait_group 2;\n");
}
__device__ __forceinline__ void ldsm_x4h(unsigned& r0, unsigned& r1, unsigned& r2, unsigned& r3,
                                         const __half* p) {
    unsigned saddr = (unsigned)__cvta_generic_to_shared((void*)p);
    asm volatile("ldmatrix.sync.aligned.m8n8.x4.shared.b16 {%0,%1,%2,%3}, [%4];\n"
                 : "=r"(r0), "=r"(r1), "=r"(r2), "=r"(r3) : "r"(saddr));
}
__device__ __forceinline__ void ldsm_x4h_t(unsigned& r0, unsigned& r1, unsigned& r2, unsigned& r3,
                                           const __half* p) {
    unsigned saddr = (unsigned)__cvta_generic_to_shared((void*)p);
    asm volatile("ldmatrix.sync.aligned.m8n8.x4.trans.shared.b16 {%0,%1,%2,%3}, [%4];\n"
                 : "=r"(r0), "=r"(r1), "=r"(r2), "=r"(r3) : "r"(saddr));
}
__device__ __forceinline__ void mma_f16(float& c0, float& c1, float& c2, float& c3,
                                        unsigned a0, unsigned a1, unsigned a2, unsigned a3,
                                        unsigned b0, unsigned b1) {
    asm volatile("mma.sync.aligned.m16n8k16.row.col.f32.f16.f16.f32 "
                 "{%0,%1,%2,%3}, {%4,%5,%6,%7}, {%8,%9}, {%0,%1,%2,%3};\n"
                 : "+f"(c0), "+f"(c1), "+f"(c2), "+f"(c3)
                 : "r"(a0), "r"(a1), "r"(a2), "r"(a3), "r"(b0), "r"(b1));
}

#define BKH 32
#define STRH 40
#define NSTAGE 4

// ---------------------------------------------------------------------------
// One fused fp32->fp16 convert over all 8 tensors (compile-time segment map).
// Segment sizes (floats): 2097152,2097152,786432,262144,262144,262144,1048576,1048576
// ---------------------------------------------------------------------------
__global__ void __launch_bounds__(256) f2h_multi_kernel(
    const float* __restrict__ s0, __half* __restrict__ d0,
    const float* __restrict__ s1, __half* __restrict__ d1,
    const float* __restrict__ s2, __half* __restrict__ d2,
    const float* __restrict__ s3, __half* __restrict__ d3,
    const float* __restrict__ s4, __half* __restrict__ d4,
    const float* __restrict__ s5, __half* __restrict__ d5,
    const float* __restrict__ s6, __half* __restrict__ d6,
    const float* __restrict__ s7, __half* __restrict__ d7)
{
    int idx = (blockIdx.x * 256 + threadIdx.x) * 4;
    const float* src; __half* dst; int off;
    if      (idx < 2097152) { src = s0; dst = d0; off = idx; }
    else if (idx < 4194304) { src = s1; dst = d1; off = idx - 2097152; }
    else if (idx < 4980736) { src = s2; dst = d2; off = idx - 4194304; }
    else if (idx < 5242880) { src = s3; dst = d3; off = idx - 4980736; }
    else if (idx < 5505024) { src = s4; dst = d4; off = idx - 5242880; }
    else if (idx < 5767168) { src = s5; dst = d5; off = idx - 5505024; }
    else if (idx < 6815744) { src = s6; dst = d6; off = idx - 5767168; }
    else                    { src = s7; dst = d7; off = idx - 6815744; }
    float4 v = *reinterpret_cast<const float4*>(src + off);
    *reinterpret_cast<__half2*>(dst + off)     = __floats2half2_rn(v.x, v.y);
    *reinterpret_cast<__half2*>(dst + off + 2) = __floats2half2_rn(v.z, v.w);
}

// concat K/V weights -> fp16 [1024,512], biases -> fp32 [1024]
__global__ void __launch_bounds__(256) concat_kv16_kernel(
    const float* __restrict__ kw, const float* __restrict__ kb,
    const float* __restrict__ vw, const float* __restrict__ vb,
    __half* __restrict__ wcat, float* __restrict__ bcat)
{
    int idx = blockIdx.x * 256 + threadIdx.x;
    wcat[idx] = __float2half_rn(kw[idx]);
    wcat[262144 + idx] = __float2half_rn(vw[idx]);
    if (idx < 512) {
        bcat[idx] = kb[idx];
        bcat[512 + idx] = vb[idx];
    }
}

// ---------------------------------------------------------------------------
// FP16 GEMM 128x128
// ---------------------------------------------------------------------------
__global__ void __launch_bounds__(256, 2) gemm_f16_kernel(
    const __half* __restrict__ A, const __half* __restrict__ Wt,
    const float* __restrict__ bias, void* __restrict__ Cout,
    int M, int N, int K, int relu, int out16)
{
    __shared__ __align__(16) __half As[NSTAGE][128 * STRH];
    __shared__ __align__(16) __half Bs[NSTAGE][128 * STRH];

    const int tid  = threadIdx.x;
    const int wid  = tid >> 5;
    const int lane = tid & 31;
    const int wm   = (wid & 3) * 32;
    const int wn   = (wid >> 2) * 64;
    const int m0   = blockIdx.y * 128;
    const int n0   = blockIdx.x * 128;

    const int lrow = tid >> 2;
    const int lcol = (tid & 3) * 8;

    float acc[2][8][4];
#pragma unroll
    for (int i = 0; i < 2; ++i)
#pragma unroll
        for (int j = 0; j < 8; ++j)
#pragma unroll
            for (int q = 0; q < 4; ++q) acc[i][j][q] = 0.f;

    const int ntiles = K / BKH;
    const __half* Abase = A + (size_t)m0 * K;
    const __half* Bbase = Wt + (size_t)n0 * K;

#pragma unroll
    for (int s = 0; s < NSTAGE - 1; ++s) {
        int k0 = s * BKH;
#pragma unroll
        for (int p = 0; p < 2; ++p) {
            int r = lrow + p * 64;
            cp_async16(&As[s][r * STRH + lcol], Abase + (size_t)r * K + k0 + lcol);
            cp_async16(&Bs[s][r * STRH + lcol], Bbase + (size_t)r * K + k0 + lcol);
        }
        cp_commit();
    }

    const int a_row = wm + (lane & 15);
    const int a_koff = (lane >> 4) * 8;
    const int b_row_base = wn + (lane & 7) + ((lane >> 4) * 8);
    const int b_koff = ((lane >> 3) & 1) * 8;

    for (int t = 0; t < ntiles; ++t) {
        cp_wait2();
        __syncthreads();

        int ps = t + NSTAGE - 1;
        if (ps < ntiles) {
            int sb = ps & (NSTAGE - 1);
            int k0 = ps * BKH;
#pragma unroll
            for (int p = 0; p < 2; ++p) {
                int r = lrow + p * 64;
                cp_async16(&As[sb][r * STRH + lcol], Abase + (size_t)r * K + k0 + lcol);
                cp_async16(&Bs[sb][r * STRH + lcol], Bbase + (size_t)r * K + k0 + lcol);
            }
        }
        cp_commit();

        const int buf = t & (NSTAGE - 1);
#pragma unroll
        for (int ks = 0; ks < 2; ++ks) {
            unsigned a[2][4];
            unsigned b[8][2];
#pragma unroll
            for (int im = 0; im < 2; ++im)
                ldsm_x4h(a[im][0], a[im][1], a[im][2], a[im][3],
                         &As[buf][(a_row + im * 16) * STRH + ks * 16 + a_koff]);
#pragma unroll
            for (int ng = 0; ng < 4; ++ng) {
                unsigned r0, r1, r2, r3;
                ldsm_x4h(r0, r1, r2, r3,
                         &Bs[buf][(b_row_base + ng * 16) * STRH + ks * 16 + b_koff]);
                b[ng * 2][0] = r0; b[ng * 2][1] = r1;
                b[ng * 2 + 1][0] = r2; b[ng * 2 + 1][1] = r3;
            }
#pragma unroll
            for (int im = 0; im < 2; ++im)
#pragma unroll
                for (int in = 0; in < 8; ++in)
                    mma_f16(acc[im][in][0], acc[im][in][1], acc[im][in][2], acc[im][in][3],
                            a[im][0], a[im][1], a[im][2], a[im][3],
                            b[in][0], b[in][1]);
        }
    }

    const int row_base = m0 + wm + (lane >> 2);
    const int col_base = n0 + wn + (lane & 3) * 2;
#pragma unroll
    for (int im = 0; im < 2; ++im) {
#pragma unroll
        for (int in = 0; in < 8; ++in) {
            int col = col_base + in * 8;
            float b0 = bias[col], b1 = bias[col + 1];
            int r0 = row_base + im * 16;
            float v0 = acc[im][in][0] + b0;
            float v1 = acc[im][in][1] + b1;
            float v2 = acc[im][in][2] + b0;
            float v3 = acc[im][in][3] + b1;
            if (relu) {
                v0 = fmaxf(v0, 0.f); v1 = fmaxf(v1, 0.f);
                v2 = fmaxf(v2, 0.f); v3 = fmaxf(v3, 0.f);
            }
            if (out16) {
                __half* C = (__half*)Cout;
                *reinterpret_cast<__half2*>(&C[(size_t)r0 * N + col]) = __floats2half2_rn(v0, v1);
                *reinterpret_cast<__half2*>(&C[(size_t)(r0 + 8) * N + col]) = __floats2half2_rn(v2, v3);
            } else {
                float* C = (float*)Cout;
                C[(size_t)r0 * N + col] = v0;
                C[(size_t)r0 * N + col + 1] = v1;
                C[(size_t)(r0 + 8) * N + col] = v2;
                C[(size_t)(r0 + 8) * N + col + 1] = v3;
            }
        }
    }
}

// ---------------------------------------------------------------------------
// FP16 GEMM 128x64
// ---------------------------------------------------------------------------
__global__ void __launch_bounds__(256, 2) gemm_f16_n64_kernel(
    const __half* __restrict__ A, const __half* __restrict__ Wt,
    const float* __restrict__ bias, void* __restrict__ Cout,
    int M, int N, int K, int relu, int out16)
{
    __shared__ __align__(16) __half As[NSTAGE][128 * STRH];
    __shared__ __align__(16) __half Bs[NSTAGE][64 * STRH];

    const int tid  = threadIdx.x;
    const int wid  = tid >> 5;
    const int lane = tid & 31;
    const int wm   = (wid & 3) * 32;
    const int wn   = (wid >> 2) * 32;
    const int m0   = blockIdx.y * 128;
    const int n0   = blockIdx.x * 64;

    const int lrow = tid >> 2;
    const int lcol = (tid & 3) * 8;

    float acc[2][4][4];
#pragma unroll
    for (int i = 0; i < 2; ++i)
#pragma unroll
        for (int j = 0; j < 4; ++j)
#pragma unroll
            for (int q = 0; q < 4; ++q) acc[i][j][q] = 0.f;

    const int ntiles = K / BKH;
    const __half* Abase = A + (size_t)m0 * K;
    const __half* Bbase = Wt + (size_t)n0 * K;

#pragma unroll
    for (int s = 0; s < NSTAGE - 1; ++s) {
        int k0 = s * BKH;
#pragma unroll
        for (int p = 0; p < 2; ++p) {
            int r = lrow + p * 64;
            cp_async16(&As[s][r * STRH + lcol], Abase + (size_t)r * K + k0 + lcol);
        }
        cp_async16(&Bs[s][lrow * STRH + lcol], Bbase + (size_t)lrow * K + k0 + lcol);
        cp_commit();
    }

    const int a_row = wm + (lane & 15);
    const int a_koff = (lane >> 4) * 8;
    const int b_row_base = wn + (lane & 7) + ((lane >> 4) * 8);
    const int b_koff = ((lane >> 3) & 1) * 8;

    for (int t = 0; t < ntiles; ++t) {
        cp_wait2();
        __syncthreads();

        int ps = t + NSTAGE - 1;
        if (ps < ntiles) {
            int sb = ps & (NSTAGE - 1);
            int k0 = ps * BKH;
#pragma unroll
            for (int p = 0; p < 2; ++p) {
                int r = lrow + p * 64;
                cp_async16(&As[sb][r * STRH + lcol], Abase + (size_t)r * K + k0 + lcol);
            }
            cp_async16(&Bs[sb][lrow * STRH + lcol], Bbase + (size_t)lrow * K + k0 + lcol);
        }
        cp_commit();

        const int buf = t & (NSTAGE - 1);
#pragma unroll
        for (int ks = 0; ks < 2; ++ks) {
            unsigned a[2][4];
            unsigned b[4][2];
#pragma unroll
            for (int im = 0; im < 2; ++im)
                ldsm_x4h(a[im][0], a[im][1], a[im][2], a[im][3],
                         &As[buf][(a_row + im * 16) * STRH + ks * 16 + a_koff]);
#pragma unroll
            for (int ng = 0; ng < 2; ++ng) {
                unsigned r0, r1, r2, r3;
                ldsm_x4h(r0, r1, r2, r3,
                         &Bs[buf][(b_row_base + ng * 16) * STRH + ks * 16 + b_koff]);
                b[ng * 2][0] = r0; b[ng * 2][1] = r1;
                b[ng * 2 + 1][0] = r2; b[ng * 2 + 1][1] = r3;
            }
#pragma unroll
            for (int im = 0; im < 2; ++im)
#pragma unroll
                for (int in = 0; in < 4; ++in)
                    mma_f16(acc[im][in][0], acc[im][in][1], acc[im][in][2], acc[im][in][3],
                            a[im][0], a[im][1], a[im][2], a[im][3],
                            b[in][0], b[in][1]);
        }
    }

    const int row_base = m0 + wm + (lane >> 2);
    const int col_base = n0 + wn + (lane & 3) * 2;
#pragma unroll
    for (int im = 0; im < 2; ++im) {
#pragma unroll
        for (int in = 0; in < 4; ++in) {
            int col = col_base + in * 8;
            float b0 = bias[col], b1 = bias[col + 1];
            int r0 = row_base + im * 16;
            float v0 = acc[im][in][0] + b0;
            float v1 = acc[im][in][1] + b1;
            float v2 = acc[im][in][2] + b0;
            float v3 = acc[im][in][3] + b1;
            if (relu) {
                v0 = fmaxf(v0, 0.f); v1 = fmaxf(v1, 0.f);
                v2 = fmaxf(v2, 0.f); v3 = fmaxf(v3, 0.f);
            }
            if (out16) {
                __half* C = (__half*)Cout;
                *reinterpret_cast<__half2*>(&C[(size_t)r0 * N + col]) = __floats2half2_rn(v0, v1);
                *reinterpret_cast<__half2*>(&C[(size_t)(r0 + 8) * N + col]) = __floats2half2_rn(v2, v3);
            } else {
                float* C = (float*)Cout;
                C[(size_t)r0 * N + col] = v0;
                C[(size_t)r0 * N + col + 1] = v1;
                C[(size_t)(r0 + 8) * N + col] = v2;
                C[(size_t)(r0 + 8) * N + col + 1] = v3;
            }
        }
    }
}

// ---------------------------------------------------------------------------
// FP16 flash self-attention with register-resident P fragments (FA2-style).
// ---------------------------------------------------------------------------
#define ASTRH 72
#define KBUFH (64 * ASTRH)
#define ROWH 6144

__global__ void __launch_bounds__(256, 2) self_attn_f16_kernel(
    const __half* __restrict__ qkv, __half* __restrict__ out)
{
    extern __shared__ __half smh[];
    __half* Ps = smh;                 // Q staging only
    __half* Ks = smh + 128 * ASTRH;
    __half* Vs = Ks + 2 * KBUFH;

    const int tid = threadIdx.x;
    const int wid = tid >> 5;
    const int lane = tid & 31;
    const int b = blockIdx.y >> 3;
    const int h = blockIdx.y & 7;
    const int t0 = blockIdx.x * 128;
    const int wm = wid * 16;

    const __half* qbase = qkv + ((size_t)t0 * B_ + b) * 1536 + h * 64;
    const __half* kroot = qkv + (size_t)b * 1536 + 512 + h * 64;
    const __half* vroot = qkv + (size_t)b * 1536 + 1024 + h * 64;

#pragma unroll
    for (int i = 0; i < 4; ++i) {
        int idx = i * 256 + tid;
        int r = idx >> 3, c = (idx & 7) * 8;
        cp_async16(&Ps[r * ASTRH + c], qbase + (size_t)r * ROWH + c);
    }
#pragma unroll
    for (int i = 0; i < 2; ++i) {
        int idx = i * 256 + tid;
        int r = idx >> 3, c = (idx & 7) * 8;
        cp_async16(&Ks[r * ASTRH + c], kroot + (size_t)r * ROWH + c);
        cp_async16(&Vs[r * ASTRH + c], vroot + (size_t)r * ROWH + c);
    }
    cp_commit();
    cp_wait0();
    __syncthreads();

    unsigned qf[4][4];
    {
        const __half2 sc2 = __float2half2_rn(SCALE_);
        const int qrow = wm + (lane & 15);
        const int qko = (lane >> 4) * 8;
#pragma unroll
        for (int ks = 0; ks < 4; ++ks) {
            unsigned r0, r1, r2, r3;
            ldsm_x4h(r0, r1, r2, r3, &Ps[qrow * ASTRH + ks * 16 + qko]);
            unsigned rr[4] = {r0, r1, r2, r3};
#pragma unroll
            for (int j = 0; j < 4; ++j) {
                __half2 v = *reinterpret_cast<__half2*>(&rr[j]);
                v = __hmul2(v, sc2);
                qf[ks][j] = *reinterpret_cast<unsigned*>(&v);
            }
        }
    }

    float o[8][4];
#pragma unroll
    for (int n = 0; n < 8; ++n)
#pragma unroll
        for (int c = 0; c < 4; ++c) o[n][c] = 0.f;
    float m0 = -1e30f, m1 = -1e30f, l0 = 0.f, l1 = 0.f;

    const int brow_base = (lane & 7) + ((lane >> 4) * 8);
    const int bko = ((lane >> 3) & 1) * 8;
    const int prow0 = wm + (lane >> 2);
    const int pcol = 2 * (lane & 3);
    const int v_row = lane & 15;
    const int v_coff = (lane >> 4) * 8;

    for (int kt = 0; kt < 16; ++kt) {
        const int buf = kt & 1;

        if (kt + 1 < 16) {
            const __half* kb = kroot + (size_t)(kt + 1) * 64 * ROWH;
            const __half* vb = vroot + (size_t)(kt + 1) * 64 * ROWH;
            __half* kd = Ks + (buf ^ 1) * KBUFH;
            __half* vd = Vs + (buf ^ 1) * KBUFH;
#pragma unroll
            for (int i = 0; i < 2; ++i) {
                int idx = i * 256 + tid;
                int r = idx >> 3, c = (idx & 7) * 8;
                cp_async16(&kd[r * ASTRH + c], kb + (size_t)r * ROWH + c);
                cp_async16(&vd[r * ASTRH + c], vb + (size_t)r * ROWH + c);
            }
            cp_commit();
            cp_wait1();
        } else {
            cp_wait0();
        }
        __syncthreads();

        // S = Q K^T
        const __half* Kb = Ks + buf * KBUFH;
        float s[8][4];
#pragma unroll
        for (int n = 0; n < 8; ++n)
#pragma unroll
            for (int c = 0; c < 4; ++c) s[n][c] = 0.f;
#pragma unroll
        for (int ks = 0; ks < 4; ++ks) {
#pragma unroll
            for (int ng = 0; ng < 4; ++ng) {
                unsigned r0, r1, r2, r3;
                ldsm_x4h(r0, r1, r2, r3, &Kb[(brow_base + ng * 16) * ASTRH + ks * 16 + bko]);
                mma_f16(s[ng * 2][0], s[ng * 2][1], s[ng * 2][2], s[ng * 2][3],
                        qf[ks][0], qf[ks][1], qf[ks][2], qf[ks][3], r0, r1);
                mma_f16(s[ng * 2 + 1][0], s[ng * 2 + 1][1], s[ng * 2 + 1][2], s[ng * 2 + 1][3],
                        qf[ks][0], qf[ks][1], qf[ks][2], qf[ks][3], r2, r3);
            }
        }

        // online softmax -> register P fragments
        float mx0 = -1e30f, mx1 = -1e30f;
#pragma unroll
        for (int n = 0; n < 8; ++n) {
            mx0 = fmaxf(mx0, fmaxf(s[n][0], s[n][1]));
            mx1 = fmaxf(mx1, fmaxf(s[n][2], s[n][3]));
        }
        mx0 = fmaxf(mx0, __shfl_xor_sync(0xffffffffu, mx0, 1));
        mx0 = fmaxf(mx0, __shfl_xor_sync(0xffffffffu, mx0, 2));
        mx1 = fmaxf(mx1, __shfl_xor_sync(0xffffffffu, mx1, 1));
        mx1 = fmaxf(mx1, __shfl_xor_sync(0xffffffffu, mx1, 2));

        float mn0 = fmaxf(m0, mx0), mn1 = fmaxf(m1, mx1);
        float corr0 = __expf(m0 - mn0), corr1 = __expf(m1 - mn1);
        m0 = mn0; m1 = mn1;
        l0 *= corr0; l1 *= corr1;
#pragma unroll
        for (int n = 0; n < 8; ++n) {
            o[n][0] *= corr0; o[n][1] *= corr0;
            o[n][2] *= corr1; o[n][3] *= corr1;
        }

        unsigned pf[4][4];
#pragma unroll
        for (int j = 0; j < 4; ++j) {
            float p00 = __expf(s[2 * j][0] - mn0);
            float p01 = __expf(s[2 * j][1] - mn0);
            float p02 = __expf(s[2 * j][2] - mn1);
            float p03 = __expf(s[2 * j][3] - mn1);
            float p10 = __expf(s[2 * j + 1][0] - mn0);
            float p11 = __expf(s[2 * j + 1][1] - mn0);
            float p12 = __expf(s[2 * j + 1][2] - mn1);
            float p13 = __expf(s[2 * j + 1][3] - mn1);
            l0 += p00 + p01 + p10 + p11;
            l1 += p02 + p03 + p12 + p13;
            __half2 hh;
            hh = __floats2half2_rn(p00, p01); pf[j][0] = *reinterpret_cast<unsigned*>(&hh);
            hh = __floats2half2_rn(p02, p03); pf[j][1] = *reinterpret_cast<unsigned*>(&hh);
            hh = __floats2half2_rn(p10, p11); pf[j][2] = *reinterpret_cast<unsigned*>(&hh);
            hh = __floats2half2_rn(p12, p13); pf[j][3] = *reinterpret_cast<unsigned*>(&hh);
        }

        // O += P V (P in registers, V via trans ldsm)
        const __half* Vb = Vs + buf * KBUFH;
#pragma unroll
        for (int ks = 0; ks < 4; ++ks) {
#pragma unroll
            for (int ng = 0; ng < 4; ++ng) {
                unsigned r0, r1, r2, r3;
                ldsm_x4h_t(r0, r1, r2, r3,
                           &Vb[(ks * 16 + v_row) * ASTRH + ng * 16 + v_coff]);
                mma_f16(o[ng * 2][0], o[ng * 2][1], o[ng * 2][2], o[ng * 2][3],
                        pf[ks][0], pf[ks][1], pf[ks][2], pf[ks][3], r0, r1);
                mma_f16(o[ng * 2 + 1][0], o[ng * 2 + 1][1], o[ng * 2 + 1][2], o[ng * 2 + 1][3],
                        pf[ks][0], pf[ks][1], pf[ks][2], pf[ks][3], r2, r3);
            }
        }
        __syncthreads();
    }

    l0 += __shfl_xor_sync(0xffffffffu, l0, 1);
    l0 += __shfl_xor_sync(0xffffffffu, l0, 2);
    l1 += __shfl_xor_sync(0xffffffffu, l1, 1);
    l1 += __shfl_xor_sync(0xffffffffu, l1, 2);
    float inv0 = 1.f / l0, inv1 = 1.f / l1;

    __half* ob0 = out + ((size_t)(t0 + prow0) * B_ + b) * D_ + h * 64 + pcol;
    __half* ob1 = out + ((size_t)(t0 + prow0 + 8) * B_ + b) * D_ + h * 64 + pcol;
#pragma unroll
    for (int n = 0; n < 8; ++n) {
        *reinterpret_cast<__half2*>(ob0 + n * 8) = __floats2half2_rn(o[n][0] * inv0, o[n][1] * inv0);
        *reinterpret_cast<__half2*>(ob1 + n * 8) = __floats2half2_rn(o[n][2] * inv1, o[n][3] * inv1);
    }
}

#define ATTN_SMEM ((128 + 4 * 64) * ASTRH * 2)

// ---------------------------------------------------------------------------
// FP16 banded sliding-window attention (register P).
// ---------------------------------------------------------------------------
__global__ void __launch_bounds__(256, 2) sw_attn_f16_kernel(
    const __half* __restrict__ q, const __half* __restrict__ kv,
    __half* __restrict__ out)
{
    extern __shared__ __half smh[];
    __half* Ps = smh;
    __half* Ks = smh + 128 * ASTRH;
    __half* Vs = Ks + 2 * KBUFH;

    const int tid = threadIdx.x;
    const int wid = tid >> 5;
    const int lane = tid & 31;
    const int b = blockIdx.y >> 3;
    const int h = blockIdx.y & 7;
    const int t0 = blockIdx.x * 128;
    const int wm = wid * 16;

#pragma unroll
    for (int i = 0; i < 4; ++i) {
        int idx = i * 256 + tid;
        int r = idx >> 3, c = (idx & 7) * 8;
        cp_async16(&Ps[r * ASTRH + c],
                   q + ((size_t)(t0 + r) * B_ + b) * D_ + h * 64 + c);
    }
    {
        int key0 = t0 - 16;
#pragma unroll
        for (int i = 0; i < 2; ++i) {
            int idx = i * 256 + tid;
            int r = idx >> 3, c = (idx & 7) * 8;
            int key = min(max(key0 + r, 0), S_ - 1);
            const __half* base = kv + ((size_t)key * B_ + b) * 1024 + h * 64;
            cp_async16(&Ks[r * ASTRH + c], base + c);
            cp_async16(&Vs[r * ASTRH + c], base + 512 + c);
        }
    }
    cp_commit();
    cp_wait0();
    __syncthreads();

    unsigned qf[4][4];
    {
        const __half2 sc2 = __float2half2_rn(SCALE_);
        const int qrow = wm + (lane & 15);
        const int qko = (lane >> 4) * 8;
#pragma unroll
        for (int ks = 0; ks < 4; ++ks) {
            unsigned r0, r1, r2, r3;
            ldsm_x4h(r0, r1, r2, r3, &Ps[qrow * ASTRH + ks * 16 + qko]);
            unsigned rr[4] = {r0, r1, r2, r3};
#pragma unroll
            for (int j = 0; j < 4; ++j) {
                __half2 v = *reinterpret_cast<__half2*>(&rr[j]);
                v = __hmul2(v, sc2);
                qf[ks][j] = *reinterpret_cast<unsigned*>(&v);
            }
        }
    }

    float o[8][4];
#pragma unroll
    for (int n = 0; n < 8; ++n)
#pragma unroll
        for (int c = 0; c < 4; ++c) o[n][c] = 0.f;
    float m0 = -1e30f, m1 = -1e30f, l0 = 0.f, l1 = 0.f;

    const int brow_base = (lane & 7) + ((lane >> 4) * 8);
    const int bko = ((lane >> 3) & 1) * 8;
    const int prow0 = wm + (lane >> 2);
    const int pcol = 2 * (lane & 3);
    const int v_row = lane & 15;
    const int v_coff = (lane >> 4) * 8;

    for (int kt = 0; kt < 3; ++kt) {
        const int buf = kt & 1;
        const int key0 = t0 - 16 + kt * 64;

        if (kt + 1 < 3) {
            int nk0 = t0 - 16 + (kt + 1) * 64;
            __half* kd = Ks + (buf ^ 1) * KBUFH;
            __half* vd = Vs + (buf ^ 1) * KBUFH;
#pragma unroll
            for (int i = 0; i < 2; ++i) {
                int idx = i * 256 + tid;
                int r = idx >> 3, c = (idx & 7) * 8;
                int key = min(max(nk0 + r, 0), S_ - 1);
                const __half* base = kv + ((size_t)key * B_ + b) * 1024 + h * 64;
                cp_async16(&kd[r * ASTRH + c], base + c);
                cp_async16(&vd[r * ASTRH + c], base + 512 + c);
            }
            cp_commit();
            cp_wait1();
        } else {
            cp_wait0();
        }
        __syncthreads();

        const __half* Kb = Ks + buf * KBUFH;
        float s[8][4];
#pragma unroll
        for (int n = 0; n < 8; ++n)
#pragma unroll
            for (int c = 0; c < 4; ++c) s[n][c] = 0.f;
#pragma unroll
        for (int ks = 0; ks < 4; ++ks) {
#pragma unroll
            for (int ng = 0; ng < 4; ++ng) {
                unsigned r0, r1, r2, r3;
                ldsm_x4h(r0, r1, r2, r3, &Kb[(brow_base + ng * 16) * ASTRH + ks * 16 + bko]);
                mma_f16(s[ng * 2][0], s[ng * 2][1], s[ng * 2][2], s[ng * 2][3],
                        qf[ks][0], qf[ks][1], qf[ks][2], qf[ks][3], r0, r1);
                mma_f16(s[ng * 2 + 1][0], s[ng * 2 + 1][1], s[ng * 2 + 1][2], s[ng * 2 + 1][3],
                        qf[ks][0], qf[ks][1], qf[ks][2], qf[ks][3], r2, r3);
            }
        }

        // band mask
#pragma unroll
        for (int n = 0; n < 8; ++n) {
#pragma unroll
            for (int c = 0; c < 4; ++c) {
                int key = key0 + n * 8 + pcol + (c & 1);
                int qg = t0 + prow0 + ((c >> 1) * 8);
                bool valid = (key >= 0) && (key < S_) && (key - qg <= W_) && (qg - key <= W_);
                if (!valid) s[n][c] = -1e38f;
            }
        }

        float mx0 = -1e30f, mx1 = -1e30f;
#pragma unroll
        for (int n = 0; n < 8; ++n) {
            mx0 = fmaxf(mx0, fmaxf(s[n][0], s[n][1]));
            mx1 = fmaxf(mx1, fmaxf(s[n][2], s[n][3]));
        }
        mx0 = fmaxf(mx0, __shfl_xor_sync(0xffffffffu, mx0, 1));
        mx0 = fmaxf(mx0, __shfl_xor_sync(0xffffffffu, mx0, 2));
        mx1 = fmaxf(mx1, __shfl_xor_sync(0xffffffffu, mx1, 1));
        mx1 = fmaxf(mx1, __shfl_xor_sync(0xffffffffu, mx1, 2));

        float mn0 = fmaxf(m0, mx0), mn1 = fmaxf(m1, mx1);
        float corr0 = __expf(m0 - mn0), corr1 = __expf(m1 - mn1);
        m0 = mn0; m1 = mn1;
        l0 *= corr0; l1 *= corr1;
#pragma unroll
        for (int n = 0; n < 8; ++n) {
            o[n][0] *= corr0; o[n][1] *= corr0;
            o[n][2] *= corr1; o[n][3] *= corr1;
        }

        unsigned pf[4][4];
#pragma unroll
        for (int j = 0; j < 4; ++j) {
            float p00 = __expf(s[2 * j][0] - mn0);
            float p01 = __expf(s[2 * j][1] - mn0);
            float p02 = __expf(s[2 * j][2] - mn1);
            float p03 = __expf(s[2 * j][3] - mn1);
            float p10 = __expf(s[2 * j + 1][0] - mn0);
            float p11 = __expf(s[2 * j + 1][1] - mn0);
            float p12 = __expf(s[2 * j + 1][2] - mn1);
            float p13 = __expf(s[2 * j + 1][3] - mn1);
            l0 += p00 + p01 + p10 + p11;
            l1 += p02 + p03 + p12 + p13;
            __half2 hh;
            hh = __floats2half2_rn(p00, p01); pf[j][0] = *reinterpret_cast<unsigned*>(&hh);
            hh = __floats2half2_rn(p02, p03); pf[j][1] = *reinterpret_cast<unsigned*>(&hh);
            hh = __floats2half2_rn(p10, p11); pf[j][2] = *reinterpret_cast<unsigned*>(&hh);
            hh = __floats2half2_rn(p12, p13); pf[j][3] = *reinterpret_cast<unsigned*>(&hh);
        }

        const __half* Vb = Vs + buf * KBUFH;
#pragma unroll
        for (int ks = 0; ks < 4; ++ks) {
#pragma unroll
            for (int ng = 0; ng < 4; ++ng) {
                unsigned r0, r1, r2, r3;
                ldsm_x4h_t(r0, r1, r2, r3,
                           &Vb[(ks * 16 + v_row) * ASTRH + ng * 16 + v_coff]);
                mma_f16(o[ng * 2][0], o[ng * 2][1], o[ng * 2][2], o[ng * 2][3],
                        pf[ks][0], pf[ks][1], pf[ks][2], pf[ks][3], r0, r1);
                mma_f16(o[ng * 2 + 1][0], o[ng * 2 + 1][1], o[ng * 2 + 1][2], o[ng * 2 + 1][3],
                        pf[ks][0], pf[ks][1], pf[ks][2], pf[ks][3], r2, r3);
            }
        }
        __syncthreads();
    }

    l0 += __shfl_xor_sync(0xffffffffu, l0, 1);
    l0 += __shfl_xor_sync(0xffffffffu, l0, 2);
    l1 += __shfl_xor_sync(0xffffffffu, l1, 1);
    l1 += __shfl_xor_sync(0xffffffffu, l1, 2);
    float inv0 = 1.f / l0, inv1 = 1.f / l1;

    __half* ob0 = out + ((size_t)(t0 + prow0) * B_ + b) * D_ + h * 64 + pcol;
    __half* ob1 = out + ((size_t)(t0 + prow0 + 8) * B_ + b) * D_ + h * 64 + pcol;
#pragma unroll
    for (int n = 0; n < 8; ++n) {
        *reinterpret_cast<__half2*>(ob0 + n * 8) = __floats2half2_rn(o[n][0] * inv0, o[n][1] * inv0);
        *reinterpret_cast<__half2*>(ob1 + n * 8) = __floats2half2_rn(o[n][2] * inv1, o[n][3] * inv1);
    }
}

// ---------------------------------------------------------------------------
// Fused residual-add(LN y in fp16) + LayerNorm; fp32 out + optional fp16 out.
// ---------------------------------------------------------------------------
__global__ void __launch_bounds__(256) add_ln_h_kernel(
    const float* __restrict__ x, const __half* __restrict__ y,
    const float* __restrict__ g, const float* __restrict__ beta,
    float* __restrict__ out, __half* __restrict__ out16)
{
    __shared__ float sh[33];
    const int row = blockIdx.x;
    const int tid = threadIdx.x;
    const size_t base = (size_t)row * D_;

    float v0 = x[base + tid] + __half2float(y[base + tid]);
    float v1 = x[base + tid + 256] + __half2float(y[base + tid + 256]);

    float s = v0 + v1;
#pragma unroll
    for (int o = 16; o > 0; o >>= 1) s += __shfl_xor_sync(0xffffffffu, s, o);
    int lane = tid & 31, wid = tid >> 5;
    if (lane == 0) sh[wid] = s;
    __syncthreads();
    if (wid == 0) {
        float t = (lane < 8) ? sh[lane] : 0.f;
#pragma unroll
        for (int o = 4; o > 0; o >>= 1) t += __shfl_xor_sync(0xffffffffu, t, o);
        if (lane == 0) sh[32] = t;
    }
    __syncthreads();
    float mean = sh[32] * (1.f / D_);
    __syncthreads();

    float d0 = v0 - mean, d1 = v1 - mean;
    float sq = d0 * d0 + d1 * d1;
#pragma unroll
    for (int o = 16; o > 0; o >>= 1) sq += __shfl_xor_sync(0xffffffffu, sq, o);
    if (lane == 0) sh[wid] = sq;
    __syncthreads();
    if (wid == 0) {
        float t = (lane < 8) ? sh[lane] : 0.f;
#pragma unroll
        for (int o = 4; o > 0; o >>= 1) t += __shfl_xor_sync(0xffffffffu, t, o);
        if (lane == 0) sh[32] = t;
    }
    __syncthreads();
    float rstd = rsqrtf(sh[32] * (1.f / D_) + EPS_);

    float r0 = d0 * rstd * g[tid] + beta[tid];
    float r1 = d1 * rstd * g[tid + 256] + beta[tid + 256];
    out[base + tid] = r0;
    out[base + tid + 256] = r1;
    if (out16) {
        out16[base + tid] = __float2half_rn(r0);
        out16[base + tid + 256] = __float2half_rn(r1);
    }
}

// ---------------------------------------------------------------------------
// Launch
// ---------------------------------------------------------------------------
extern "C" void kernel_launch(void* const* d_in, const int* in_sizes, int n_in,
                              void* d_out, int out_size)
{
    (void)in_sizes; (void)n_in; (void)out_size;
    const float* tgt        = (const float*)d_in[0];
    const float* memory     = (const float*)d_in[1];
    const float* in_proj_w  = (const float*)d_in[2];
    const float* in_proj_b  = (const float*)d_in[3];
    const float* out_proj_w = (const float*)d_in[4];
    const float* out_proj_b = (const float*)d_in[5];
    const float* sw_q_w = (const float*)d_in[6];
    const float* sw_q_b = (const float*)d_in[7];
    const float* sw_k_w = (const float*)d_in[8];
    const float* sw_k_b = (const float*)d_in[9];
    const float* sw_v_w = (const float*)d_in[10];
    const float* sw_v_b = (const float*)d_in[11];
    const float* sw_o_w = (const float*)d_in[12];
    const float* sw_o_b = (const float*)d_in[13];
    const float* lin1_w = (const float*)d_in[14];
    const float* lin1_b = (const float*)d_in[15];
    const float* lin2_w = (const float*)d_in[16];
    const float* lin2_b = (const float*)d_in[17];
    const float* n1_g = (const float*)d_in[18];
    const float* n1_b = (const float*)d_in[19];
    const float* n2_g = (const float*)d_in[20];
    const float* n2_b = (const float*)d_in[21];
    const float* n3_g = (const float*)d_in[22];
    const float* n3_b = (const float*)d_in[23];
    float* out = (float*)d_out;

    float* s = nullptr;
    cudaGetSymbolAddress((void**)&s, g_scratch);
    float* x1    = s + FOFF_X1;
    float* x2    = s + FOFF_X2;
    float* bcat  = s + FOFF_BCAT;
    __half* hb = (__half*)(s + HALF_BASE_F);
    __half* qkv16    = hb + HOFF_QKV;
    __half* attn16   = hb + HOFF_ATTN;
    __half* swq16    = hb + HOFF_SWQ;
    __half* swkv16   = hb + HOFF_SWKV;
    __half* swattn16 = hb + HOFF_SWATTN;
    __half* hbuf16   = hb + HOFF_HBUF;
    __half* tgt16    = hb + HOFF_TGT;
    __half* mem16    = hb + HOFF_MEM;
    __half* x1h      = hb + HOFF_X1H;
    __half* x2h      = hb + HOFF_X2H;
    __half* w_in     = hb + HOFF_WIN;
    __half* w_out    = hb + HOFF_WOUT;
    __half* w_swq    = hb + HOFF_WSWQ;
    __half* w_swkv   = hb + HOFF_WSWKV;
    __half* w_swo    = hb + HOFF_WSWO;
    __half* w_lin1   = hb + HOFF_WLIN1;
    __half* w_lin2   = hb + HOFF_WLIN2;
    __half* proj16   = hb + HOFF_PROJ16;
    __half* ff16     = hb + HOFF_FF16;

    cudaFuncSetAttribute(self_attn_f16_kernel,
                         cudaFuncAttributeMaxDynamicSharedMemorySize, ATTN_SMEM);
    cudaFuncSetAttribute(sw_attn_f16_kernel,
                         cudaFuncAttributeMaxDynamicSharedMemorySize, ATTN_SMEM);

    // converts: one fused kernel + KV concat
    f2h_multi_kernel<<<7680, 256>>>(tgt, tgt16, memory, mem16,
                                    in_proj_w, w_in, out_proj_w, w_out,
                                    sw_q_w, w_swq, sw_o_w, w_swo,
                                    lin1_w, w_lin1, lin2_w, w_lin2);
    concat_kv16_kernel<<<1024, 256>>>(sw_k_w, sw_k_b, sw_v_w, sw_v_b, w_swkv, bcat);

    // fused KV projection of memory
    gemm_f16_kernel<<<dim3(8, 32), 256>>>(mem16, w_swkv, bcat, swkv16,
                                          NROWS, 1024, D_, 0, 1);
    // QKV projection
    gemm_f16_kernel<<<dim3(12, 32), 256>>>(tgt16, w_in, in_proj_b, qkv16,
                                           NROWS, 3 * D_, D_, 0, 1);
    // self attention
    self_attn_f16_kernel<<<dim3(8, 32), 256, ATTN_SMEM>>>(qkv16, attn16);
    // out projection -> fp16
    gemm_f16_n64_kernel<<<dim3(8, 32), 256>>>(attn16, w_out, out_proj_b, proj16,
                                              NROWS, D_, D_, 0, 1);
    // add + LN1
    add_ln_h_kernel<<<NROWS, 256>>>(tgt, proj16, n1_g, n1_b, x1, x1h);
    // sw q projection
    gemm_f16_n64_kernel<<<dim3(8, 32), 256>>>(x1h, w_swq, sw_q_b, swq16,
                                              NROWS, D_, D_, 0, 1);
    // banded attention
    sw_attn_f16_kernel<<<dim3(8, 32), 256, ATTN_SMEM>>>(swq16, swkv16, swattn16);
    // sw out projection -> fp16
    gemm_f16_n64_kernel<<<dim3(8, 32), 256>>>(swattn16, w_swo, sw_o_b, proj16,
                                              NROWS, D_, D_, 0, 1);
    // add + LN2
    add_ln_h_kernel<<<NROWS, 256>>>(x1, proj16, n2_g, n2_b, x2, x2h);
    // FFN up + ReLU
    gemm_f16_kernel<<<dim3(16, 32), 256>>>(x2h, w_lin1, lin1_b, hbuf16,
                                           NROWS, DFF_, D_, 1, 1);
    // FFN down -> fp16
    gemm_f16_n64_kernel<<<dim3(8, 32), 256>>>(hbuf16, w_lin2, lin2_b, ff16,
                                              NROWS, D_, DFF_, 0, 1);
    // add + LN3 -> output (fp32 only)
    add_ln_h_kernel<<<NROWS, 256>>>(x2, ff16, n3_g, n3_b, out, nullptr);
}

// round 11
// speedup vs baseline: 6.6145x; 1.0450x over previous
#include <cuda_runtime.h>
#include <cuda_fp16.h>
#include <stdint.h>
#include <math.h>

#define T_ 1024
#define S_ 1024
#define B_ 4
#define D_ 512
#define H_ 8
#define HD_ 64
#define DFF_ 2048
#define W_ 16
#define NROWS (T_ * B_)
#define SCALE_ 0.125f
#define EPS_ 1e-5f

// fp32 region (float offsets)
#define FOFF_X1     0
#define FOFF_X2     2097152
#define FOFF_BCAT   4194304
#define HALF_BASE_F 5000000

// half region (half offsets)
#define HOFF_QKV    0
#define HOFF_ATTN   6291456
#define HOFF_SWQ    8388608
#define HOFF_SWKV   10485760
#define HOFF_SWATTN 14680064
#define HOFF_HBUF   16777216
#define HOFF_TGT    25165824
#define HOFF_MEM    27262976
#define HOFF_X1H    29360128
#define HOFF_X2H    31457280
#define HOFF_WIN    33554432
#define HOFF_WOUT   34340864
#define HOFF_WSWQ   34603008
#define HOFF_WSWKV  34865152
#define HOFF_WSWO   35389440
#define HOFF_WLIN1  35651584
#define HOFF_WLIN2  36700160
#define HOFF_PROJ16 37748736
#define HOFF_FF16   39845888

#define SCRATCH_FLOATS 33554432
__device__ float g_scratch[SCRATCH_FLOATS];

// ---------------------------------------------------------------------------
// PTX helpers
// ---------------------------------------------------------------------------
__device__ __forceinline__ void cp_async16(void* smem_ptr, const void* gmem_ptr) {
    unsigned saddr = (unsigned)__cvta_generic_to_shared(smem_ptr);
    asm volatile("cp.async.cg.shared.global [%0], [%1], 16;\n"
                 :: "r"(saddr), "l"(gmem_ptr));
}
__device__ __forceinline__ void cp_commit() {
    asm volatile("cp.async.commit_group;\n");
}
__device__ __forceinline__ void cp_wait0() {
    asm volatile("cp.async.wait_group 0;\n");
}
__device__ __forceinline__ void cp_wait1() {
    asm volatile("cp.async.wait_group 1;\n");
}
__device__ __forceinline__ void ldsm_x4h(unsigned& r0, unsigned& r1, unsigned& r2, unsigned& r3,
                                         const __half* p) {
    unsigned saddr = (unsigned)__cvta_generic_to_shared((void*)p);
    asm volatile("ldmatrix.sync.aligned.m8n8.x4.shared.b16 {%0,%1,%2,%3}, [%4];\n"
                 : "=r"(r0), "=r"(r1), "=r"(r2), "=r"(r3) : "r"(saddr));
}
__device__ __forceinline__ void ldsm_x4h_t(unsigned& r0, unsigned& r1, unsigned& r2, unsigned& r3,
                                           const __half* p) {
    unsigned saddr = (unsigned)__cvta_generic_to_shared((void*)p);
    asm volatile("ldmatrix.sync.aligned.m8n8.x4.trans.shared.b16 {%0,%1,%2,%3}, [%4];\n"
                 : "=r"(r0), "=r"(r1), "=r"(r2), "=r"(r3) : "r"(saddr));
}
__device__ __forceinline__ void mma_f16(float& c0, float& c1, float& c2, float& c3,
                                        unsigned a0, unsigned a1, unsigned a2, unsigned a3,
                                        unsigned b0, unsigned b1) {
    asm volatile("mma.sync.aligned.m16n8k16.row.col.f32.f16.f16.f32 "
                 "{%0,%1,%2,%3}, {%4,%5,%6,%7}, {%8,%9}, {%0,%1,%2,%3};\n"
                 : "+f"(c0), "+f"(c1), "+f"(c2), "+f"(c3)
                 : "r"(a0), "r"(a1), "r"(a2), "r"(a3), "r"(b0), "r"(b1));
}

// ---------------------------------------------------------------------------
// fp32->fp16 fused convert (8 segments)
// ---------------------------------------------------------------------------
__global__ void __launch_bounds__(256) f2h_multi_kernel(
    const float* __restrict__ s0, __half* __restrict__ d0,
    const float* __restrict__ s1, __half* __restrict__ d1,
    const float* __restrict__ s2, __half* __restrict__ d2,
    const float* __restrict__ s3, __half* __restrict__ d3,
    const float* __restrict__ s4, __half* __restrict__ d4,
    const float* __restrict__ s5, __half* __restrict__ d5,
    const float* __restrict__ s6, __half* __restrict__ d6,
    const float* __restrict__ s7, __half* __restrict__ d7)
{
    int idx = (blockIdx.x * 256 + threadIdx.x) * 4;
    const float* src; __half* dst; int off;
    if      (idx < 2097152) { src = s0; dst = d0; off = idx; }
    else if (idx < 4194304) { src = s1; dst = d1; off = idx - 2097152; }
    else if (idx < 4980736) { src = s2; dst = d2; off = idx - 4194304; }
    else if (idx < 5242880) { src = s3; dst = d3; off = idx - 4980736; }
    else if (idx < 5505024) { src = s4; dst = d4; off = idx - 5242880; }
    else if (idx < 5767168) { src = s5; dst = d5; off = idx - 5505024; }
    else if (idx < 6815744) { src = s6; dst = d6; off = idx - 5767168; }
    else                    { src = s7; dst = d7; off = idx - 6815744; }
    float4 v = *reinterpret_cast<const float4*>(src + off);
    *reinterpret_cast<__half2*>(dst + off)     = __floats2half2_rn(v.x, v.y);
    *reinterpret_cast<__half2*>(dst + off + 2) = __floats2half2_rn(v.z, v.w);
}

__global__ void __launch_bounds__(256) concat_kv16_kernel(
    const float* __restrict__ kw, const float* __restrict__ kb,
    const float* __restrict__ vw, const float* __restrict__ vb,
    __half* __restrict__ wcat, float* __restrict__ bcat)
{
    int idx = blockIdx.x * 256 + threadIdx.x;
    wcat[idx] = __float2half_rn(kw[idx]);
    wcat[262144 + idx] = __float2half_rn(vw[idx]);
    if (idx < 512) {
        bcat[idx] = kb[idx];
        bcat[512 + idx] = vb[idx];
    }
}

// ---------------------------------------------------------------------------
// FP16 GEMM 128x128, BK=64, 3-stage pipeline, dynamic smem.
// smem halfs: As[3][128*72] then Bs[3][128*72] (total 55296 halfs = 108 KB).
// ---------------------------------------------------------------------------
#define STR64 72
#define ASTG (128 * STR64)          // 9216 halfs per A stage
#define G128_SMEM (6 * ASTG * 2)    // bytes = 110592

__global__ void __launch_bounds__(256, 2) gemm_f16_kernel(
    const __half* __restrict__ A, const __half* __restrict__ Wt,
    const float* __restrict__ bias, void* __restrict__ Cout,
    int M, int N, int K, int relu, int out16)
{
    extern __shared__ __half sg[];
    __half* As = sg;
    __half* Bs = sg + 3 * ASTG;

    const int tid  = threadIdx.x;
    const int wid  = tid >> 5;
    const int lane = tid & 31;
    const int wm   = (wid & 3) * 32;
    const int wn   = (wid >> 2) * 64;
    const int m0   = blockIdx.y * 128;
    const int n0   = blockIdx.x * 128;

    float acc[2][8][4];
#pragma unroll
    for (int i = 0; i < 2; ++i)
#pragma unroll
        for (int j = 0; j < 8; ++j)
#pragma unroll
            for (int q = 0; q < 4; ++q) acc[i][j][q] = 0.f;

    const int ntiles = K / 64;
    const __half* Abase = A + (size_t)m0 * K;
    const __half* Bbase = Wt + (size_t)n0 * K;

    // loader: 128 rows x 64 halfs = 1024 cp16, 4 per thread (A), 4 (B)
    auto load_stage = [&](int t, int st) {
        int k0 = t * 64;
        __half* Ad = As + st * ASTG;
        __half* Bd = Bs + st * ASTG;
#pragma unroll
        for (int it = 0; it < 4; ++it) {
            int idx = it * 256 + tid;
            int row = idx >> 3, col = (idx & 7) * 8;
            cp_async16(&Ad[row * STR64 + col], Abase + (size_t)row * K + k0 + col);
            cp_async16(&Bd[row * STR64 + col], Bbase + (size_t)row * K + k0 + col);
        }
    };

    load_stage(0, 0); cp_commit();
    load_stage(1, 1); cp_commit();

    const int a_row = wm + (lane & 15);
    const int a_koff = (lane >> 4) * 8;
    const int b_row_base = wn + (lane & 7) + ((lane >> 4) * 8);
    const int b_koff = ((lane >> 3) & 1) * 8;

    for (int t = 0; t < ntiles; ++t) {
        cp_wait1();
        __syncthreads();

        int ps = t + 2;
        if (ps < ntiles) load_stage(ps, ps % 3);
        cp_commit();

        const int buf = t % 3;
        const __half* Ab = As + buf * ASTG;
        const __half* Bb = Bs + buf * ASTG;
#pragma unroll
        for (int ks = 0; ks < 4; ++ks) {
            unsigned a[2][4];
            unsigned b[8][2];
#pragma unroll
            for (int im = 0; im < 2; ++im)
                ldsm_x4h(a[im][0], a[im][1], a[im][2], a[im][3],
                         &Ab[(a_row + im * 16) * STR64 + ks * 16 + a_koff]);
#pragma unroll
            for (int ng = 0; ng < 4; ++ng) {
                unsigned r0, r1, r2, r3;
                ldsm_x4h(r0, r1, r2, r3,
                         &Bb[(b_row_base + ng * 16) * STR64 + ks * 16 + b_koff]);
                b[ng * 2][0] = r0; b[ng * 2][1] = r1;
                b[ng * 2 + 1][0] = r2; b[ng * 2 + 1][1] = r3;
            }
#pragma unroll
            for (int im = 0; im < 2; ++im)
#pragma unroll
                for (int in = 0; in < 8; ++in)
                    mma_f16(acc[im][in][0], acc[im][in][1], acc[im][in][2], acc[im][in][3],
                            a[im][0], a[im][1], a[im][2], a[im][3],
                            b[in][0], b[in][1]);
        }
    }

    const int row_base = m0 + wm + (lane >> 2);
    const int col_base = n0 + wn + (lane & 3) * 2;
#pragma unroll
    for (int im = 0; im < 2; ++im) {
#pragma unroll
        for (int in = 0; in < 8; ++in) {
            int col = col_base + in * 8;
            float b0 = bias[col], b1 = bias[col + 1];
            int r0 = row_base + im * 16;
            float v0 = acc[im][in][0] + b0;
            float v1 = acc[im][in][1] + b1;
            float v2 = acc[im][in][2] + b0;
            float v3 = acc[im][in][3] + b1;
            if (relu) {
                v0 = fmaxf(v0, 0.f); v1 = fmaxf(v1, 0.f);
                v2 = fmaxf(v2, 0.f); v3 = fmaxf(v3, 0.f);
            }
            if (out16) {
                __half* C = (__half*)Cout;
                *reinterpret_cast<__half2*>(&C[(size_t)r0 * N + col]) = __floats2half2_rn(v0, v1);
                *reinterpret_cast<__half2*>(&C[(size_t)(r0 + 8) * N + col]) = __floats2half2_rn(v2, v3);
            } else {
                float* C = (float*)Cout;
                C[(size_t)r0 * N + col] = v0;
                C[(size_t)r0 * N + col + 1] = v1;
                C[(size_t)(r0 + 8) * N + col] = v2;
                C[(size_t)(r0 + 8) * N + col + 1] = v3;
            }
        }
    }
}

// ---------------------------------------------------------------------------
// FP16 GEMM 128x64, BK=64, 3-stage, dynamic smem (A 3x9216 + B 3x4608 halfs).
// ---------------------------------------------------------------------------
#define BSTG64 (64 * STR64)          // 4608 halfs per B stage
#define G64_SMEM ((3 * ASTG + 3 * BSTG64) * 2)   // bytes = 82944

__global__ void __launch_bounds__(256, 2) gemm_f16_n64_kernel(
    const __half* __restrict__ A, const __half* __restrict__ Wt,
    const float* __restrict__ bias, void* __restrict__ Cout,
    int M, int N, int K, int relu, int out16)
{
    extern __shared__ __half sg[];
    __half* As = sg;
    __half* Bs = sg + 3 * ASTG;

    const int tid  = threadIdx.x;
    const int wid  = tid >> 5;
    const int lane = tid & 31;
    const int wm   = (wid & 3) * 32;
    const int wn   = (wid >> 2) * 32;
    const int m0   = blockIdx.y * 128;
    const int n0   = blockIdx.x * 64;

    float acc[2][4][4];
#pragma unroll
    for (int i = 0; i < 2; ++i)
#pragma unroll
        for (int j = 0; j < 4; ++j)
#pragma unroll
            for (int q = 0; q < 4; ++q) acc[i][j][q] = 0.f;

    const int ntiles = K / 64;
    const __half* Abase = A + (size_t)m0 * K;
    const __half* Bbase = Wt + (size_t)n0 * K;

    auto load_stage = [&](int t, int st) {
        int k0 = t * 64;
        __half* Ad = As + st * ASTG;
        __half* Bd = Bs + st * BSTG64;
#pragma unroll
        for (int it = 0; it < 4; ++it) {
            int idx = it * 256 + tid;
            int row = idx >> 3, col = (idx & 7) * 8;
            cp_async16(&Ad[row * STR64 + col], Abase + (size_t)row * K + k0 + col);
        }
#pragma unroll
        for (int it = 0; it < 2; ++it) {
            int idx = it * 256 + tid;
            int row = idx >> 3, col = (idx & 7) * 8;
            cp_async16(&Bd[row * STR64 + col], Bbase + (size_t)row * K + k0 + col);
        }
    };

    load_stage(0, 0); cp_commit();
    load_stage(1, 1); cp_commit();

    const int a_row = wm + (lane & 15);
    const int a_koff = (lane >> 4) * 8;
    const int b_row_base = wn + (lane & 7) + ((lane >> 4) * 8);
    const int b_koff = ((lane >> 3) & 1) * 8;

    for (int t = 0; t < ntiles; ++t) {
        cp_wait1();
        __syncthreads();

        int ps = t + 2;
        if (ps < ntiles) load_stage(ps, ps % 3);
        cp_commit();

        const int buf = t % 3;
        const __half* Ab = As + buf * ASTG;
        const __half* Bb = Bs + buf * BSTG64;
#pragma unroll
        for (int ks = 0; ks < 4; ++ks) {
            unsigned a[2][4];
            unsigned b[4][2];
#pragma unroll
            for (int im = 0; im < 2; ++im)
                ldsm_x4h(a[im][0], a[im][1], a[im][2], a[im][3],
                         &Ab[(a_row + im * 16) * STR64 + ks * 16 + a_koff]);
#pragma unroll
            for (int ng = 0; ng < 2; ++ng) {
                unsigned r0, r1, r2, r3;
                ldsm_x4h(r0, r1, r2, r3,
                         &Bb[(b_row_base + ng * 16) * STR64 + ks * 16 + b_koff]);
                b[ng * 2][0] = r0; b[ng * 2][1] = r1;
                b[ng * 2 + 1][0] = r2; b[ng * 2 + 1][1] = r3;
            }
#pragma unroll
            for (int im = 0; im < 2; ++im)
#pragma unroll
                for (int in = 0; in < 4; ++in)
                    mma_f16(acc[im][in][0], acc[im][in][1], acc[im][in][2], acc[im][in][3],
                            a[im][0], a[im][1], a[im][2], a[im][3],
                            b[in][0], b[in][1]);
        }
    }

    const int row_base = m0 + wm + (lane >> 2);
    const int col_base = n0 + wn + (lane & 3) * 2;
#pragma unroll
    for (int im = 0; im < 2; ++im) {
#pragma unroll
        for (int in = 0; in < 4; ++in) {
            int col = col_base + in * 8;
            float b0 = bias[col], b1 = bias[col + 1];
            int r0 = row_base + im * 16;
            float v0 = acc[im][in][0] + b0;
            float v1 = acc[im][in][1] + b1;
            float v2 = acc[im][in][2] + b0;
            float v3 = acc[im][in][3] + b1;
            if (relu) {
                v0 = fmaxf(v0, 0.f); v1 = fmaxf(v1, 0.f);
                v2 = fmaxf(v2, 0.f); v3 = fmaxf(v3, 0.f);
            }
            if (out16) {
                __half* C = (__half*)Cout;
                *reinterpret_cast<__half2*>(&C[(size_t)r0 * N + col]) = __floats2half2_rn(v0, v1);
                *reinterpret_cast<__half2*>(&C[(size_t)(r0 + 8) * N + col]) = __floats2half2_rn(v2, v3);
            } else {
                float* C = (float*)Cout;
                C[(size_t)r0 * N + col] = v0;
                C[(size_t)r0 * N + col + 1] = v1;
                C[(size_t)(r0 + 8) * N + col] = v2;
                C[(size_t)(r0 + 8) * N + col + 1] = v3;
            }
        }
    }
}

// ---------------------------------------------------------------------------
// FP16 flash self-attention (register P) — unchanged from R8.
// ---------------------------------------------------------------------------
#define ASTRH 72
#define KBUFH (64 * ASTRH)
#define ROWH 6144

__global__ void __launch_bounds__(256, 2) self_attn_f16_kernel(
    const __half* __restrict__ qkv, __half* __restrict__ out)
{
    extern __shared__ __half smh[];
    __half* Ps = smh;
    __half* Ks = smh + 128 * ASTRH;
    __half* Vs = Ks + 2 * KBUFH;

    const int tid = threadIdx.x;
    const int wid = tid >> 5;
    const int lane = tid & 31;
    const int b = blockIdx.y >> 3;
    const int h = blockIdx.y & 7;
    const int t0 = blockIdx.x * 128;
    const int wm = wid * 16;

    const __half* qbase = qkv + ((size_t)t0 * B_ + b) * 1536 + h * 64;
    const __half* kroot = qkv + (size_t)b * 1536 + 512 + h * 64;
    const __half* vroot = qkv + (size_t)b * 1536 + 1024 + h * 64;

#pragma unroll
    for (int i = 0; i < 4; ++i) {
        int idx = i * 256 + tid;
        int r = idx >> 3, c = (idx & 7) * 8;
        cp_async16(&Ps[r * ASTRH + c], qbase + (size_t)r * ROWH + c);
    }
#pragma unroll
    for (int i = 0; i < 2; ++i) {
        int idx = i * 256 + tid;
        int r = idx >> 3, c = (idx & 7) * 8;
        cp_async16(&Ks[r * ASTRH + c], kroot + (size_t)r * ROWH + c);
        cp_async16(&Vs[r * ASTRH + c], vroot + (size_t)r * ROWH + c);
    }
    cp_commit();
    cp_wait0();
    __syncthreads();

    unsigned qf[4][4];
    {
        const __half2 sc2 = __float2half2_rn(SCALE_);
        const int qrow = wm + (lane & 15);
        const int qko = (lane >> 4) * 8;
#pragma unroll
        for (int ks = 0; ks < 4; ++ks) {
            unsigned r0, r1, r2, r3;
            ldsm_x4h(r0, r1, r2, r3, &Ps[qrow * ASTRH + ks * 16 + qko]);
            unsigned rr[4] = {r0, r1, r2, r3};
#pragma unroll
            for (int j = 0; j < 4; ++j) {
                __half2 v = *reinterpret_cast<__half2*>(&rr[j]);
                v = __hmul2(v, sc2);
                qf[ks][j] = *reinterpret_cast<unsigned*>(&v);
            }
        }
    }

    float o[8][4];
#pragma unroll
    for (int n = 0; n < 8; ++n)
#pragma unroll
        for (int c = 0; c < 4; ++c) o[n][c] = 0.f;
    float m0 = -1e30f, m1 = -1e30f, l0 = 0.f, l1 = 0.f;

    const int brow_base = (lane & 7) + ((lane >> 4) * 8);
    const int bko = ((lane >> 3) & 1) * 8;
    const int prow0 = wm + (lane >> 2);
    const int pcol = 2 * (lane & 3);
    const int v_row = lane & 15;
    const int v_coff = (lane >> 4) * 8;

    for (int kt = 0; kt < 16; ++kt) {
        const int buf = kt & 1;

        if (kt + 1 < 16) {
            const __half* kb = kroot + (size_t)(kt + 1) * 64 * ROWH;
            const __half* vb = vroot + (size_t)(kt + 1) * 64 * ROWH;
            __half* kd = Ks + (buf ^ 1) * KBUFH;
            __half* vd = Vs + (buf ^ 1) * KBUFH;
#pragma unroll
            for (int i = 0; i < 2; ++i) {
                int idx = i * 256 + tid;
                int r = idx >> 3, c = (idx & 7) * 8;
                cp_async16(&kd[r * ASTRH + c], kb + (size_t)r * ROWH + c);
                cp_async16(&vd[r * ASTRH + c], vb + (size_t)r * ROWH + c);
            }
            cp_commit();
            cp_wait1();
        } else {
            cp_wait0();
        }
        __syncthreads();

        const __half* Kb = Ks + buf * KBUFH;
        float s[8][4];
#pragma unroll
        for (int n = 0; n < 8; ++n)
#pragma unroll
            for (int c = 0; c < 4; ++c) s[n][c] = 0.f;
#pragma unroll
        for (int ks = 0; ks < 4; ++ks) {
#pragma unroll
            for (int ng = 0; ng < 4; ++ng) {
                unsigned r0, r1, r2, r3;
                ldsm_x4h(r0, r1, r2, r3, &Kb[(brow_base + ng * 16) * ASTRH + ks * 16 + bko]);
                mma_f16(s[ng * 2][0], s[ng * 2][1], s[ng * 2][2], s[ng * 2][3],
                        qf[ks][0], qf[ks][1], qf[ks][2], qf[ks][3], r0, r1);
                mma_f16(s[ng * 2 + 1][0], s[ng * 2 + 1][1], s[ng * 2 + 1][2], s[ng * 2 + 1][3],
                        qf[ks][0], qf[ks][1], qf[ks][2], qf[ks][3], r2, r3);
            }
        }

        float mx0 = -1e30f, mx1 = -1e30f;
#pragma unroll
        for (int n = 0; n < 8; ++n) {
            mx0 = fmaxf(mx0, fmaxf(s[n][0], s[n][1]));
            mx1 = fmaxf(mx1, fmaxf(s[n][2], s[n][3]));
        }
        mx0 = fmaxf(mx0, __shfl_xor_sync(0xffffffffu, mx0, 1));
        mx0 = fmaxf(mx0, __shfl_xor_sync(0xffffffffu, mx0, 2));
        mx1 = fmaxf(mx1, __shfl_xor_sync(0xffffffffu, mx1, 1));
        mx1 = fmaxf(mx1, __shfl_xor_sync(0xffffffffu, mx1, 2));

        float mn0 = fmaxf(m0, mx0), mn1 = fmaxf(m1, mx1);
        float corr0 = __expf(m0 - mn0), corr1 = __expf(m1 - mn1);
        m0 = mn0; m1 = mn1;
        l0 *= corr0; l1 *= corr1;
#pragma unroll
        for (int n = 0; n < 8; ++n) {
            o[n][0] *= corr0; o[n][1] *= corr0;
            o[n][2] *= corr1; o[n][3] *= corr1;
        }

        unsigned pf[4][4];
#pragma unroll
        for (int j = 0; j < 4; ++j) {
            float p00 = __expf(s[2 * j][0] - mn0);
            float p01 = __expf(s[2 * j][1] - mn0);
            float p02 = __expf(s[2 * j][2] - mn1);
            float p03 = __expf(s[2 * j][3] - mn1);
            float p10 = __expf(s[2 * j + 1][0] - mn0);
            float p11 = __expf(s[2 * j + 1][1] - mn0);
            float p12 = __expf(s[2 * j + 1][2] - mn1);
            float p13 = __expf(s[2 * j + 1][3] - mn1);
            l0 += p00 + p01 + p10 + p11;
            l1 += p02 + p03 + p12 + p13;
            __half2 hh;
            hh = __floats2half2_rn(p00, p01); pf[j][0] = *reinterpret_cast<unsigned*>(&hh);
            hh = __floats2half2_rn(p02, p03); pf[j][1] = *reinterpret_cast<unsigned*>(&hh);
            hh = __floats2half2_rn(p10, p11); pf[j][2] = *reinterpret_cast<unsigned*>(&hh);
            hh = __floats2half2_rn(p12, p13); pf[j][3] = *reinterpret_cast<unsigned*>(&hh);
        }

        const __half* Vb = Vs + buf * KBUFH;
#pragma unroll
        for (int ks = 0; ks < 4; ++ks) {
#pragma unroll
            for (int ng = 0; ng < 4; ++ng) {
                unsigned r0, r1, r2, r3;
                ldsm_x4h_t(r0, r1, r2, r3,
                           &Vb[(ks * 16 + v_row) * ASTRH + ng * 16 + v_coff]);
                mma_f16(o[ng * 2][0], o[ng * 2][1], o[ng * 2][2], o[ng * 2][3],
                        pf[ks][0], pf[ks][1], pf[ks][2], pf[ks][3], r0, r1);
                mma_f16(o[ng * 2 + 1][0], o[ng * 2 + 1][1], o[ng * 2 + 1][2], o[ng * 2 + 1][3],
                        pf[ks][0], pf[ks][1], pf[ks][2], pf[ks][3], r2, r3);
            }
        }
        __syncthreads();
    }

    l0 += __shfl_xor_sync(0xffffffffu, l0, 1);
    l0 += __shfl_xor_sync(0xffffffffu, l0, 2);
    l1 += __shfl_xor_sync(0xffffffffu, l1, 1);
    l1 += __shfl_xor_sync(0xffffffffu, l1, 2);
    float inv0 = 1.f / l0, inv1 = 1.f / l1;

    __half* ob0 = out + ((size_t)(t0 + prow0) * B_ + b) * D_ + h * 64 + pcol;
    __half* ob1 = out + ((size_t)(t0 + prow0 + 8) * B_ + b) * D_ + h * 64 + pcol;
#pragma unroll
    for (int n = 0; n < 8; ++n) {
        *reinterpret_cast<__half2*>(ob0 + n * 8) = __floats2half2_rn(o[n][0] * inv0, o[n][1] * inv0);
        *reinterpret_cast<__half2*>(ob1 + n * 8) = __floats2half2_rn(o[n][2] * inv1, o[n][3] * inv1);
    }
}

#define ATTN_SMEM ((128 + 4 * 64) * ASTRH * 2)

// ---------------------------------------------------------------------------
// FP16 banded sliding-window attention (register P) — unchanged from R8.
// ---------------------------------------------------------------------------
__global__ void __launch_bounds__(256, 2) sw_attn_f16_kernel(
    const __half* __restrict__ q, const __half* __restrict__ kv,
    __half* __restrict__ out)
{
    extern __shared__ __half smh[];
    __half* Ps = smh;
    __half* Ks = smh + 128 * ASTRH;
    __half* Vs = Ks + 2 * KBUFH;

    const int tid = threadIdx.x;
    const int wid = tid >> 5;
    const int lane = tid & 31;
    const int b = blockIdx.y >> 3;
    const int h = blockIdx.y & 7;
    const int t0 = blockIdx.x * 128;
    const int wm = wid * 16;

#pragma unroll
    for (int i = 0; i < 4; ++i) {
        int idx = i * 256 + tid;
        int r = idx >> 3, c = (idx & 7) * 8;
        cp_async16(&Ps[r * ASTRH + c],
                   q + ((size_t)(t0 + r) * B_ + b) * D_ + h * 64 + c);
    }
    {
        int key0 = t0 - 16;
#pragma unroll
        for (int i = 0; i < 2; ++i) {
            int idx = i * 256 + tid;
            int r = idx >> 3, c = (idx & 7) * 8;
            int key = min(max(key0 + r, 0), S_ - 1);
            const __half* base = kv + ((size_t)key * B_ + b) * 1024 + h * 64;
            cp_async16(&Ks[r * ASTRH + c], base + c);
            cp_async16(&Vs[r * ASTRH + c], base + 512 + c);
        }
    }
    cp_commit();
    cp_wait0();
    __syncthreads();

    unsigned qf[4][4];
    {
        const __half2 sc2 = __float2half2_rn(SCALE_);
        const int qrow = wm + (lane & 15);
        const int qko = (lane >> 4) * 8;
#pragma unroll
        for (int ks = 0; ks < 4; ++ks) {
            unsigned r0, r1, r2, r3;
            ldsm_x4h(r0, r1, r2, r3, &Ps[qrow * ASTRH + ks * 16 + qko]);
            unsigned rr[4] = {r0, r1, r2, r3};
#pragma unroll
            for (int j = 0; j < 4; ++j) {
                __half2 v = *reinterpret_cast<__half2*>(&rr[j]);
                v = __hmul2(v, sc2);
                qf[ks][j] = *reinterpret_cast<unsigned*>(&v);
            }
        }
    }

    float o[8][4];
#pragma unroll
    for (int n = 0; n < 8; ++n)
#pragma unroll
        for (int c = 0; c < 4; ++c) o[n][c] = 0.f;
    float m0 = -1e30f, m1 = -1e30f, l0 = 0.f, l1 = 0.f;

    const int brow_base = (lane & 7) + ((lane >> 4) * 8);
    const int bko = ((lane >> 3) & 1) * 8;
    const int prow0 = wm + (lane >> 2);
    const int pcol = 2 * (lane & 3);
    const int v_row = lane & 15;
    const int v_coff = (lane >> 4) * 8;

    for (int kt = 0; kt < 3; ++kt) {
        const int buf = kt & 1;
        const int key0 = t0 - 16 + kt * 64;

        if (kt + 1 < 3) {
            int nk0 = t0 - 16 + (kt + 1) * 64;
            __half* kd = Ks + (buf ^ 1) * KBUFH;
            __half* vd = Vs + (buf ^ 1) * KBUFH;
#pragma unroll
            for (int i = 0; i < 2; ++i) {
                int idx = i * 256 + tid;
                int r = idx >> 3, c = (idx & 7) * 8;
                int key = min(max(nk0 + r, 0), S_ - 1);
                const __half* base = kv + ((size_t)key * B_ + b) * 1024 + h * 64;
                cp_async16(&kd[r * ASTRH + c], base + c);
                cp_async16(&vd[r * ASTRH + c], base + 512 + c);
            }
            cp_commit();
            cp_wait1();
        } else {
            cp_wait0();
        }
        __syncthreads();

        const __half* Kb = Ks + buf * KBUFH;
        float s[8][4];
#pragma unroll
        for (int n = 0; n < 8; ++n)
#pragma unroll
            for (int c = 0; c < 4; ++c) s[n][c] = 0.f;
#pragma unroll
        for (int ks = 0; ks < 4; ++ks) {
#pragma unroll
            for (int ng = 0; ng < 4; ++ng) {
                unsigned r0, r1, r2, r3;
                ldsm_x4h(r0, r1, r2, r3, &Kb[(brow_base + ng * 16) * ASTRH + ks * 16 + bko]);
                mma_f16(s[ng * 2][0], s[ng * 2][1], s[ng * 2][2], s[ng * 2][3],
                        qf[ks][0], qf[ks][1], qf[ks][2], qf[ks][3], r0, r1);
                mma_f16(s[ng * 2 + 1][0], s[ng * 2 + 1][1], s[ng * 2 + 1][2], s[ng * 2 + 1][3],
                        qf[ks][0], qf[ks][1], qf[ks][2], qf[ks][3], r2, r3);
            }
        }

#pragma unroll
        for (int n = 0; n < 8; ++n) {
#pragma unroll
            for (int c = 0; c < 4; ++c) {
                int key = key0 + n * 8 + pcol + (c & 1);
                int qg = t0 + prow0 + ((c >> 1) * 8);
                bool valid = (key >= 0) && (key < S_) && (key - qg <= W_) && (qg - key <= W_);
                if (!valid) s[n][c] = -1e38f;
            }
        }

        float mx0 = -1e30f, mx1 = -1e30f;
#pragma unroll
        for (int n = 0; n < 8; ++n) {
            mx0 = fmaxf(mx0, fmaxf(s[n][0], s[n][1]));
            mx1 = fmaxf(mx1, fmaxf(s[n][2], s[n][3]));
        }
        mx0 = fmaxf(mx0, __shfl_xor_sync(0xffffffffu, mx0, 1));
        mx0 = fmaxf(mx0, __shfl_xor_sync(0xffffffffu, mx0, 2));
        mx1 = fmaxf(mx1, __shfl_xor_sync(0xffffffffu, mx1, 1));
        mx1 = fmaxf(mx1, __shfl_xor_sync(0xffffffffu, mx1, 2));

        float mn0 = fmaxf(m0, mx0), mn1 = fmaxf(m1, mx1);
        float corr0 = __expf(m0 - mn0), corr1 = __expf(m1 - mn1);
        m0 = mn0; m1 = mn1;
        l0 *= corr0; l1 *= corr1;
#pragma unroll
        for (int n = 0; n < 8; ++n) {
            o[n][0] *= corr0; o[n][1] *= corr0;
            o[n][2] *= corr1; o[n][3] *= corr1;
        }

        unsigned pf[4][4];
#pragma unroll
        for (int j = 0; j < 4; ++j) {
            float p00 = __expf(s[2 * j][0] - mn0);
            float p01 = __expf(s[2 * j][1] - mn0);
            float p02 = __expf(s[2 * j][2] - mn1);
            float p03 = __expf(s[2 * j][3] - mn1);
            float p10 = __expf(s[2 * j + 1][0] - mn0);
            float p11 = __expf(s[2 * j + 1][1] - mn0);
            float p12 = __expf(s[2 * j + 1][2] - mn1);
            float p13 = __expf(s[2 * j + 1][3] - mn1);
            l0 += p00 + p01 + p10 + p11;
            l1 += p02 + p03 + p12 + p13;
            __half2 hh;
            hh = __floats2half2_rn(p00, p01); pf[j][0] = *reinterpret_cast<unsigned*>(&hh);
            hh = __floats2half2_rn(p02, p03); pf[j][1] = *reinterpret_cast<unsigned*>(&hh);
            hh = __floats2half2_rn(p10, p11); pf[j][2] = *reinterpret_cast<unsigned*>(&hh);
            hh = __floats2half2_rn(p12, p13); pf[j][3] = *reinterpret_cast<unsigned*>(&hh);
        }

        const __half* Vb = Vs + buf * KBUFH;
#pragma unroll
        for (int ks = 0; ks < 4; ++ks) {
#pragma unroll
            for (int ng = 0; ng < 4; ++ng) {
                unsigned r0, r1, r2, r3;
                ldsm_x4h_t(r0, r1, r2, r3,
                           &Vb[(ks * 16 + v_row) * ASTRH + ng * 16 + v_coff]);
                mma_f16(o[ng * 2][0], o[ng * 2][1], o[ng * 2][2], o[ng * 2][3],
                        pf[ks][0], pf[ks][1], pf[ks][2], pf[ks][3], r0, r1);
                mma_f16(o[ng * 2 + 1][0], o[ng * 2 + 1][1], o[ng * 2 + 1][2], o[ng * 2 + 1][3],
                        pf[ks][0], pf[ks][1], pf[ks][2], pf[ks][3], r2, r3);
            }
        }
        __syncthreads();
    }

    l0 += __shfl_xor_sync(0xffffffffu, l0, 1);
    l0 += __shfl_xor_sync(0xffffffffu, l0, 2);
    l1 += __shfl_xor_sync(0xffffffffu, l1, 1);
    l1 += __shfl_xor_sync(0xffffffffu, l1, 2);
    float inv0 = 1.f / l0, inv1 = 1.f / l1;

    __half* ob0 = out + ((size_t)(t0 + prow0) * B_ + b) * D_ + h * 64 + pcol;
    __half* ob1 = out + ((size_t)(t0 + prow0 + 8) * B_ + b) * D_ + h * 64 + pcol;
#pragma unroll
    for (int n = 0; n < 8; ++n) {
        *reinterpret_cast<__half2*>(ob0 + n * 8) = __floats2half2_rn(o[n][0] * inv0, o[n][1] * inv0);
        *reinterpret_cast<__half2*>(ob1 + n * 8) = __floats2half2_rn(o[n][2] * inv1, o[n][3] * inv1);
    }
}

// ---------------------------------------------------------------------------
// Fused residual-add(y fp16) + LayerNorm; fp32 out + optional fp16 out.
// ---------------------------------------------------------------------------
__global__ void __launch_bounds__(256) add_ln_h_kernel(
    const float* __restrict__ x, const __half* __restrict__ y,
    const float* __restrict__ g, const float* __restrict__ beta,
    float* __restrict__ out, __half* __restrict__ out16)
{
    __shared__ float sh[33];
    const int row = blockIdx.x;
    const int tid = threadIdx.x;
    const size_t base = (size_t)row * D_;

    float v0 = x[base + tid] + __half2float(y[base + tid]);
    float v1 = x[base + tid + 256] + __half2float(y[base + tid + 256]);

    float s = v0 + v1;
#pragma unroll
    for (int o = 16; o > 0; o >>= 1) s += __shfl_xor_sync(0xffffffffu, s, o);
    int lane = tid & 31, wid = tid >> 5;
    if (lane == 0) sh[wid] = s;
    __syncthreads();
    if (wid == 0) {
        float t = (lane < 8) ? sh[lane] : 0.f;
#pragma unroll
        for (int o = 4; o > 0; o >>= 1) t += __shfl_xor_sync(0xffffffffu, t, o);
        if (lane == 0) sh[32] = t;
    }
    __syncthreads();
    float mean = sh[32] * (1.f / D_);
    __syncthreads();

    float d0 = v0 - mean, d1 = v1 - mean;
    float sq = d0 * d0 + d1 * d1;
#pragma unroll
    for (int o = 16; o > 0; o >>= 1) sq += __shfl_xor_sync(0xffffffffu, sq, o);
    if (lane == 0) sh[wid] = sq;
    __syncthreads();
    if (wid == 0) {
        float t = (lane < 8) ? sh[lane] : 0.f;
#pragma unroll
        for (int o = 4; o > 0; o >>= 1) t += __shfl_xor_sync(0xffffffffu, t, o);
        if (lane == 0) sh[32] = t;
    }
    __syncthreads();
    float rstd = rsqrtf(sh[32] * (1.f / D_) + EPS_);

    float r0 = d0 * rstd * g[tid] + beta[tid];
    float r1 = d1 * rstd * g[tid + 256] + beta[tid + 256];
    out[base + tid] = r0;
    out[base + tid + 256] = r1;
    if (out16) {
        out16[base + tid] = __float2half_rn(r0);
        out16[base + tid + 256] = __float2half_rn(r1);
    }
}

// ---------------------------------------------------------------------------
// Launch
// ---------------------------------------------------------------------------
extern "C" void kernel_launch(void* const* d_in, const int* in_sizes, int n_in,
                              void* d_out, int out_size)
{
    (void)in_sizes; (void)n_in; (void)out_size;
    const float* tgt        = (const float*)d_in[0];
    const float* memory     = (const float*)d_in[1];
    const float* in_proj_w  = (const float*)d_in[2];
    const float* in_proj_b  = (const float*)d_in[3];
    const float* out_proj_w = (const float*)d_in[4];
    const float* out_proj_b = (const float*)d_in[5];
    const float* sw_q_w = (const float*)d_in[6];
    const float* sw_q_b = (const float*)d_in[7];
    const float* sw_k_w = (const float*)d_in[8];
    const float* sw_k_b = (const float*)d_in[9];
    const float* sw_v_w = (const float*)d_in[10];
    const float* sw_v_b = (const float*)d_in[11];
    const float* sw_o_w = (const float*)d_in[12];
    const float* sw_o_b = (const float*)d_in[13];
    const float* lin1_w = (const float*)d_in[14];
    const float* lin1_b = (const float*)d_in[15];
    const float* lin2_w = (const float*)d_in[16];
    const float* lin2_b = (const float*)d_in[17];
    const float* n1_g = (const float*)d_in[18];
    const float* n1_b = (const float*)d_in[19];
    const float* n2_g = (const float*)d_in[20];
    const float* n2_b = (const float*)d_in[21];
    const float* n3_g = (const float*)d_in[22];
    const float* n3_b = (const float*)d_in[23];
    float* out = (float*)d_out;

    float* s = nullptr;
    cudaGetSymbolAddress((void**)&s, g_scratch);
    float* x1   = s + FOFF_X1;
    float* x2   = s + FOFF_X2;
    float* bcat = s + FOFF_BCAT;
    __half* hb = (__half*)(s + HALF_BASE_F);
    __half* qkv16    = hb + HOFF_QKV;
    __half* attn16   = hb + HOFF_ATTN;
    __half* swq16    = hb + HOFF_SWQ;
    __half* swkv16   = hb + HOFF_SWKV;
    __half* swattn16 = hb + HOFF_SWATTN;
    __half* hbuf16   = hb + HOFF_HBUF;
    __half* tgt16    = hb + HOFF_TGT;
    __half* mem16    = hb + HOFF_MEM;
    __half* x1h      = hb + HOFF_X1H;
    __half* x2h      = hb + HOFF_X2H;
    __half* w_in     = hb + HOFF_WIN;
    __half* w_out    = hb + HOFF_WOUT;
    __half* w_swq    = hb + HOFF_WSWQ;
    __half* w_swkv   = hb + HOFF_WSWKV;
    __half* w_swo    = hb + HOFF_WSWO;
    __half* w_lin1   = hb + HOFF_WLIN1;
    __half* w_lin2   = hb + HOFF_WLIN2;
    __half* proj16   = hb + HOFF_PROJ16;
    __half* ff16     = hb + HOFF_FF16;

    cudaFuncSetAttribute(self_attn_f16_kernel,
                         cudaFuncAttributeMaxDynamicSharedMemorySize, ATTN_SMEM);
    cudaFuncSetAttribute(sw_attn_f16_kernel,
                         cudaFuncAttributeMaxDynamicSharedMemorySize, ATTN_SMEM);
    cudaFuncSetAttribute(gemm_f16_kernel,
                         cudaFuncAttributeMaxDynamicSharedMemorySize, G128_SMEM);
    cudaFuncSetAttribute(gemm_f16_n64_kernel,
                         cudaFuncAttributeMaxDynamicSharedMemorySize, G64_SMEM);

    // converts: one fused kernel + KV concat
    f2h_multi_kernel<<<7680, 256>>>(tgt, tgt16, memory, mem16,
                                    in_proj_w, w_in, out_proj_w, w_out,
                                    sw_q_w, w_swq, sw_o_w, w_swo,
                                    lin1_w, w_lin1, lin2_w, w_lin2);
    concat_kv16_kernel<<<1024, 256>>>(sw_k_w, sw_k_b, sw_v_w, sw_v_b, w_swkv, bcat);

    // fused KV projection of memory
    gemm_f16_kernel<<<dim3(8, 32), 256, G128_SMEM>>>(mem16, w_swkv, bcat, swkv16,
                                                     NROWS, 1024, D_, 0, 1);
    // QKV projection
    gemm_f16_kernel<<<dim3(12, 32), 256, G128_SMEM>>>(tgt16, w_in, in_proj_b, qkv16,
                                                      NROWS, 3 * D_, D_, 0, 1);
    // self attention
    self_attn_f16_kernel<<<dim3(8, 32), 256, ATTN_SMEM>>>(qkv16, attn16);
    // out projection -> fp16
    gemm_f16_n64_kernel<<<dim3(8, 32), 256, G64_SMEM>>>(attn16, w_out, out_proj_b, proj16,
                                                        NROWS, D_, D_, 0, 1);
    // add + LN1
    add_ln_h_kernel<<<NROWS, 256>>>(tgt, proj16, n1_g, n1_b, x1, x1h);
    // sw q projection
    gemm_f16_n64_kernel<<<dim3(8, 32), 256, G64_SMEM>>>(x1h, w_swq, sw_q_b, swq16,
                                                        NROWS, D_, D_, 0, 1);
    // banded attention
    sw_attn_f16_kernel<<<dim3(8, 32), 256, ATTN_SMEM>>>(swq16, swkv16, swattn16);
    // sw out projection -> fp16
    gemm_f16_n64_kernel<<<dim3(8, 32), 256, G64_SMEM>>>(swattn16, w_swo, sw_o_b, proj16,
                                                        NROWS, D_, D_, 0, 1);
    // add + LN2
    add_ln_h_kernel<<<NROWS, 256>>>(x1, proj16, n2_g, n2_b, x2, x2h);
    // FFN up + ReLU
    gemm_f16_kernel<<<dim3(16, 32), 256, G128_SMEM>>>(x2h, w_lin1, lin1_b, hbuf16,
                                                      NROWS, DFF_, D_, 1, 1);
    // FFN down -> fp16
    gemm_f16_n64_kernel<<<dim3(8, 32), 256, G64_SMEM>>>(hbuf16, w_lin2, lin2_b, ff16,
                                                        NROWS, D_, DFF_, 0, 1);
    // add + LN3 -> output (fp32 only)
    add_ln_h_kernel<<<NROWS, 256>>>(x2, ff16, n3_g, n3_b, out, nullptr);
}

// round 12
// speedup vs baseline: 6.7156x; 1.0153x over previous
#include <cuda_runtime.h>
#include <cuda_fp16.h>
#include <stdint.h>
#include <math.h>

#define T_ 1024
#define S_ 1024
#define B_ 4
#define D_ 512
#define H_ 8
#define HD_ 64
#define DFF_ 2048
#define W_ 16
#define NROWS (T_ * B_)
#define SCALE_ 0.125f
#define EPS_ 1e-5f

// fp32 region (float offsets)
#define FOFF_X1     0
#define FOFF_X2     2097152
#define FOFF_BCAT   4194304
#define HALF_BASE_F 5000000

// half region (half offsets)
#define HOFF_QKV    0
#define HOFF_ATTN   6291456
#define HOFF_SWQ    8388608
#define HOFF_SWKV   10485760
#define HOFF_SWATTN 14680064
#define HOFF_HBUF   16777216
#define HOFF_TGT    25165824
#define HOFF_MEM    27262976
#define HOFF_X1H    29360128
#define HOFF_X2H    31457280
#define HOFF_WIN    33554432
#define HOFF_WOUT   34340864
#define HOFF_WSWQ   34603008
#define HOFF_WSWKV  34865152
#define HOFF_WSWO   35389440
#define HOFF_WLIN1  35651584
#define HOFF_WLIN2  36700160
#define HOFF_PROJ16 37748736
#define HOFF_FF16   39845888

#define SCRATCH_FLOATS 33554432
__device__ float g_scratch[SCRATCH_FLOATS];

// ---------------------------------------------------------------------------
// PTX helpers
// ---------------------------------------------------------------------------
__device__ __forceinline__ void cp_async16(void* smem_ptr, const void* gmem_ptr) {
    unsigned saddr = (unsigned)__cvta_generic_to_shared(smem_ptr);
    asm volatile("cp.async.cg.shared.global [%0], [%1], 16;\n"
                 :: "r"(saddr), "l"(gmem_ptr));
}
__device__ __forceinline__ void cp_commit() {
    asm volatile("cp.async.commit_group;\n");
}
__device__ __forceinline__ void cp_wait0() {
    asm volatile("cp.async.wait_group 0;\n");
}
__device__ __forceinline__ void cp_wait1() {
    asm volatile("cp.async.wait_group 1;\n");
}
__device__ __forceinline__ void ldsm_x4h(unsigned& r0, unsigned& r1, unsigned& r2, unsigned& r3,
                                         const __half* p) {
    unsigned saddr = (unsigned)__cvta_generic_to_shared((void*)p);
    asm volatile("ldmatrix.sync.aligned.m8n8.x4.shared.b16 {%0,%1,%2,%3}, [%4];\n"
                 : "=r"(r0), "=r"(r1), "=r"(r2), "=r"(r3) : "r"(saddr));
}
__device__ __forceinline__ void ldsm_x4h_t(unsigned& r0, unsigned& r1, unsigned& r2, unsigned& r3,
                                           const __half* p) {
    unsigned saddr = (unsigned)__cvta_generic_to_shared((void*)p);
    asm volatile("ldmatrix.sync.aligned.m8n8.x4.trans.shared.b16 {%0,%1,%2,%3}, [%4];\n"
                 : "=r"(r0), "=r"(r1), "=r"(r2), "=r"(r3) : "r"(saddr));
}
__device__ __forceinline__ void mma_f16(float& c0, float& c1, float& c2, float& c3,
                                        unsigned a0, unsigned a1, unsigned a2, unsigned a3,
                                        unsigned b0, unsigned b1) {
    asm volatile("mma.sync.aligned.m16n8k16.row.col.f32.f16.f16.f32 "
                 "{%0,%1,%2,%3}, {%4,%5,%6,%7}, {%8,%9}, {%0,%1,%2,%3};\n"
                 : "+f"(c0), "+f"(c1), "+f"(c2), "+f"(c3)
                 : "r"(a0), "r"(a1), "r"(a2), "r"(a3), "r"(b0), "r"(b1));
}

// ---------------------------------------------------------------------------
// fp32->fp16 fused convert: 10 segments incl. KV weight concat + bias copy.
// Cumulative float counts:
//  tgt 2097152 | mem 4194304 | w_in 4980736 | w_out 5242880 | w_swq 5505024
//  w_swo 5767168 | w_lin1 6815744 | w_lin2 7864320 | kw 8126464 | vw 8388608
// ---------------------------------------------------------------------------
__global__ void __launch_bounds__(256) f2h_multi_kernel(
    const float* __restrict__ s0, __half* __restrict__ d0,
    const float* __restrict__ s1, __half* __restrict__ d1,
    const float* __restrict__ s2, __half* __restrict__ d2,
    const float* __restrict__ s3, __half* __restrict__ d3,
    const float* __restrict__ s4, __half* __restrict__ d4,
    const float* __restrict__ s5, __half* __restrict__ d5,
    const float* __restrict__ s6, __half* __restrict__ d6,
    const float* __restrict__ s7, __half* __restrict__ d7,
    const float* __restrict__ s8, __half* __restrict__ d8,
    const float* __restrict__ s9, __half* __restrict__ d9,
    const float* __restrict__ kb, const float* __restrict__ vb,
    float* __restrict__ bcat)
{
    if (blockIdx.x == 0) {
        // bias concat: 1024 floats
        int t = threadIdx.x;
        bcat[t] = kb[t];          bcat[512 + t] = vb[t];
        bcat[256 + t] = kb[256 + t]; bcat[768 + t] = vb[256 + t];
    }
    int idx = (blockIdx.x * 256 + threadIdx.x) * 4;
    const float* src; __half* dst; int off;
    if      (idx < 2097152) { src = s0; dst = d0; off = idx; }
    else if (idx < 4194304) { src = s1; dst = d1; off = idx - 2097152; }
    else if (idx < 4980736) { src = s2; dst = d2; off = idx - 4194304; }
    else if (idx < 5242880) { src = s3; dst = d3; off = idx - 4980736; }
    else if (idx < 5505024) { src = s4; dst = d4; off = idx - 5242880; }
    else if (idx < 5767168) { src = s5; dst = d5; off = idx - 5505024; }
    else if (idx < 6815744) { src = s6; dst = d6; off = idx - 5767168; }
    else if (idx < 7864320) { src = s7; dst = d7; off = idx - 6815744; }
    else if (idx < 8126464) { src = s8; dst = d8; off = idx - 7864320; }
    else                    { src = s9; dst = d9; off = idx - 8126464; }
    float4 v = *reinterpret_cast<const float4*>(src + off);
    *reinterpret_cast<__half2*>(dst + off)     = __floats2half2_rn(v.x, v.y);
    *reinterpret_cast<__half2*>(dst + off + 2) = __floats2half2_rn(v.z, v.w);
}

// ---------------------------------------------------------------------------
// FP16 GEMM 128x128, BK=64, 3-stage pipeline, dynamic smem.
// ---------------------------------------------------------------------------
#define STR64 72
#define ASTG (128 * STR64)
#define G128_SMEM (6 * ASTG * 2)

__global__ void __launch_bounds__(256, 2) gemm_f16_kernel(
    const __half* __restrict__ A, const __half* __restrict__ Wt,
    const float* __restrict__ bias, void* __restrict__ Cout,
    int M, int N, int K, int relu, int out16)
{
    extern __shared__ __half sg[];
    __half* As = sg;
    __half* Bs = sg + 3 * ASTG;

    const int tid  = threadIdx.x;
    const int wid  = tid >> 5;
    const int lane = tid & 31;
    const int wm   = (wid & 3) * 32;
    const int wn   = (wid >> 2) * 64;
    const int m0   = blockIdx.y * 128;
    const int n0   = blockIdx.x * 128;

    float acc[2][8][4];
#pragma unroll
    for (int i = 0; i < 2; ++i)
#pragma unroll
        for (int j = 0; j < 8; ++j)
#pragma unroll
            for (int q = 0; q < 4; ++q) acc[i][j][q] = 0.f;

    const int ntiles = K / 64;
    const __half* Abase = A + (size_t)m0 * K;
    const __half* Bbase = Wt + (size_t)n0 * K;

    auto load_stage = [&](int t, int st) {
        int k0 = t * 64;
        __half* Ad = As + st * ASTG;
        __half* Bd = Bs + st * ASTG;
#pragma unroll
        for (int it = 0; it < 4; ++it) {
            int idx = it * 256 + tid;
            int row = idx >> 3, col = (idx & 7) * 8;
            cp_async16(&Ad[row * STR64 + col], Abase + (size_t)row * K + k0 + col);
            cp_async16(&Bd[row * STR64 + col], Bbase + (size_t)row * K + k0 + col);
        }
    };

    load_stage(0, 0); cp_commit();
    load_stage(1, 1); cp_commit();

    const int a_row = wm + (lane & 15);
    const int a_koff = (lane >> 4) * 8;
    const int b_row_base = wn + (lane & 7) + ((lane >> 4) * 8);
    const int b_koff = ((lane >> 3) & 1) * 8;

    for (int t = 0; t < ntiles; ++t) {
        cp_wait1();
        __syncthreads();

        int ps = t + 2;
        if (ps < ntiles) load_stage(ps, ps % 3);
        cp_commit();

        const int buf = t % 3;
        const __half* Ab = As + buf * ASTG;
        const __half* Bb = Bs + buf * ASTG;
#pragma unroll
        for (int ks = 0; ks < 4; ++ks) {
            unsigned a[2][4];
            unsigned b[8][2];
#pragma unroll
            for (int im = 0; im < 2; ++im)
                ldsm_x4h(a[im][0], a[im][1], a[im][2], a[im][3],
                         &Ab[(a_row + im * 16) * STR64 + ks * 16 + a_koff]);
#pragma unroll
            for (int ng = 0; ng < 4; ++ng) {
                unsigned r0, r1, r2, r3;
                ldsm_x4h(r0, r1, r2, r3,
                         &Bb[(b_row_base + ng * 16) * STR64 + ks * 16 + b_koff]);
                b[ng * 2][0] = r0; b[ng * 2][1] = r1;
                b[ng * 2 + 1][0] = r2; b[ng * 2 + 1][1] = r3;
            }
#pragma unroll
            for (int im = 0; im < 2; ++im)
#pragma unroll
                for (int in = 0; in < 8; ++in)
                    mma_f16(acc[im][in][0], acc[im][in][1], acc[im][in][2], acc[im][in][3],
                            a[im][0], a[im][1], a[im][2], a[im][3],
                            b[in][0], b[in][1]);
        }
    }

    const int row_base = m0 + wm + (lane >> 2);
    const int col_base = n0 + wn + (lane & 3) * 2;
#pragma unroll
    for (int im = 0; im < 2; ++im) {
#pragma unroll
        for (int in = 0; in < 8; ++in) {
            int col = col_base + in * 8;
            float b0 = bias[col], b1 = bias[col + 1];
            int r0 = row_base + im * 16;
            float v0 = acc[im][in][0] + b0;
            float v1 = acc[im][in][1] + b1;
            float v2 = acc[im][in][2] + b0;
            float v3 = acc[im][in][3] + b1;
            if (relu) {
                v0 = fmaxf(v0, 0.f); v1 = fmaxf(v1, 0.f);
                v2 = fmaxf(v2, 0.f); v3 = fmaxf(v3, 0.f);
            }
            if (out16) {
                __half* C = (__half*)Cout;
                *reinterpret_cast<__half2*>(&C[(size_t)r0 * N + col]) = __floats2half2_rn(v0, v1);
                *reinterpret_cast<__half2*>(&C[(size_t)(r0 + 8) * N + col]) = __floats2half2_rn(v2, v3);
            } else {
                float* C = (float*)Cout;
                C[(size_t)r0 * N + col] = v0;
                C[(size_t)r0 * N + col + 1] = v1;
                C[(size_t)(r0 + 8) * N + col] = v2;
                C[(size_t)(r0 + 8) * N + col + 1] = v3;
            }
        }
    }
}

// ---------------------------------------------------------------------------
// FP16 GEMM 128x64, BK=64, 3-stage, register-pipelined fragments.
// ---------------------------------------------------------------------------
#define BSTG64 (64 * STR64)
#define G64_SMEM ((3 * ASTG + 3 * BSTG64) * 2)

__global__ void __launch_bounds__(256, 2) gemm_f16_n64_kernel(
    const __half* __restrict__ A, const __half* __restrict__ Wt,
    const float* __restrict__ bias, void* __restrict__ Cout,
    int M, int N, int K, int relu, int out16)
{
    extern __shared__ __half sg[];
    __half* As = sg;
    __half* Bs = sg + 3 * ASTG;

    const int tid  = threadIdx.x;
    const int wid  = tid >> 5;
    const int lane = tid & 31;
    const int wm   = (wid & 3) * 32;
    const int wn   = (wid >> 2) * 32;
    const int m0   = blockIdx.y * 128;
    const int n0   = blockIdx.x * 64;

    float acc[2][4][4];
#pragma unroll
    for (int i = 0; i < 2; ++i)
#pragma unroll
        for (int j = 0; j < 4; ++j)
#pragma unroll
            for (int q = 0; q < 4; ++q) acc[i][j][q] = 0.f;

    const int ntiles = K / 64;
    const __half* Abase = A + (size_t)m0 * K;
    const __half* Bbase = Wt + (size_t)n0 * K;

    auto load_stage = [&](int t, int st) {
        int k0 = t * 64;
        __half* Ad = As + st * ASTG;
        __half* Bd = Bs + st * BSTG64;
#pragma unroll
        for (int it = 0; it < 4; ++it) {
            int idx = it * 256 + tid;
            int row = idx >> 3, col = (idx & 7) * 8;
            cp_async16(&Ad[row * STR64 + col], Abase + (size_t)row * K + k0 + col);
        }
#pragma unroll
        for (int it = 0; it < 2; ++it) {
            int idx = it * 256 + tid;
            int row = idx >> 3, col = (idx & 7) * 8;
            cp_async16(&Bd[row * STR64 + col], Bbase + (size_t)row * K + k0 + col);
        }
    };

    load_stage(0, 0); cp_commit();
    load_stage(1, 1); cp_commit();

    const int a_row = wm + (lane & 15);
    const int a_koff = (lane >> 4) * 8;
    const int b_row_base = wn + (lane & 7) + ((lane >> 4) * 8);
    const int b_koff = ((lane >> 3) & 1) * 8;

    for (int t = 0; t < ntiles; ++t) {
        cp_wait1();
        __syncthreads();

        int ps = t + 2;
        if (ps < ntiles) load_stage(ps, ps % 3);
        cp_commit();

        const int buf = t % 3;
        const __half* Ab = As + buf * ASTG;
        const __half* Bb = Bs + buf * BSTG64;

        // register-pipelined fragments: prefetch ks+1 while mma on ks
        unsigned a[2][2][4];
        unsigned b[2][4][2];

        // preload ks = 0
#pragma unroll
        for (int im = 0; im < 2; ++im)
            ldsm_x4h(a[0][im][0], a[0][im][1], a[0][im][2], a[0][im][3],
                     &Ab[(a_row + im * 16) * STR64 + a_koff]);
#pragma unroll
        for (int ng = 0; ng < 2; ++ng) {
            unsigned r0, r1, r2, r3;
            ldsm_x4h(r0, r1, r2, r3, &Bb[(b_row_base + ng * 16) * STR64 + b_koff]);
            b[0][ng * 2][0] = r0; b[0][ng * 2][1] = r1;
            b[0][ng * 2 + 1][0] = r2; b[0][ng * 2 + 1][1] = r3;
        }

#pragma unroll
        for (int ks = 0; ks < 4; ++ks) {
            const int cur = ks & 1;
            if (ks < 3) {
                const int nxt = cur ^ 1;
#pragma unroll
                for (int im = 0; im < 2; ++im)
                    ldsm_x4h(a[nxt][im][0], a[nxt][im][1], a[nxt][im][2], a[nxt][im][3],
                             &Ab[(a_row + im * 16) * STR64 + (ks + 1) * 16 + a_koff]);
#pragma unroll
                for (int ng = 0; ng < 2; ++ng) {
                    unsigned r0, r1, r2, r3;
                    ldsm_x4h(r0, r1, r2, r3,
                             &Bb[(b_row_base + ng * 16) * STR64 + (ks + 1) * 16 + b_koff]);
                    b[nxt][ng * 2][0] = r0; b[nxt][ng * 2][1] = r1;
                    b[nxt][ng * 2 + 1][0] = r2; b[nxt][ng * 2 + 1][1] = r3;
                }
            }
#pragma unroll
            for (int im = 0; im < 2; ++im)
#pragma unroll
                for (int in = 0; in < 4; ++in)
                    mma_f16(acc[im][in][0], acc[im][in][1], acc[im][in][2], acc[im][in][3],
                            a[cur][im][0], a[cur][im][1], a[cur][im][2], a[cur][im][3],
                            b[cur][in][0], b[cur][in][1]);
        }
    }

    const int row_base = m0 + wm + (lane >> 2);
    const int col_base = n0 + wn + (lane & 3) * 2;
#pragma unroll
    for (int im = 0; im < 2; ++im) {
#pragma unroll
        for (int in = 0; in < 4; ++in) {
            int col = col_base + in * 8;
            float b0 = bias[col], b1 = bias[col + 1];
            int r0 = row_base + im * 16;
            float v0 = acc[im][in][0] + b0;
            float v1 = acc[im][in][1] + b1;
            float v2 = acc[im][in][2] + b0;
            float v3 = acc[im][in][3] + b1;
            if (relu) {
                v0 = fmaxf(v0, 0.f); v1 = fmaxf(v1, 0.f);
                v2 = fmaxf(v2, 0.f); v3 = fmaxf(v3, 0.f);
            }
            if (out16) {
                __half* C = (__half*)Cout;
                *reinterpret_cast<__half2*>(&C[(size_t)r0 * N + col]) = __floats2half2_rn(v0, v1);
                *reinterpret_cast<__half2*>(&C[(size_t)(r0 + 8) * N + col]) = __floats2half2_rn(v2, v3);
            } else {
                float* C = (float*)Cout;
                C[(size_t)r0 * N + col] = v0;
                C[(size_t)r0 * N + col + 1] = v1;
                C[(size_t)(r0 + 8) * N + col] = v2;
                C[(size_t)(r0 + 8) * N + col + 1] = v3;
            }
        }
    }
}

// ---------------------------------------------------------------------------
// FP16 flash self-attention (register P) — unchanged.
// ---------------------------------------------------------------------------
#define ASTRH 72
#define KBUFH (64 * ASTRH)
#define ROWH 6144

__global__ void __launch_bounds__(256, 2) self_attn_f16_kernel(
    const __half* __restrict__ qkv, __half* __restrict__ out)
{
    extern __shared__ __half smh[];
    __half* Ps = smh;
    __half* Ks = smh + 128 * ASTRH;
    __half* Vs = Ks + 2 * KBUFH;

    const int tid = threadIdx.x;
    const int wid = tid >> 5;
    const int lane = tid & 31;
    const int b = blockIdx.y >> 3;
    const int h = blockIdx.y & 7;
    const int t0 = blockIdx.x * 128;
    const int wm = wid * 16;

    const __half* qbase = qkv + ((size_t)t0 * B_ + b) * 1536 + h * 64;
    const __half* kroot = qkv + (size_t)b * 1536 + 512 + h * 64;
    const __half* vroot = qkv + (size_t)b * 1536 + 1024 + h * 64;

#pragma unroll
    for (int i = 0; i < 4; ++i) {
        int idx = i * 256 + tid;
        int r = idx >> 3, c = (idx & 7) * 8;
        cp_async16(&Ps[r * ASTRH + c], qbase + (size_t)r * ROWH + c);
    }
#pragma unroll
    for (int i = 0; i < 2; ++i) {
        int idx = i * 256 + tid;
        int r = idx >> 3, c = (idx & 7) * 8;
        cp_async16(&Ks[r * ASTRH + c], kroot + (size_t)r * ROWH + c);
        cp_async16(&Vs[r * ASTRH + c], vroot + (size_t)r * ROWH + c);
    }
    cp_commit();
    cp_wait0();
    __syncthreads();

    unsigned qf[4][4];
    {
        const __half2 sc2 = __float2half2_rn(SCALE_);
        const int qrow = wm + (lane & 15);
        const int qko = (lane >> 4) * 8;
#pragma unroll
        for (int ks = 0; ks < 4; ++ks) {
            unsigned r0, r1, r2, r3;
            ldsm_x4h(r0, r1, r2, r3, &Ps[qrow * ASTRH + ks * 16 + qko]);
            unsigned rr[4] = {r0, r1, r2, r3};
#pragma unroll
            for (int j = 0; j < 4; ++j) {
                __half2 v = *reinterpret_cast<__half2*>(&rr[j]);
                v = __hmul2(v, sc2);
                qf[ks][j] = *reinterpret_cast<unsigned*>(&v);
            }
        }
    }

    float o[8][4];
#pragma unroll
    for (int n = 0; n < 8; ++n)
#pragma unroll
        for (int c = 0; c < 4; ++c) o[n][c] = 0.f;
    float m0 = -1e30f, m1 = -1e30f, l0 = 0.f, l1 = 0.f;

    const int brow_base = (lane & 7) + ((lane >> 4) * 8);
    const int bko = ((lane >> 3) & 1) * 8;
    const int prow0 = wm + (lane >> 2);
    const int pcol = 2 * (lane & 3);
    const int v_row = lane & 15;
    const int v_coff = (lane >> 4) * 8;

    for (int kt = 0; kt < 16; ++kt) {
        const int buf = kt & 1;

        if (kt + 1 < 16) {
            const __half* kb = kroot + (size_t)(kt + 1) * 64 * ROWH;
            const __half* vb = vroot + (size_t)(kt + 1) * 64 * ROWH;
            __half* kd = Ks + (buf ^ 1) * KBUFH;
            __half* vd = Vs + (buf ^ 1) * KBUFH;
#pragma unroll
            for (int i = 0; i < 2; ++i) {
                int idx = i * 256 + tid;
                int r = idx >> 3, c = (idx & 7) * 8;
                cp_async16(&kd[r * ASTRH + c], kb + (size_t)r * ROWH + c);
                cp_async16(&vd[r * ASTRH + c], vb + (size_t)r * ROWH + c);
            }
            cp_commit();
            cp_wait1();
        } else {
            cp_wait0();
        }
        __syncthreads();

        const __half* Kb = Ks + buf * KBUFH;
        float s[8][4];
#pragma unroll
        for (int n = 0; n < 8; ++n)
#pragma unroll
            for (int c = 0; c < 4; ++c) s[n][c] = 0.f;
#pragma unroll
        for (int ks = 0; ks < 4; ++ks) {
#pragma unroll
            for (int ng = 0; ng < 4; ++ng) {
                unsigned r0, r1, r2, r3;
                ldsm_x4h(r0, r1, r2, r3, &Kb[(brow_base + ng * 16) * ASTRH + ks * 16 + bko]);
                mma_f16(s[ng * 2][0], s[ng * 2][1], s[ng * 2][2], s[ng * 2][3],
                        qf[ks][0], qf[ks][1], qf[ks][2], qf[ks][3], r0, r1);
                mma_f16(s[ng * 2 + 1][0], s[ng * 2 + 1][1], s[ng * 2 + 1][2], s[ng * 2 + 1][3],
                        qf[ks][0], qf[ks][1], qf[ks][2], qf[ks][3], r2, r3);
            }
        }

        float mx0 = -1e30f, mx1 = -1e30f;
#pragma unroll
        for (int n = 0; n < 8; ++n) {
            mx0 = fmaxf(mx0, fmaxf(s[n][0], s[n][1]));
            mx1 = fmaxf(mx1, fmaxf(s[n][2], s[n][3]));
        }
        mx0 = fmaxf(mx0, __shfl_xor_sync(0xffffffffu, mx0, 1));
        mx0 = fmaxf(mx0, __shfl_xor_sync(0xffffffffu, mx0, 2));
        mx1 = fmaxf(mx1, __shfl_xor_sync(0xffffffffu, mx1, 1));
        mx1 = fmaxf(mx1, __shfl_xor_sync(0xffffffffu, mx1, 2));

        float mn0 = fmaxf(m0, mx0), mn1 = fmaxf(m1, mx1);
        float corr0 = __expf(m0 - mn0), corr1 = __expf(m1 - mn1);
        m0 = mn0; m1 = mn1;
        l0 *= corr0; l1 *= corr1;
#pragma unroll
        for (int n = 0; n < 8; ++n) {
            o[n][0] *= corr0; o[n][1] *= corr0;
            o[n][2] *= corr1; o[n][3] *= corr1;
        }

        unsigned pf[4][4];
#pragma unroll
        for (int j = 0; j < 4; ++j) {
            float p00 = __expf(s[2 * j][0] - mn0);
            float p01 = __expf(s[2 * j][1] - mn0);
            float p02 = __expf(s[2 * j][2] - mn1);
            float p03 = __expf(s[2 * j][3] - mn1);
            float p10 = __expf(s[2 * j + 1][0] - mn0);
            float p11 = __expf(s[2 * j + 1][1] - mn0);
            float p12 = __expf(s[2 * j + 1][2] - mn1);
            float p13 = __expf(s[2 * j + 1][3] - mn1);
            l0 += p00 + p01 + p10 + p11;
            l1 += p02 + p03 + p12 + p13;
            __half2 hh;
            hh = __floats2half2_rn(p00, p01); pf[j][0] = *reinterpret_cast<unsigned*>(&hh);
            hh = __floats2half2_rn(p02, p03); pf[j][1] = *reinterpret_cast<unsigned*>(&hh);
            hh = __floats2half2_rn(p10, p11); pf[j][2] = *reinterpret_cast<unsigned*>(&hh);
            hh = __floats2half2_rn(p12, p13); pf[j][3] = *reinterpret_cast<unsigned*>(&hh);
        }

        const __half* Vb = Vs + buf * KBUFH;
#pragma unroll
        for (int ks = 0; ks < 4; ++ks) {
#pragma unroll
            for (int ng = 0; ng < 4; ++ng) {
                unsigned r0, r1, r2, r3;
                ldsm_x4h_t(r0, r1, r2, r3,
                           &Vb[(ks * 16 + v_row) * ASTRH + ng * 16 + v_coff]);
                mma_f16(o[ng * 2][0], o[ng * 2][1], o[ng * 2][2], o[ng * 2][3],
                        pf[ks][0], pf[ks][1], pf[ks][2], pf[ks][3], r0, r1);
                mma_f16(o[ng * 2 + 1][0], o[ng * 2 + 1][1], o[ng * 2 + 1][2], o[ng * 2 + 1][3],
                        pf[ks][0], pf[ks][1], pf[ks][2], pf[ks][3], r2, r3);
            }
        }
        __syncthreads();
    }

    l0 += __shfl_xor_sync(0xffffffffu, l0, 1);
    l0 += __shfl_xor_sync(0xffffffffu, l0, 2);
    l1 += __shfl_xor_sync(0xffffffffu, l1, 1);
    l1 += __shfl_xor_sync(0xffffffffu, l1, 2);
    float inv0 = 1.f / l0, inv1 = 1.f / l1;

    __half* ob0 = out + ((size_t)(t0 + prow0) * B_ + b) * D_ + h * 64 + pcol;
    __half* ob1 = out + ((size_t)(t0 + prow0 + 8) * B_ + b) * D_ + h * 64 + pcol;
#pragma unroll
    for (int n = 0; n < 8; ++n) {
        *reinterpret_cast<__half2*>(ob0 + n * 8) = __floats2half2_rn(o[n][0] * inv0, o[n][1] * inv0);
        *reinterpret_cast<__half2*>(ob1 + n * 8) = __floats2half2_rn(o[n][2] * inv1, o[n][3] * inv1);
    }
}

#define ATTN_SMEM ((128 + 4 * 64) * ASTRH * 2)

// ---------------------------------------------------------------------------
// FP16 banded sliding-window attention (register P) — unchanged.
// ---------------------------------------------------------------------------
__global__ void __launch_bounds__(256, 2) sw_attn_f16_kernel(
    const __half* __restrict__ q, const __half* __restrict__ kv,
    __half* __restrict__ out)
{
    extern __shared__ __half smh[];
    __half* Ps = smh;
    __half* Ks = smh + 128 * ASTRH;
    __half* Vs = Ks + 2 * KBUFH;

    const int tid = threadIdx.x;
    const int wid = tid >> 5;
    const int lane = tid & 31;
    const int b = blockIdx.y >> 3;
    const int h = blockIdx.y & 7;
    const int t0 = blockIdx.x * 128;
    const int wm = wid * 16;

#pragma unroll
    for (int i = 0; i < 4; ++i) {
        int idx = i * 256 + tid;
        int r = idx >> 3, c = (idx & 7) * 8;
        cp_async16(&Ps[r * ASTRH + c],
                   q + ((size_t)(t0 + r) * B_ + b) * D_ + h * 64 + c);
    }
    {
        int key0 = t0 - 16;
#pragma unroll
        for (int i = 0; i < 2; ++i) {
            int idx = i * 256 + tid;
            int r = idx >> 3, c = (idx & 7) * 8;
            int key = min(max(key0 + r, 0), S_ - 1);
            const __half* base = kv + ((size_t)key * B_ + b) * 1024 + h * 64;
            cp_async16(&Ks[r * ASTRH + c], base + c);
            cp_async16(&Vs[r * ASTRH + c], base + 512 + c);
        }
    }
    cp_commit();
    cp_wait0();
    __syncthreads();

    unsigned qf[4][4];
    {
        const __half2 sc2 = __float2half2_rn(SCALE_);
        const int qrow = wm + (lane & 15);
        const int qko = (lane >> 4) * 8;
#pragma unroll
        for (int ks = 0; ks < 4; ++ks) {
            unsigned r0, r1, r2, r3;
            ldsm_x4h(r0, r1, r2, r3, &Ps[qrow * ASTRH + ks * 16 + qko]);
            unsigned rr[4] = {r0, r1, r2, r3};
#pragma unroll
            for (int j = 0; j < 4; ++j) {
                __half2 v = *reinterpret_cast<__half2*>(&rr[j]);
                v = __hmul2(v, sc2);
                qf[ks][j] = *reinterpret_cast<unsigned*>(&v);
            }
        }
    }

    float o[8][4];
#pragma unroll
    for (int n = 0; n < 8; ++n)
#pragma unroll
        for (int c = 0; c < 4; ++c) o[n][c] = 0.f;
    float m0 = -1e30f, m1 = -1e30f, l0 = 0.f, l1 = 0.f;

    const int brow_base = (lane & 7) + ((lane >> 4) * 8);
    const int bko = ((lane >> 3) & 1) * 8;
    const int prow0 = wm + (lane >> 2);
    const int pcol = 2 * (lane & 3);
    const int v_row = lane & 15;
    const int v_coff = (lane >> 4) * 8;

    for (int kt = 0; kt < 3; ++kt) {
        const int buf = kt & 1;
        const int key0 = t0 - 16 + kt * 64;

        if (kt + 1 < 3) {
            int nk0 = t0 - 16 + (kt + 1) * 64;
            __half* kd = Ks + (buf ^ 1) * KBUFH;
            __half* vd = Vs + (buf ^ 1) * KBUFH;
#pragma unroll
            for (int i = 0; i < 2; ++i) {
                int idx = i * 256 + tid;
                int r = idx >> 3, c = (idx & 7) * 8;
                int key = min(max(nk0 + r, 0), S_ - 1);
                const __half* base = kv + ((size_t)key * B_ + b) * 1024 + h * 64;
                cp_async16(&kd[r * ASTRH + c], base + c);
                cp_async16(&vd[r * ASTRH + c], base + 512 + c);
            }
            cp_commit();
            cp_wait1();
        } else {
            cp_wait0();
        }
        __syncthreads();

        const __half* Kb = Ks + buf * KBUFH;
        float s[8][4];
#pragma unroll
        for (int n = 0; n < 8; ++n)
#pragma unroll
            for (int c = 0; c < 4; ++c) s[n][c] = 0.f;
#pragma unroll
        for (int ks = 0; ks < 4; ++ks) {
#pragma unroll
            for (int ng = 0; ng < 4; ++ng) {
                unsigned r0, r1, r2, r3;
                ldsm_x4h(r0, r1, r2, r3, &Kb[(brow_base + ng * 16) * ASTRH + ks * 16 + bko]);
                mma_f16(s[ng * 2][0], s[ng * 2][1], s[ng * 2][2], s[ng * 2][3],
                        qf[ks][0], qf[ks][1], qf[ks][2], qf[ks][3], r0, r1);
                mma_f16(s[ng * 2 + 1][0], s[ng * 2 + 1][1], s[ng * 2 + 1][2], s[ng * 2 + 1][3],
                        qf[ks][0], qf[ks][1], qf[ks][2], qf[ks][3], r2, r3);
            }
        }

#pragma unroll
        for (int n = 0; n < 8; ++n) {
#pragma unroll
            for (int c = 0; c < 4; ++c) {
                int key = key0 + n * 8 + pcol + (c & 1);
                int qg = t0 + prow0 + ((c >> 1) * 8);
                bool valid = (key >= 0) && (key < S_) && (key - qg <= W_) && (qg - key <= W_);
                if (!valid) s[n][c] = -1e38f;
            }
        }

        float mx0 = -1e30f, mx1 = -1e30f;
#pragma unroll
        for (int n = 0; n < 8; ++n) {
            mx0 = fmaxf(mx0, fmaxf(s[n][0], s[n][1]));
            mx1 = fmaxf(mx1, fmaxf(s[n][2], s[n][3]));
        }
        mx0 = fmaxf(mx0, __shfl_xor_sync(0xffffffffu, mx0, 1));
        mx0 = fmaxf(mx0, __shfl_xor_sync(0xffffffffu, mx0, 2));
        mx1 = fmaxf(mx1, __shfl_xor_sync(0xffffffffu, mx1, 1));
        mx1 = fmaxf(mx1, __shfl_xor_sync(0xffffffffu, mx1, 2));

        float mn0 = fmaxf(m0, mx0), mn1 = fmaxf(m1, mx1);
        float corr0 = __expf(m0 - mn0), corr1 = __expf(m1 - mn1);
        m0 = mn0; m1 = mn1;
        l0 *= corr0; l1 *= corr1;
#pragma unroll
        for (int n = 0; n < 8; ++n) {
            o[n][0] *= corr0; o[n][1] *= corr0;
            o[n][2] *= corr1; o[n][3] *= corr1;
        }

        unsigned pf[4][4];
#pragma unroll
        for (int j = 0; j < 4; ++j) {
            float p00 = __expf(s[2 * j][0] - mn0);
            float p01 = __expf(s[2 * j][1] - mn0);
            float p02 = __expf(s[2 * j][2] - mn1);
            float p03 = __expf(s[2 * j][3] - mn1);
            float p10 = __expf(s[2 * j + 1][0] - mn0);
            float p11 = __expf(s[2 * j + 1][1] - mn0);
            float p12 = __expf(s[2 * j + 1][2] - mn1);
            float p13 = __expf(s[2 * j + 1][3] - mn1);
            l0 += p00 + p01 + p10 + p11;
            l1 += p02 + p03 + p12 + p13;
            __half2 hh;
            hh = __floats2half2_rn(p00, p01); pf[j][0] = *reinterpret_cast<unsigned*>(&hh);
            hh = __floats2half2_rn(p02, p03); pf[j][1] = *reinterpret_cast<unsigned*>(&hh);
            hh = __floats2half2_rn(p10, p11); pf[j][2] = *reinterpret_cast<unsigned*>(&hh);
            hh = __floats2half2_rn(p12, p13); pf[j][3] = *reinterpret_cast<unsigned*>(&hh);
        }

        const __half* Vb = Vs + buf * KBUFH;
#pragma unroll
        for (int ks = 0; ks < 4; ++ks) {
#pragma unroll
            for (int ng = 0; ng < 4; ++ng) {
                unsigned r0, r1, r2, r3;
                ldsm_x4h_t(r0, r1, r2, r3,
                           &Vb[(ks * 16 + v_row) * ASTRH + ng * 16 + v_coff]);
                mma_f16(o[ng * 2][0], o[ng * 2][1], o[ng * 2][2], o[ng * 2][3],
                        pf[ks][0], pf[ks][1], pf[ks][2], pf[ks][3], r0, r1);
                mma_f16(o[ng * 2 + 1][0], o[ng * 2 + 1][1], o[ng * 2 + 1][2], o[ng * 2 + 1][3],
                        pf[ks][0], pf[ks][1], pf[ks][2], pf[ks][3], r2, r3);
            }
        }
        __syncthreads();
    }

    l0 += __shfl_xor_sync(0xffffffffu, l0, 1);
    l0 += __shfl_xor_sync(0xffffffffu, l0, 2);
    l1 += __shfl_xor_sync(0xffffffffu, l1, 1);
    l1 += __shfl_xor_sync(0xffffffffu, l1, 2);
    float inv0 = 1.f / l0, inv1 = 1.f / l1;

    __half* ob0 = out + ((size_t)(t0 + prow0) * B_ + b) * D_ + h * 64 + pcol;
    __half* ob1 = out + ((size_t)(t0 + prow0 + 8) * B_ + b) * D_ + h * 64 + pcol;
#pragma unroll
    for (int n = 0; n < 8; ++n) {
        *reinterpret_cast<__half2*>(ob0 + n * 8) = __floats2half2_rn(o[n][0] * inv0, o[n][1] * inv0);
        *reinterpret_cast<__half2*>(ob1 + n * 8) = __floats2half2_rn(o[n][2] * inv1, o[n][3] * inv1);
    }
}

// ---------------------------------------------------------------------------
// Fused residual-add(y fp16) + LayerNorm, single-pass (sum & sumsq together).
// ---------------------------------------------------------------------------
__global__ void __launch_bounds__(256) add_ln_h_kernel(
    const float* __restrict__ x, const __half* __restrict__ y,
    const float* __restrict__ g, const float* __restrict__ beta,
    float* __restrict__ out, __half* __restrict__ out16)
{
    __shared__ float shs[8];
    __shared__ float shq[8];
    __shared__ float sres[2];
    const int row = blockIdx.x;
    const int tid = threadIdx.x;
    const size_t base = (size_t)row * D_;

    float v0 = x[base + tid] + __half2float(y[base + tid]);
    float v1 = x[base + tid + 256] + __half2float(y[base + tid + 256]);

    float s = v0 + v1;
    float sq = v0 * v0 + v1 * v1;
#pragma unroll
    for (int o = 16; o > 0; o >>= 1) {
        s  += __shfl_xor_sync(0xffffffffu, s, o);
        sq += __shfl_xor_sync(0xffffffffu, sq, o);
    }
    int lane = tid & 31, wid = tid >> 5;
    if (lane == 0) { shs[wid] = s; shq[wid] = sq; }
    __syncthreads();
    if (wid == 0) {
        float ts = (lane < 8) ? shs[lane] : 0.f;
        float tq = (lane < 8) ? shq[lane] : 0.f;
#pragma unroll
        for (int o = 4; o > 0; o >>= 1) {
            ts += __shfl_xor_sync(0xffffffffu, ts, o);
            tq += __shfl_xor_sync(0xffffffffu, tq, o);
        }
        if (lane == 0) {
            float mean = ts * (1.f / D_);
            float var = tq * (1.f / D_) - mean * mean;
            sres[0] = mean;
            sres[1] = rsqrtf(var + EPS_);
        }
    }
    __syncthreads();
    float mean = sres[0];
    float rstd = sres[1];

    float r0 = (v0 - mean) * rstd * g[tid] + beta[tid];
    float r1 = (v1 - mean) * rstd * g[tid + 256] + beta[tid + 256];
    out[base + tid] = r0;
    out[base + tid + 256] = r1;
    if (out16) {
        out16[base + tid] = __float2half_rn(r0);
        out16[base + tid + 256] = __float2half_rn(r1);
    }
}

// ---------------------------------------------------------------------------
// Launch
// ---------------------------------------------------------------------------
extern "C" void kernel_launch(void* const* d_in, const int* in_sizes, int n_in,
                              void* d_out, int out_size)
{
    (void)in_sizes; (void)n_in; (void)out_size;
    const float* tgt        = (const float*)d_in[0];
    const float* memory     = (const float*)d_in[1];
    const float* in_proj_w  = (const float*)d_in[2];
    const float* in_proj_b  = (const float*)d_in[3];
    const float* out_proj_w = (const float*)d_in[4];
    const float* out_proj_b = (const float*)d_in[5];
    const float* sw_q_w = (const float*)d_in[6];
    const float* sw_q_b = (const float*)d_in[7];
    const float* sw_k_w = (const float*)d_in[8];
    const float* sw_k_b = (const float*)d_in[9];
    const float* sw_v_w = (const float*)d_in[10];
    const float* sw_v_b = (const float*)d_in[11];
    const float* sw_o_w = (const float*)d_in[12];
    const float* sw_o_b = (const float*)d_in[13];
    const float* lin1_w = (const float*)d_in[14];
    const float* lin1_b = (const float*)d_in[15];
    const float* lin2_w = (const float*)d_in[16];
    const float* lin2_b = (const float*)d_in[17];
    const float* n1_g = (const float*)d_in[18];
    const float* n1_b = (const float*)d_in[19];
    const float* n2_g = (const float*)d_in[20];
    const float* n2_b = (const float*)d_in[21];
    const float* n3_g = (const float*)d_in[22];
    const float* n3_b = (const float*)d_in[23];
    float* out = (float*)d_out;

    float* s = nullptr;
    cudaGetSymbolAddress((void**)&s, g_scratch);
    float* x1   = s + FOFF_X1;
    float* x2   = s + FOFF_X2;
    float* bcat = s + FOFF_BCAT;
    __half* hb = (__half*)(s + HALF_BASE_F);
    __half* qkv16    = hb + HOFF_QKV;
    __half* attn16   = hb + HOFF_ATTN;
    __half* swq16    = hb + HOFF_SWQ;
    __half* swkv16   = hb + HOFF_SWKV;
    __half* swattn16 = hb + HOFF_SWATTN;
    __half* hbuf16   = hb + HOFF_HBUF;
    __half* tgt16    = hb + HOFF_TGT;
    __half* mem16    = hb + HOFF_MEM;
    __half* x1h      = hb + HOFF_X1H;
    __half* x2h      = hb + HOFF_X2H;
    __half* w_in     = hb + HOFF_WIN;
    __half* w_out    = hb + HOFF_WOUT;
    __half* w_swq    = hb + HOFF_WSWQ;
    __half* w_swkv   = hb + HOFF_WSWKV;
    __half* w_swo    = hb + HOFF_WSWO;
    __half* w_lin1   = hb + HOFF_WLIN1;
    __half* w_lin2   = hb + HOFF_WLIN2;
    __half* proj16   = hb + HOFF_PROJ16;
    __half* ff16     = hb + HOFF_FF16;

    cudaFuncSetAttribute(self_attn_f16_kernel,
                         cudaFuncAttributeMaxDynamicSharedMemorySize, ATTN_SMEM);
    cudaFuncSetAttribute(sw_attn_f16_kernel,
                         cudaFuncAttributeMaxDynamicSharedMemorySize, ATTN_SMEM);
    cudaFuncSetAttribute(gemm_f16_kernel,
                         cudaFuncAttributeMaxDynamicSharedMemorySize, G128_SMEM);
    cudaFuncSetAttribute(gemm_f16_n64_kernel,
                         cudaFuncAttributeMaxDynamicSharedMemorySize, G64_SMEM);

    // one fused convert (incl. KV weight concat + bias concat)
    f2h_multi_kernel<<<8192, 256>>>(tgt, tgt16, memory, mem16,
                                    in_proj_w, w_in, out_proj_w, w_out,
                                    sw_q_w, w_swq, sw_o_w, w_swo,
                                    lin1_w, w_lin1, lin2_w, w_lin2,
                                    sw_k_w, w_swkv, sw_v_w, w_swkv + 262144,
                                    sw_k_b, sw_v_b, bcat);

    // fused KV projection of memory
    gemm_f16_kernel<<<dim3(8, 32), 256, G128_SMEM>>>(mem16, w_swkv, bcat, swkv16,
                                                     NROWS, 1024, D_, 0, 1);
    // QKV projection
    gemm_f16_kernel<<<dim3(12, 32), 256, G128_SMEM>>>(tgt16, w_in, in_proj_b, qkv16,
                                                      NROWS, 3 * D_, D_, 0, 1);
    // self attention
    self_attn_f16_kernel<<<dim3(8, 32), 256, ATTN_SMEM>>>(qkv16, attn16);
    // out projection -> fp16
    gemm_f16_n64_kernel<<<dim3(8, 32), 256, G64_SMEM>>>(attn16, w_out, out_proj_b, proj16,
                                                        NROWS, D_, D_, 0, 1);
    // add + LN1
    add_ln_h_kernel<<<NROWS, 256>>>(tgt, proj16, n1_g, n1_b, x1, x1h);
    // sw q projection
    gemm_f16_n64_kernel<<<dim3(8, 32), 256, G64_SMEM>>>(x1h, w_swq, sw_q_b, swq16,
                                                        NROWS, D_, D_, 0, 1);
    // banded attention
    sw_attn_f16_kernel<<<dim3(8, 32), 256, ATTN_SMEM>>>(swq16, swkv16, swattn16);
    // sw out projection -> fp16
    gemm_f16_n64_kernel<<<dim3(8, 32), 256, G64_SMEM>>>(swattn16, w_swo, sw_o_b, proj16,
                                                        NROWS, D_, D_, 0, 1);
    // add + LN2
    add_ln_h_kernel<<<NROWS, 256>>>(x1, proj16, n2_g, n2_b, x2, x2h);
    // FFN up + ReLU
    gemm_f16_kernel<<<dim3(16, 32), 256, G128_SMEM>>>(x2h, w_lin1, lin1_b, hbuf16,
                                                      NROWS, DFF_, D_, 1, 1);
    // FFN down -> fp16
    gemm_f16_n64_kernel<<<dim3(8, 32), 256, G64_SMEM>>>(hbuf16, w_lin2, lin2_b, ff16,
                                                        NROWS, D_, DFF_, 0, 1);
    // add + LN3 -> output (fp32 only)
    add_ln_h_kernel<<<NROWS, 256>>>(x2, ff16, n3_g, n3_b, out, nullptr);
}

// round 13
// speedup vs baseline: 6.8409x; 1.0187x over previous
#include <cuda_runtime.h>
#include <cuda_fp16.h>
#include <stdint.h>
#include <math.h>

#define T_ 1024
#define S_ 1024
#define B_ 4
#define D_ 512
#define H_ 8
#define HD_ 64
#define DFF_ 2048
#define W_ 16
#define NROWS (T_ * B_)
#define SCALE_ 0.125f
#define LOG2E_ 1.4426950408889634f
#define EPS_ 1e-5f

// fp32 region (float offsets)
#define FOFF_X1     0
#define FOFF_X2     2097152
#define FOFF_BCAT   4194304
#define HALF_BASE_F 5000000

// half region (half offsets)
#define HOFF_QKV    0
#define HOFF_ATTN   6291456
#define HOFF_SWQ    8388608
#define HOFF_SWKV   10485760
#define HOFF_SWATTN 14680064
#define HOFF_HBUF   16777216
#define HOFF_TGT    25165824
#define HOFF_MEM    27262976
#define HOFF_X1H    29360128
#define HOFF_X2H    31457280
#define HOFF_WIN    33554432
#define HOFF_WOUT   34340864
#define HOFF_WSWQ   34603008
#define HOFF_WSWKV  34865152
#define HOFF_WSWO   35389440
#define HOFF_WLIN1  35651584
#define HOFF_WLIN2  36700160
#define HOFF_PROJ16 37748736
#define HOFF_FF16   39845888

#define SCRATCH_FLOATS 33554432
__device__ float g_scratch[SCRATCH_FLOATS];

// ---------------------------------------------------------------------------
// PTX helpers
// ---------------------------------------------------------------------------
__device__ __forceinline__ void cp_async16(void* smem_ptr, const void* gmem_ptr) {
    unsigned saddr = (unsigned)__cvta_generic_to_shared(smem_ptr);
    asm volatile("cp.async.cg.shared.global [%0], [%1], 16;\n"
                 :: "r"(saddr), "l"(gmem_ptr));
}
__device__ __forceinline__ void cp_commit() {
    asm volatile("cp.async.commit_group;\n");
}
__device__ __forceinline__ void cp_wait0() {
    asm volatile("cp.async.wait_group 0;\n");
}
__device__ __forceinline__ void cp_wait1() {
    asm volatile("cp.async.wait_group 1;\n");
}
__device__ __forceinline__ void ldsm_x4h(unsigned& r0, unsigned& r1, unsigned& r2, unsigned& r3,
                                         const __half* p) {
    unsigned saddr = (unsigned)__cvta_generic_to_shared((void*)p);
    asm volatile("ldmatrix.sync.aligned.m8n8.x4.shared.b16 {%0,%1,%2,%3}, [%4];\n"
                 : "=r"(r0), "=r"(r1), "=r"(r2), "=r"(r3) : "r"(saddr));
}
__device__ __forceinline__ void ldsm_x4h_t(unsigned& r0, unsigned& r1, unsigned& r2, unsigned& r3,
                                           const __half* p) {
    unsigned saddr = (unsigned)__cvta_generic_to_shared((void*)p);
    asm volatile("ldmatrix.sync.aligned.m8n8.x4.trans.shared.b16 {%0,%1,%2,%3}, [%4];\n"
                 : "=r"(r0), "=r"(r1), "=r"(r2), "=r"(r3) : "r"(saddr));
}
__device__ __forceinline__ void mma_f16(float& c0, float& c1, float& c2, float& c3,
                                        unsigned a0, unsigned a1, unsigned a2, unsigned a3,
                                        unsigned b0, unsigned b1) {
    asm volatile("mma.sync.aligned.m16n8k16.row.col.f32.f16.f16.f32 "
                 "{%0,%1,%2,%3}, {%4,%5,%6,%7}, {%8,%9}, {%0,%1,%2,%3};\n"
                 : "+f"(c0), "+f"(c1), "+f"(c2), "+f"(c3)
                 : "r"(a0), "r"(a1), "r"(a2), "r"(a3), "r"(b0), "r"(b1));
}

// ---------------------------------------------------------------------------
// fp32->fp16 fused convert: 10 segments incl. KV weight concat + bias copy.
// ---------------------------------------------------------------------------
__global__ void __launch_bounds__(256) f2h_multi_kernel(
    const float* __restrict__ s0, __half* __restrict__ d0,
    const float* __restrict__ s1, __half* __restrict__ d1,
    const float* __restrict__ s2, __half* __restrict__ d2,
    const float* __restrict__ s3, __half* __restrict__ d3,
    const float* __restrict__ s4, __half* __restrict__ d4,
    const float* __restrict__ s5, __half* __restrict__ d5,
    const float* __restrict__ s6, __half* __restrict__ d6,
    const float* __restrict__ s7, __half* __restrict__ d7,
    const float* __restrict__ s8, __half* __restrict__ d8,
    const float* __restrict__ s9, __half* __restrict__ d9,
    const float* __restrict__ kb, const float* __restrict__ vb,
    float* __restrict__ bcat)
{
    if (blockIdx.x == 0) {
        int t = threadIdx.x;
        bcat[t] = kb[t];          bcat[512 + t] = vb[t];
        bcat[256 + t] = kb[256 + t]; bcat[768 + t] = vb[256 + t];
    }
    int idx = (blockIdx.x * 256 + threadIdx.x) * 4;
    const float* src; __half* dst; int off;
    if      (idx < 2097152) { src = s0; dst = d0; off = idx; }
    else if (idx < 4194304) { src = s1; dst = d1; off = idx - 2097152; }
    else if (idx < 4980736) { src = s2; dst = d2; off = idx - 4194304; }
    else if (idx < 5242880) { src = s3; dst = d3; off = idx - 4980736; }
    else if (idx < 5505024) { src = s4; dst = d4; off = idx - 5242880; }
    else if (idx < 5767168) { src = s5; dst = d5; off = idx - 5505024; }
    else if (idx < 6815744) { src = s6; dst = d6; off = idx - 5767168; }
    else if (idx < 7864320) { src = s7; dst = d7; off = idx - 6815744; }
    else if (idx < 8126464) { src = s8; dst = d8; off = idx - 7864320; }
    else                    { src = s9; dst = d9; off = idx - 8126464; }
    float4 v = *reinterpret_cast<const float4*>(src + off);
    *reinterpret_cast<__half2*>(dst + off)     = __floats2half2_rn(v.x, v.y);
    *reinterpret_cast<__half2*>(dst + off + 2) = __floats2half2_rn(v.z, v.w);
}

// ---------------------------------------------------------------------------
// FP16 GEMM 128x128 core (device function), BK=64, 3-stage pipeline.
// ---------------------------------------------------------------------------
#define STR64 72
#define ASTG (128 * STR64)
#define G128_SMEM (6 * ASTG * 2)

__device__ __forceinline__ void gemm128_body(
    const __half* __restrict__ A, const __half* __restrict__ Wt,
    const float* __restrict__ bias, void* __restrict__ Cout,
    int N, int K, int relu, int out16, int m0, int n0, __half* sg)
{
    __half* As = sg;
    __half* Bs = sg + 3 * ASTG;

    const int tid  = threadIdx.x;
    const int wid  = tid >> 5;
    const int lane = tid & 31;
    const int wm   = (wid & 3) * 32;
    const int wn   = (wid >> 2) * 64;

    float acc[2][8][4];
#pragma unroll
    for (int i = 0; i < 2; ++i)
#pragma unroll
        for (int j = 0; j < 8; ++j)
#pragma unroll
            for (int q = 0; q < 4; ++q) acc[i][j][q] = 0.f;

    const int ntiles = K / 64;
    const __half* Abase = A + (size_t)m0 * K;
    const __half* Bbase = Wt + (size_t)n0 * K;

    auto load_stage = [&](int t, int st) {
        int k0 = t * 64;
        __half* Ad = As + st * ASTG;
        __half* Bd = Bs + st * ASTG;
#pragma unroll
        for (int it = 0; it < 4; ++it) {
            int idx = it * 256 + tid;
            int row = idx >> 3, col = (idx & 7) * 8;
            cp_async16(&Ad[row * STR64 + col], Abase + (size_t)row * K + k0 + col);
            cp_async16(&Bd[row * STR64 + col], Bbase + (size_t)row * K + k0 + col);
        }
    };

    load_stage(0, 0); cp_commit();
    load_stage(1, 1); cp_commit();

    const int a_row = wm + (lane & 15);
    const int a_koff = (lane >> 4) * 8;
    const int b_row_base = wn + (lane & 7) + ((lane >> 4) * 8);
    const int b_koff = ((lane >> 3) & 1) * 8;

    for (int t = 0; t < ntiles; ++t) {
        cp_wait1();
        __syncthreads();

        int ps = t + 2;
        if (ps < ntiles) load_stage(ps, ps % 3);
        cp_commit();

        const int buf = t % 3;
        const __half* Ab = As + buf * ASTG;
        const __half* Bb = Bs + buf * ASTG;
#pragma unroll
        for (int ks = 0; ks < 4; ++ks) {
            unsigned a[2][4];
            unsigned b[8][2];
#pragma unroll
            for (int im = 0; im < 2; ++im)
                ldsm_x4h(a[im][0], a[im][1], a[im][2], a[im][3],
                         &Ab[(a_row + im * 16) * STR64 + ks * 16 + a_koff]);
#pragma unroll
            for (int ng = 0; ng < 4; ++ng) {
                unsigned r0, r1, r2, r3;
                ldsm_x4h(r0, r1, r2, r3,
                         &Bb[(b_row_base + ng * 16) * STR64 + ks * 16 + b_koff]);
                b[ng * 2][0] = r0; b[ng * 2][1] = r1;
                b[ng * 2 + 1][0] = r2; b[ng * 2 + 1][1] = r3;
            }
#pragma unroll
            for (int im = 0; im < 2; ++im)
#pragma unroll
                for (int in = 0; in < 8; ++in)
                    mma_f16(acc[im][in][0], acc[im][in][1], acc[im][in][2], acc[im][in][3],
                            a[im][0], a[im][1], a[im][2], a[im][3],
                            b[in][0], b[in][1]);
        }
    }

    const int row_base = m0 + wm + (lane >> 2);
    const int col_base = n0 + wn + (lane & 3) * 2;
#pragma unroll
    for (int im = 0; im < 2; ++im) {
#pragma unroll
        for (int in = 0; in < 8; ++in) {
            int col = col_base + in * 8;
            float b0 = bias[col], b1 = bias[col + 1];
            int r0 = row_base + im * 16;
            float v0 = acc[im][in][0] + b0;
            float v1 = acc[im][in][1] + b1;
            float v2 = acc[im][in][2] + b0;
            float v3 = acc[im][in][3] + b1;
            if (relu) {
                v0 = fmaxf(v0, 0.f); v1 = fmaxf(v1, 0.f);
                v2 = fmaxf(v2, 0.f); v3 = fmaxf(v3, 0.f);
            }
            if (out16) {
                __half* C = (__half*)Cout;
                *reinterpret_cast<__half2*>(&C[(size_t)r0 * N + col]) = __floats2half2_rn(v0, v1);
                *reinterpret_cast<__half2*>(&C[(size_t)(r0 + 8) * N + col]) = __floats2half2_rn(v2, v3);
            } else {
                float* C = (float*)Cout;
                C[(size_t)r0 * N + col] = v0;
                C[(size_t)r0 * N + col + 1] = v1;
                C[(size_t)(r0 + 8) * N + col] = v2;
                C[(size_t)(r0 + 8) * N + col + 1] = v3;
            }
        }
    }
}

__global__ void __launch_bounds__(256, 2) gemm_f16_kernel(
    const __half* __restrict__ A, const __half* __restrict__ Wt,
    const float* __restrict__ bias, void* __restrict__ Cout,
    int M, int N, int K, int relu, int out16)
{
    extern __shared__ __half sg[];
    gemm128_body(A, Wt, bias, Cout, N, K, relu, out16,
                 blockIdx.y * 128, blockIdx.x * 128, sg);
}

// Dual-problem GEMM: blockIdx.x < split -> problem 1, else problem 2.
__global__ void __launch_bounds__(256, 2) gemm_f16_dual_kernel(
    const __half* __restrict__ A1, const __half* __restrict__ W1,
    const float* __restrict__ b1, void* __restrict__ C1, int N1,
    const __half* __restrict__ A2, const __half* __restrict__ W2,
    const float* __restrict__ b2, void* __restrict__ C2, int N2,
    int K, int split)
{
    extern __shared__ __half sg[];
    if ((int)blockIdx.x < split)
        gemm128_body(A1, W1, b1, C1, N1, K, 0, 1,
                     blockIdx.y * 128, blockIdx.x * 128, sg);
    else
        gemm128_body(A2, W2, b2, C2, N2, K, 0, 1,
                     blockIdx.y * 128, (blockIdx.x - split) * 128, sg);
}

// ---------------------------------------------------------------------------
// FP16 GEMM 128x64, BK=64, 3-stage.
// ---------------------------------------------------------------------------
#define BSTG64 (64 * STR64)
#define G64_SMEM ((3 * ASTG + 3 * BSTG64) * 2)

__global__ void __launch_bounds__(256, 2) gemm_f16_n64_kernel(
    const __half* __restrict__ A, const __half* __restrict__ Wt,
    const float* __restrict__ bias, void* __restrict__ Cout,
    int M, int N, int K, int relu, int out16)
{
    extern __shared__ __half sg[];
    __half* As = sg;
    __half* Bs = sg + 3 * ASTG;

    const int tid  = threadIdx.x;
    const int wid  = tid >> 5;
    const int lane = tid & 31;
    const int wm   = (wid & 3) * 32;
    const int wn   = (wid >> 2) * 32;
    const int m0   = blockIdx.y * 128;
    const int n0   = blockIdx.x * 64;

    float acc[2][4][4];
#pragma unroll
    for (int i = 0; i < 2; ++i)
#pragma unroll
        for (int j = 0; j < 4; ++j)
#pragma unroll
            for (int q = 0; q < 4; ++q) acc[i][j][q] = 0.f;

    const int ntiles = K / 64;
    const __half* Abase = A + (size_t)m0 * K;
    const __half* Bbase = Wt + (size_t)n0 * K;

    auto load_stage = [&](int t, int st) {
        int k0 = t * 64;
        __half* Ad = As + st * ASTG;
        __half* Bd = Bs + st * BSTG64;
#pragma unroll
        for (int it = 0; it < 4; ++it) {
            int idx = it * 256 + tid;
            int row = idx >> 3, col = (idx & 7) * 8;
            cp_async16(&Ad[row * STR64 + col], Abase + (size_t)row * K + k0 + col);
        }
#pragma unroll
        for (int it = 0; it < 2; ++it) {
            int idx = it * 256 + tid;
            int row = idx >> 3, col = (idx & 7) * 8;
            cp_async16(&Bd[row * STR64 + col], Bbase + (size_t)row * K + k0 + col);
        }
    };

    load_stage(0, 0); cp_commit();
    load_stage(1, 1); cp_commit();

    const int a_row = wm + (lane & 15);
    const int a_koff = (lane >> 4) * 8;
    const int b_row_base = wn + (lane & 7) + ((lane >> 4) * 8);
    const int b_koff = ((lane >> 3) & 1) * 8;

    for (int t = 0; t < ntiles; ++t) {
        cp_wait1();
        __syncthreads();

        int ps = t + 2;
        if (ps < ntiles) load_stage(ps, ps % 3);
        cp_commit();

        const int buf = t % 3;
        const __half* Ab = As + buf * ASTG;
        const __half* Bb = Bs + buf * BSTG64;
#pragma unroll
        for (int ks = 0; ks < 4; ++ks) {
            unsigned a[2][4];
            unsigned b[4][2];
#pragma unroll
            for (int im = 0; im < 2; ++im)
                ldsm_x4h(a[im][0], a[im][1], a[im][2], a[im][3],
                         &Ab[(a_row + im * 16) * STR64 + ks * 16 + a_koff]);
#pragma unroll
            for (int ng = 0; ng < 2; ++ng) {
                unsigned r0, r1, r2, r3;
                ldsm_x4h(r0, r1, r2, r3,
                         &Bb[(b_row_base + ng * 16) * STR64 + ks * 16 + b_koff]);
                b[ng * 2][0] = r0; b[ng * 2][1] = r1;
                b[ng * 2 + 1][0] = r2; b[ng * 2 + 1][1] = r3;
            }
#pragma unroll
            for (int im = 0; im < 2; ++im)
#pragma unroll
                for (int in = 0; in < 4; ++in)
                    mma_f16(acc[im][in][0], acc[im][in][1], acc[im][in][2], acc[im][in][3],
                            a[im][0], a[im][1], a[im][2], a[im][3],
                            b[in][0], b[in][1]);
        }
    }

    const int row_base = m0 + wm + (lane >> 2);
    const int col_base = n0 + wn + (lane & 3) * 2;
#pragma unroll
    for (int im = 0; im < 2; ++im) {
#pragma unroll
        for (int in = 0; in < 4; ++in) {
            int col = col_base + in * 8;
            float b0 = bias[col], b1 = bias[col + 1];
            int r0 = row_base + im * 16;
            float v0 = acc[im][in][0] + b0;
            float v1 = acc[im][in][1] + b1;
            float v2 = acc[im][in][2] + b0;
            float v3 = acc[im][in][3] + b1;
            if (relu) {
                v0 = fmaxf(v0, 0.f); v1 = fmaxf(v1, 0.f);
                v2 = fmaxf(v2, 0.f); v3 = fmaxf(v3, 0.f);
            }
            if (out16) {
                __half* C = (__half*)Cout;
                *reinterpret_cast<__half2*>(&C[(size_t)r0 * N + col]) = __floats2half2_rn(v0, v1);
                *reinterpret_cast<__half2*>(&C[(size_t)(r0 + 8) * N + col]) = __floats2half2_rn(v2, v3);
            } else {
                float* C = (float*)Cout;
                C[(size_t)r0 * N + col] = v0;
                C[(size_t)r0 * N + col + 1] = v1;
                C[(size_t)(r0 + 8) * N + col] = v2;
                C[(size_t)(r0 + 8) * N + col + 1] = v3;
            }
        }
    }
}

// ---------------------------------------------------------------------------
// FP16 flash self-attention: 128-key tiles (softmax per 64-key half),
// register P, exp2-domain softmax.
// smem halfs: Ps[128*72] | Ks[2][128*72] | Vs[2][128*72]  (92160 B)
// ---------------------------------------------------------------------------
#define ASTRH 72
#define KB128 (128 * ASTRH)
#define ROWH 6144
#define ATTN_SMEM ((128 + 4 * 128) * ASTRH * 2)

__global__ void __launch_bounds__(256, 2) self_attn_f16_kernel(
    const __half* __restrict__ qkv, __half* __restrict__ out)
{
    extern __shared__ __half smh[];
    __half* Ps = smh;
    __half* Ks = smh + 128 * ASTRH;
    __half* Vs = Ks + 2 * KB128;

    const int tid = threadIdx.x;
    const int wid = tid >> 5;
    const int lane = tid & 31;
    const int b = blockIdx.y >> 3;
    const int h = blockIdx.y & 7;
    const int t0 = blockIdx.x * 128;
    const int wm = wid * 16;

    const __half* qbase = qkv + ((size_t)t0 * B_ + b) * 1536 + h * 64;
    const __half* kroot = qkv + (size_t)b * 1536 + 512 + h * 64;
    const __half* vroot = qkv + (size_t)b * 1536 + 1024 + h * 64;

#pragma unroll
    for (int i = 0; i < 4; ++i) {
        int idx = i * 256 + tid;
        int r = idx >> 3, c = (idx & 7) * 8;
        cp_async16(&Ps[r * ASTRH + c], qbase + (size_t)r * ROWH + c);
    }
    // K/V tile 0 (keys 0..127)
#pragma unroll
    for (int i = 0; i < 4; ++i) {
        int idx = i * 256 + tid;
        int r = idx >> 3, c = (idx & 7) * 8;
        cp_async16(&Ks[r * ASTRH + c], kroot + (size_t)r * ROWH + c);
        cp_async16(&Vs[r * ASTRH + c], vroot + (size_t)r * ROWH + c);
    }
    cp_commit();
    cp_wait0();
    __syncthreads();

    unsigned qf[4][4];
    {
        const __half2 sc2 = __float2half2_rn(SCALE_ * LOG2E_);
        const int qrow = wm + (lane & 15);
        const int qko = (lane >> 4) * 8;
#pragma unroll
        for (int ks = 0; ks < 4; ++ks) {
            unsigned r0, r1, r2, r3;
            ldsm_x4h(r0, r1, r2, r3, &Ps[qrow * ASTRH + ks * 16 + qko]);
            unsigned rr[4] = {r0, r1, r2, r3};
#pragma unroll
            for (int j = 0; j < 4; ++j) {
                __half2 v = *reinterpret_cast<__half2*>(&rr[j]);
                v = __hmul2(v, sc2);
                qf[ks][j] = *reinterpret_cast<unsigned*>(&v);
            }
        }
    }

    float o[8][4];
#pragma unroll
    for (int n = 0; n < 8; ++n)
#pragma unroll
        for (int c = 0; c < 4; ++c) o[n][c] = 0.f;
    float m0 = -1e30f, m1 = -1e30f, l0 = 0.f, l1 = 0.f;

    const int brow_base = (lane & 7) + ((lane >> 4) * 8);
    const int bko = ((lane >> 3) & 1) * 8;
    const int prow0 = wm + (lane >> 2);
    const int pcol = 2 * (lane & 3);
    const int v_row = lane & 15;
    const int v_coff = (lane >> 4) * 8;

    for (int kt = 0; kt < 8; ++kt) {
        const int buf = kt & 1;

        if (kt + 1 < 8) {
            const __half* kb = kroot + (size_t)(kt + 1) * 128 * ROWH;
            const __half* vb = vroot + (size_t)(kt + 1) * 128 * ROWH;
            __half* kd = Ks + (buf ^ 1) * KB128;
            __half* vd = Vs + (buf ^ 1) * KB128;
#pragma unroll
            for (int i = 0; i < 4; ++i) {
                int idx = i * 256 + tid;
                int r = idx >> 3, c = (idx & 7) * 8;
                cp_async16(&kd[r * ASTRH + c], kb + (size_t)r * ROWH + c);
                cp_async16(&vd[r * ASTRH + c], vb + (size_t)r * ROWH + c);
            }
            cp_commit();
            cp_wait1();
        } else {
            cp_wait0();
        }
        __syncthreads();

#pragma unroll
        for (int half = 0; half < 2; ++half) {
            const __half* Kb = Ks + buf * KB128 + half * 64 * ASTRH;
            const __half* Vb = Vs + buf * KB128 + half * 64 * ASTRH;

            float s[8][4];
#pragma unroll
            for (int n = 0; n < 8; ++n)
#pragma unroll
                for (int c = 0; c < 4; ++c) s[n][c] = 0.f;
#pragma unroll
            for (int ks = 0; ks < 4; ++ks) {
#pragma unroll
                for (int ng = 0; ng < 4; ++ng) {
                    unsigned r0, r1, r2, r3;
                    ldsm_x4h(r0, r1, r2, r3, &Kb[(brow_base + ng * 16) * ASTRH + ks * 16 + bko]);
                    mma_f16(s[ng * 2][0], s[ng * 2][1], s[ng * 2][2], s[ng * 2][3],
                            qf[ks][0], qf[ks][1], qf[ks][2], qf[ks][3], r0, r1);
                    mma_f16(s[ng * 2 + 1][0], s[ng * 2 + 1][1], s[ng * 2 + 1][2], s[ng * 2 + 1][3],
                            qf[ks][0], qf[ks][1], qf[ks][2], qf[ks][3], r2, r3);
                }
            }

            float mx0 = -1e30f, mx1 = -1e30f;
#pragma unroll
            for (int n = 0; n < 8; ++n) {
                mx0 = fmaxf(mx0, fmaxf(s[n][0], s[n][1]));
                mx1 = fmaxf(mx1, fmaxf(s[n][2], s[n][3]));
            }
            mx0 = fmaxf(mx0, __shfl_xor_sync(0xffffffffu, mx0, 1));
            mx0 = fmaxf(mx0, __shfl_xor_sync(0xffffffffu, mx0, 2));
            mx1 = fmaxf(mx1, __shfl_xor_sync(0xffffffffu, mx1, 1));
            mx1 = fmaxf(mx1, __shfl_xor_sync(0xffffffffu, mx1, 2));

            float mn0 = fmaxf(m0, mx0), mn1 = fmaxf(m1, mx1);
            float corr0 = exp2f(m0 - mn0), corr1 = exp2f(m1 - mn1);
            m0 = mn0; m1 = mn1;
            l0 *= corr0; l1 *= corr1;
#pragma unroll
            for (int n = 0; n < 8; ++n) {
                o[n][0] *= corr0; o[n][1] *= corr0;
                o[n][2] *= corr1; o[n][3] *= corr1;
            }

            unsigned pf[4][4];
#pragma unroll
            for (int j = 0; j < 4; ++j) {
                float p00 = exp2f(s[2 * j][0] - mn0);
                float p01 = exp2f(s[2 * j][1] - mn0);
                float p02 = exp2f(s[2 * j][2] - mn1);
                float p03 = exp2f(s[2 * j][3] - mn1);
                float p10 = exp2f(s[2 * j + 1][0] - mn0);
                float p11 = exp2f(s[2 * j + 1][1] - mn0);
                float p12 = exp2f(s[2 * j + 1][2] - mn1);
                float p13 = exp2f(s[2 * j + 1][3] - mn1);
                l0 += p00 + p01 + p10 + p11;
                l1 += p02 + p03 + p12 + p13;
                __half2 hh;
                hh = __floats2half2_rn(p00, p01); pf[j][0] = *reinterpret_cast<unsigned*>(&hh);
                hh = __floats2half2_rn(p02, p03); pf[j][1] = *reinterpret_cast<unsigned*>(&hh);
                hh = __floats2half2_rn(p10, p11); pf[j][2] = *reinterpret_cast<unsigned*>(&hh);
                hh = __floats2half2_rn(p12, p13); pf[j][3] = *reinterpret_cast<unsigned*>(&hh);
            }

#pragma unroll
            for (int ks = 0; ks < 4; ++ks) {
#pragma unroll
                for (int ng = 0; ng < 4; ++ng) {
                    unsigned r0, r1, r2, r3;
                    ldsm_x4h_t(r0, r1, r2, r3,
                               &Vb[(ks * 16 + v_row) * ASTRH + ng * 16 + v_coff]);
                    mma_f16(o[ng * 2][0], o[ng * 2][1], o[ng * 2][2], o[ng * 2][3],
                            pf[ks][0], pf[ks][1], pf[ks][2], pf[ks][3], r0, r1);
                    mma_f16(o[ng * 2 + 1][0], o[ng * 2 + 1][1], o[ng * 2 + 1][2], o[ng * 2 + 1][3],
                            pf[ks][0], pf[ks][1], pf[ks][2], pf[ks][3], r2, r3);
                }
            }
        }
        __syncthreads();
    }

    l0 += __shfl_xor_sync(0xffffffffu, l0, 1);
    l0 += __shfl_xor_sync(0xffffffffu, l0, 2);
    l1 += __shfl_xor_sync(0xffffffffu, l1, 1);
    l1 += __shfl_xor_sync(0xffffffffu, l1, 2);
    float inv0 = 1.f / l0, inv1 = 1.f / l1;

    __half* ob0 = out + ((size_t)(t0 + prow0) * B_ + b) * D_ + h * 64 + pcol;
    __half* ob1 = out + ((size_t)(t0 + prow0 + 8) * B_ + b) * D_ + h * 64 + pcol;
#pragma unroll
    for (int n = 0; n < 8; ++n) {
        *reinterpret_cast<__half2*>(ob0 + n * 8) = __floats2half2_rn(o[n][0] * inv0, o[n][1] * inv0);
        *reinterpret_cast<__half2*>(ob1 + n * 8) = __floats2half2_rn(o[n][2] * inv1, o[n][3] * inv1);
    }
}

// ---------------------------------------------------------------------------
// FP16 banded sliding-window attention (register P, exp2 softmax).
// ---------------------------------------------------------------------------
#define KBUFH (64 * ASTRH)
#define SWA_SMEM ((128 + 4 * 64) * ASTRH * 2)

__global__ void __launch_bounds__(256, 2) sw_attn_f16_kernel(
    const __half* __restrict__ q, const __half* __restrict__ kv,
    __half* __restrict__ out)
{
    extern __shared__ __half smh[];
    __half* Ps = smh;
    __half* Ks = smh + 128 * ASTRH;
    __half* Vs = Ks + 2 * KBUFH;

    const int tid = threadIdx.x;
    const int wid = tid >> 5;
    const int lane = tid & 31;
    const int b = blockIdx.y >> 3;
    const int h = blockIdx.y & 7;
    const int t0 = blockIdx.x * 128;
    const int wm = wid * 16;

#pragma unroll
    for (int i = 0; i < 4; ++i) {
        int idx = i * 256 + tid;
        int r = idx >> 3, c = (idx & 7) * 8;
        cp_async16(&Ps[r * ASTRH + c],
                   q + ((size_t)(t0 + r) * B_ + b) * D_ + h * 64 + c);
    }
    {
        int key0 = t0 - 16;
#pragma unroll
        for (int i = 0; i < 2; ++i) {
            int idx = i * 256 + tid;
            int r = idx >> 3, c = (idx & 7) * 8;
            int key = min(max(key0 + r, 0), S_ - 1);
            const __half* base = kv + ((size_t)key * B_ + b) * 1024 + h * 64;
            cp_async16(&Ks[r * ASTRH + c], base + c);
            cp_async16(&Vs[r * ASTRH + c], base + 512 + c);
        }
    }
    cp_commit();
    cp_wait0();
    __syncthreads();

    unsigned qf[4][4];
    {
        const __half2 sc2 = __float2half2_rn(SCALE_ * LOG2E_);
        const int qrow = wm + (lane & 15);
        const int qko = (lane >> 4) * 8;
#pragma unroll
        for (int ks = 0; ks < 4; ++ks) {
            unsigned r0, r1, r2, r3;
            ldsm_x4h(r0, r1, r2, r3, &Ps[qrow * ASTRH + ks * 16 + qko]);
            unsigned rr[4] = {r0, r1, r2, r3};
#pragma unroll
            for (int j = 0; j < 4; ++j) {
                __half2 v = *reinterpret_cast<__half2*>(&rr[j]);
                v = __hmul2(v, sc2);
                qf[ks][j] = *reinterpret_cast<unsigned*>(&v);
            }
        }
    }

    float o[8][4];
#pragma unroll
    for (int n = 0; n < 8; ++n)
#pragma unroll
        for (int c = 0; c < 4; ++c) o[n][c] = 0.f;
    float m0 = -1e30f, m1 = -1e30f, l0 = 0.f, l1 = 0.f;

    const int brow_base = (lane & 7) + ((lane >> 4) * 8);
    const int bko = ((lane >> 3) & 1) * 8;
    const int prow0 = wm + (lane >> 2);
    const int pcol = 2 * (lane & 3);
    const int v_row = lane & 15;
    const int v_coff = (lane >> 4) * 8;

    for (int kt = 0; kt < 3; ++kt) {
        const int buf = kt & 1;
        const int key0 = t0 - 16 + kt * 64;

        if (kt + 1 < 3) {
            int nk0 = t0 - 16 + (kt + 1) * 64;
            __half* kd = Ks + (buf ^ 1) * KBUFH;
            __half* vd = Vs + (buf ^ 1) * KBUFH;
#pragma unroll
            for (int i = 0; i < 2; ++i) {
                int idx = i * 256 + tid;
                int r = idx >> 3, c = (idx & 7) * 8;
                int key = min(max(nk0 + r, 0), S_ - 1);
                const __half* base = kv + ((size_t)key * B_ + b) * 1024 + h * 64;
                cp_async16(&kd[r * ASTRH + c], base + c);
                cp_async16(&vd[r * ASTRH + c], base + 512 + c);
            }
            cp_commit();
            cp_wait1();
        } else {
            cp_wait0();
        }
        __syncthreads();

        const __half* Kb = Ks + buf * KBUFH;
        float s[8][4];
#pragma unroll
        for (int n = 0; n < 8; ++n)
#pragma unroll
            for (int c = 0; c < 4; ++c) s[n][c] = 0.f;
#pragma unroll
        for (int ks = 0; ks < 4; ++ks) {
#pragma unroll
            for (int ng = 0; ng < 4; ++ng) {
                unsigned r0, r1, r2, r3;
                ldsm_x4h(r0, r1, r2, r3, &Kb[(brow_base + ng * 16) * ASTRH + ks * 16 + bko]);
                mma_f16(s[ng * 2][0], s[ng * 2][1], s[ng * 2][2], s[ng * 2][3],
                        qf[ks][0], qf[ks][1], qf[ks][2], qf[ks][3], r0, r1);
                mma_f16(s[ng * 2 + 1][0], s[ng * 2 + 1][1], s[ng * 2 + 1][2], s[ng * 2 + 1][3],
                        qf[ks][0], qf[ks][1], qf[ks][2], qf[ks][3], r2, r3);
            }
        }

#pragma unroll
        for (int n = 0; n < 8; ++n) {
#pragma unroll
            for (int c = 0; c < 4; ++c) {
                int key = key0 + n * 8 + pcol + (c & 1);
                int qg = t0 + prow0 + ((c >> 1) * 8);
                bool valid = (key >= 0) && (key < S_) && (key - qg <= W_) && (qg - key <= W_);
                if (!valid) s[n][c] = -1e38f;
            }
        }

        float mx0 = -1e30f, mx1 = -1e30f;
#pragma unroll
        for (int n = 0; n < 8; ++n) {
            mx0 = fmaxf(mx0, fmaxf(s[n][0], s[n][1]));
            mx1 = fmaxf(mx1, fmaxf(s[n][2], s[n][3]));
        }
        mx0 = fmaxf(mx0, __shfl_xor_sync(0xffffffffu, mx0, 1));
        mx0 = fmaxf(mx0, __shfl_xor_sync(0xffffffffu, mx0, 2));
        mx1 = fmaxf(mx1, __shfl_xor_sync(0xffffffffu, mx1, 1));
        mx1 = fmaxf(mx1, __shfl_xor_sync(0xffffffffu, mx1, 2));

        float mn0 = fmaxf(m0, mx0), mn1 = fmaxf(m1, mx1);
        float corr0 = exp2f(m0 - mn0), corr1 = exp2f(m1 - mn1);
        m0 = mn0; m1 = mn1;
        l0 *= corr0; l1 *= corr1;
#pragma unroll
        for (int n = 0; n < 8; ++n) {
            o[n][0] *= corr0; o[n][1] *= corr0;
            o[n][2] *= corr1; o[n][3] *= corr1;
        }

        unsigned pf[4][4];
#pragma unroll
        for (int j = 0; j < 4; ++j) {
            float p00 = exp2f(s[2 * j][0] - mn0);
            float p01 = exp2f(s[2 * j][1] - mn0);
            float p02 = exp2f(s[2 * j][2] - mn1);
            float p03 = exp2f(s[2 * j][3] - mn1);
            float p10 = exp2f(s[2 * j + 1][0] - mn0);
            float p11 = exp2f(s[2 * j + 1][1] - mn0);
            float p12 = exp2f(s[2 * j + 1][2] - mn1);
            float p13 = exp2f(s[2 * j + 1][3] - mn1);
            l0 += p00 + p01 + p10 + p11;
            l1 += p02 + p03 + p12 + p13;
            __half2 hh;
            hh = __floats2half2_rn(p00, p01); pf[j][0] = *reinterpret_cast<unsigned*>(&hh);
            hh = __floats2half2_rn(p02, p03); pf[j][1] = *reinterpret_cast<unsigned*>(&hh);
            hh = __floats2half2_rn(p10, p11); pf[j][2] = *reinterpret_cast<unsigned*>(&hh);
            hh = __floats2half2_rn(p12, p13); pf[j][3] = *reinterpret_cast<unsigned*>(&hh);
        }

        const __half* Vb = Vs + buf * KBUFH;
#pragma unroll
        for (int ks = 0; ks < 4; ++ks) {
#pragma unroll
            for (int ng = 0; ng < 4; ++ng) {
                unsigned r0, r1, r2, r3;
                ldsm_x4h_t(r0, r1, r2, r3,
                           &Vb[(ks * 16 + v_row) * ASTRH + ng * 16 + v_coff]);
                mma_f16(o[ng * 2][0], o[ng * 2][1], o[ng * 2][2], o[ng * 2][3],
                        pf[ks][0], pf[ks][1], pf[ks][2], pf[ks][3], r0, r1);
                mma_f16(o[ng * 2 + 1][0], o[ng * 2 + 1][1], o[ng * 2 + 1][2], o[ng * 2 + 1][3],
                        pf[ks][0], pf[ks][1], pf[ks][2], pf[ks][3], r2, r3);
            }
        }
        __syncthreads();
    }

    l0 += __shfl_xor_sync(0xffffffffu, l0, 1);
    l0 += __shfl_xor_sync(0xffffffffu, l0, 2);
    l1 += __shfl_xor_sync(0xffffffffu, l1, 1);
    l1 += __shfl_xor_sync(0xffffffffu, l1, 2);
    float inv0 = 1.f / l0, inv1 = 1.f / l1;

    __half* ob0 = out + ((size_t)(t0 + prow0) * B_ + b) * D_ + h * 64 + pcol;
    __half* ob1 = out + ((size_t)(t0 + prow0 + 8) * B_ + b) * D_ + h * 64 + pcol;
#pragma unroll
    for (int n = 0; n < 8; ++n) {
        *reinterpret_cast<__half2*>(ob0 + n * 8) = __floats2half2_rn(o[n][0] * inv0, o[n][1] * inv0);
        *reinterpret_cast<__half2*>(ob1 + n * 8) = __floats2half2_rn(o[n][2] * inv1, o[n][3] * inv1);
    }
}

// ---------------------------------------------------------------------------
// Fused residual-add(y fp16) + LayerNorm, single-pass.
// ---------------------------------------------------------------------------
__global__ void __launch_bounds__(256) add_ln_h_kernel(
    const float* __restrict__ x, const __half* __restrict__ y,
    const float* __restrict__ g, const float* __restrict__ beta,
    float* __restrict__ out, __half* __restrict__ out16)
{
    __shared__ float shs[8];
    __shared__ float shq[8];
    __shared__ float sres[2];
    const int row = blockIdx.x;
    const int tid = threadIdx.x;
    const size_t base = (size_t)row * D_;

    float v0 = x[base + tid] + __half2float(y[base + tid]);
    float v1 = x[base + tid + 256] + __half2float(y[base + tid + 256]);

    float s = v0 + v1;
    float sq = v0 * v0 + v1 * v1;
#pragma unroll
    for (int o = 16; o > 0; o >>= 1) {
        s  += __shfl_xor_sync(0xffffffffu, s, o);
        sq += __shfl_xor_sync(0xffffffffu, sq, o);
    }
    int lane = tid & 31, wid = tid >> 5;
    if (lane == 0) { shs[wid] = s; shq[wid] = sq; }
    __syncthreads();
    if (wid == 0) {
        float ts = (lane < 8) ? shs[lane] : 0.f;
        float tq = (lane < 8) ? shq[lane] : 0.f;
#pragma unroll
        for (int o = 4; o > 0; o >>= 1) {
            ts += __shfl_xor_sync(0xffffffffu, ts, o);
            tq += __shfl_xor_sync(0xffffffffu, tq, o);
        }
        if (lane == 0) {
            float mean = ts * (1.f / D_);
            float var = tq * (1.f / D_) - mean * mean;
            sres[0] = mean;
            sres[1] = rsqrtf(var + EPS_);
        }
    }
    __syncthreads();
    float mean = sres[0];
    float rstd = sres[1];

    float r0 = (v0 - mean) * rstd * g[tid] + beta[tid];
    float r1 = (v1 - mean) * rstd * g[tid + 256] + beta[tid + 256];
    out[base + tid] = r0;
    out[base + tid + 256] = r1;
    if (out16) {
        out16[base + tid] = __float2half_rn(r0);
        out16[base + tid + 256] = __float2half_rn(r1);
    }
}

// ---------------------------------------------------------------------------
// Launch
// ---------------------------------------------------------------------------
extern "C" void kernel_launch(void* const* d_in, const int* in_sizes, int n_in,
                              void* d_out, int out_size)
{
    (void)in_sizes; (void)n_in; (void)out_size;
    const float* tgt        = (const float*)d_in[0];
    const float* memory     = (const float*)d_in[1];
    const float* in_proj_w  = (const float*)d_in[2];
    const float* in_proj_b  = (const float*)d_in[3];
    const float* out_proj_w = (const float*)d_in[4];
    const float* out_proj_b = (const float*)d_in[5];
    const float* sw_q_w = (const float*)d_in[6];
    const float* sw_q_b = (const float*)d_in[7];
    const float* sw_k_w = (const float*)d_in[8];
    const float* sw_k_b = (const float*)d_in[9];
    const float* sw_v_w = (const float*)d_in[10];
    const float* sw_v_b = (const float*)d_in[11];
    const float* sw_o_w = (const float*)d_in[12];
    const float* sw_o_b = (const float*)d_in[13];
    const float* lin1_w = (const float*)d_in[14];
    const float* lin1_b = (const float*)d_in[15];
    const float* lin2_w = (const float*)d_in[16];
    const float* lin2_b = (const float*)d_in[17];
    const float* n1_g = (const float*)d_in[18];
    const float* n1_b = (const float*)d_in[19];
    const float* n2_g = (const float*)d_in[20];
    const float* n2_b = (const float*)d_in[21];
    const float* n3_g = (const float*)d_in[22];
    const float* n3_b = (const float*)d_in[23];
    float* out = (float*)d_out;

    float* s = nullptr;
    cudaGetSymbolAddress((void**)&s, g_scratch);
    float* x1   = s + FOFF_X1;
    float* x2   = s + FOFF_X2;
    float* bcat = s + FOFF_BCAT;
    __half* hb = (__half*)(s + HALF_BASE_F);
    __half* qkv16    = hb + HOFF_QKV;
    __half* attn16   = hb + HOFF_ATTN;
    __half* swq16    = hb + HOFF_SWQ;
    __half* swkv16   = hb + HOFF_SWKV;
    __half* swattn16 = hb + HOFF_SWATTN;
    __half* hbuf16   = hb + HOFF_HBUF;
    __half* tgt16    = hb + HOFF_TGT;
    __half* mem16    = hb + HOFF_MEM;
    __half* x1h      = hb + HOFF_X1H;
    __half* x2h      = hb + HOFF_X2H;
    __half* w_in     = hb + HOFF_WIN;
    __half* w_out    = hb + HOFF_WOUT;
    __half* w_swq    = hb + HOFF_WSWQ;
    __half* w_swkv   = hb + HOFF_WSWKV;
    __half* w_swo    = hb + HOFF_WSWO;
    __half* w_lin1   = hb + HOFF_WLIN1;
    __half* w_lin2   = hb + HOFF_WLIN2;
    __half* proj16   = hb + HOFF_PROJ16;
    __half* ff16     = hb + HOFF_FF16;

    cudaFuncSetAttribute(self_attn_f16_kernel,
                         cudaFuncAttributeMaxDynamicSharedMemorySize, ATTN_SMEM);
    cudaFuncSetAttribute(sw_attn_f16_kernel,
                         cudaFuncAttributeMaxDynamicSharedMemorySize, SWA_SMEM);
    cudaFuncSetAttribute(gemm_f16_kernel,
                         cudaFuncAttributeMaxDynamicSharedMemorySize, G128_SMEM);
    cudaFuncSetAttribute(gemm_f16_dual_kernel,
                         cudaFuncAttributeMaxDynamicSharedMemorySize, G128_SMEM);
    cudaFuncSetAttribute(gemm_f16_n64_kernel,
                         cudaFuncAttributeMaxDynamicSharedMemorySize, G64_SMEM);

    // one fused convert (incl. KV weight concat + bias concat)
    f2h_multi_kernel<<<8192, 256>>>(tgt, tgt16, memory, mem16,
                                    in_proj_w, w_in, out_proj_w, w_out,
                                    sw_q_w, w_swq, sw_o_w, w_swo,
                                    lin1_w, w_lin1, lin2_w, w_lin2,
                                    sw_k_w, w_swkv, sw_v_w, w_swkv + 262144,
                                    sw_k_b, sw_v_b, bcat);

    // combined QKV (N=1536, 12 blocks) + fused KV (N=1024, 8 blocks)
    gemm_f16_dual_kernel<<<dim3(20, 32), 256, G128_SMEM>>>(
        tgt16, w_in, in_proj_b, qkv16, 3 * D_,
        mem16, w_swkv, bcat, swkv16, 1024,
        D_, 12);
    // self attention
    self_attn_f16_kernel<<<dim3(8, 32), 256, ATTN_SMEM>>>(qkv16, attn16);
    // out projection -> fp16
    gemm_f16_n64_kernel<<<dim3(8, 32), 256, G64_SMEM>>>(attn16, w_out, out_proj_b, proj16,
                                                        NROWS, D_, D_, 0, 1);
    // add + LN1
    add_ln_h_kernel<<<NROWS, 256>>>(tgt, proj16, n1_g, n1_b, x1, x1h);
    // sw q projection
    gemm_f16_n64_kernel<<<dim3(8, 32), 256, G64_SMEM>>>(x1h, w_swq, sw_q_b, swq16,
                                                        NROWS, D_, D_, 0, 1);
    // banded attention
    sw_attn_f16_kernel<<<dim3(8, 32), 256, SWA_SMEM>>>(swq16, swkv16, swattn16);
    // sw out projection -> fp16
    gemm_f16_n64_kernel<<<dim3(8, 32), 256, G64_SMEM>>>(swattn16, w_swo, sw_o_b, proj16,
                                                        NROWS, D_, D_, 0, 1);
    // add + LN2
    add_ln_h_kernel<<<NROWS, 256>>>(x1, proj16, n2_g, n2_b, x2, x2h);
    // FFN up + ReLU
    gemm_f16_kernel<<<dim3(16, 32), 256, G128_SMEM>>>(x2h, w_lin1, lin1_b, hbuf16,
                                                      NROWS, DFF_, D_, 1, 1);
    // FFN down -> fp16
    gemm_f16_n64_kernel<<<dim3(8, 32), 256, G64_SMEM>>>(hbuf16, w_lin2, lin2_b, ff16,
                                                        NROWS, D_, DFF_, 0, 1);
    // add + LN3 -> output (fp32 only)
    add_ln_h_kernel<<<NROWS, 256>>>(x2, ff16, n3_g, n3_b, out, nullptr);
}